// round 1
// baseline (speedup 1.0000x reference)
#include <cuda_runtime.h>
#include <math.h>

// Problem constants (fixed by setup_inputs)
#define DMODEL 1024
#define BATCH  8
#define SEQ    512
#define NHEAD  16
#define DKH    64
#define MTOK   4096            // BATCH*SEQ
#define DFF    4096
#define NCLIP  64              // SEQ / 8
#define LN_EPS 1e-5f

// ---------------------------------------------------------------------------
// Device scratch (static — no allocations allowed)
// ---------------------------------------------------------------------------
__device__ float g_q[MTOK * DMODEL];
__device__ float g_k[MTOK * DMODEL];
__device__ float g_v[MTOK * DMODEL];
__device__ float g_attn[MTOK * DMODEL];
__device__ float g_spatial[MTOK * DMODEL];
__device__ float g_temporal[MTOK * DMODEL];
__device__ float g_x[MTOK * DMODEL];
__device__ float g_h[MTOK * DMODEL];
__device__ float g_ffn[MTOK * DFF];
__device__ float g_scores[BATCH * NHEAD * SEQ * SEQ];   // 128 * 512 * 512 = 33.5M floats

// ---------------------------------------------------------------------------
// Generic SGEMM: C[M,N] = A[M,K] @ B[K,N] (+ bias) (+ residual) (ReLU opt)
// All dims multiples of 128 (K multiple of 16). 128x128 tile, 256 threads,
// 8x8 per-thread microtile.
// ---------------------------------------------------------------------------
__global__ __launch_bounds__(256, 2)
void gemm_kernel(const float* __restrict__ A, const float* __restrict__ B,
                 const float* __restrict__ bias, const float* R,
                 float* C, int M, int N, int K, int relu)
{
    __shared__ float As[16][132];   // padded to reduce store conflicts
    __shared__ float Bs[16][128];

    const int tid = threadIdx.x;
    const int tx  = tid & 15;
    const int ty  = tid >> 4;
    const int row0 = blockIdx.y * 128;
    const int col0 = blockIdx.x * 128;

    const int a_r = tid >> 2;          // 0..63
    const int a_c = (tid & 3) << 2;    // 0,4,8,12
    const int b_r = tid >> 5;          // 0..7
    const int b_c = (tid & 31) << 2;   // 0..124

    float acc[8][8];
#pragma unroll
    for (int i = 0; i < 8; i++)
#pragma unroll
        for (int j = 0; j < 8; j++) acc[i][j] = 0.f;

    const float* Aptr0 = A + (row0 + a_r) * K + a_c;
    const float* Aptr1 = A + (row0 + a_r + 64) * K + a_c;
    const float* Bptr0 = B + b_r * N + col0 + b_c;
    const float* Bptr1 = B + (b_r + 8) * N + col0 + b_c;

    for (int k0 = 0; k0 < K; k0 += 16) {
        float4 av0 = *(const float4*)(Aptr0 + k0);
        float4 av1 = *(const float4*)(Aptr1 + k0);
        float4 bv0 = *(const float4*)(Bptr0 + k0 * N);
        float4 bv1 = *(const float4*)(Bptr1 + k0 * N);

        As[a_c + 0][a_r] = av0.x; As[a_c + 1][a_r] = av0.y;
        As[a_c + 2][a_r] = av0.z; As[a_c + 3][a_r] = av0.w;
        As[a_c + 0][a_r + 64] = av1.x; As[a_c + 1][a_r + 64] = av1.y;
        As[a_c + 2][a_r + 64] = av1.z; As[a_c + 3][a_r + 64] = av1.w;
        *(float4*)&Bs[b_r][b_c]     = bv0;
        *(float4*)&Bs[b_r + 8][b_c] = bv1;
        __syncthreads();

#pragma unroll
        for (int kk = 0; kk < 16; kk++) {
            float4 a0 = *(const float4*)&As[kk][ty * 8];
            float4 a1 = *(const float4*)&As[kk][ty * 8 + 4];
            float4 b0 = *(const float4*)&Bs[kk][tx * 8];
            float4 b1 = *(const float4*)&Bs[kk][tx * 8 + 4];
            float a[8] = {a0.x, a0.y, a0.z, a0.w, a1.x, a1.y, a1.z, a1.w};
            float b[8] = {b0.x, b0.y, b0.z, b0.w, b1.x, b1.y, b1.z, b1.w};
#pragma unroll
            for (int i = 0; i < 8; i++)
#pragma unroll
                for (int j = 0; j < 8; j++)
                    acc[i][j] += a[i] * b[j];
        }
        __syncthreads();
    }

    // Epilogue (bias optional, residual optional — residual may alias C)
#pragma unroll
    for (int i = 0; i < 8; i++) {
        int row = row0 + ty * 8 + i;
#pragma unroll
        for (int j = 0; j < 8; j += 4) {
            int col = col0 + tx * 8 + j;
            float4 vv;
            vv.x = acc[i][j + 0]; vv.y = acc[i][j + 1];
            vv.z = acc[i][j + 2]; vv.w = acc[i][j + 3];
            if (bias) {
                float4 bb = *(const float4*)(bias + col);
                vv.x += bb.x; vv.y += bb.y; vv.z += bb.z; vv.w += bb.w;
            }
            if (R) {
                float4 rr = *(const float4*)(R + row * N + col);
                vv.x += rr.x; vv.y += rr.y; vv.z += rr.z; vv.w += rr.w;
            }
            if (relu) {
                vv.x = fmaxf(vv.x, 0.f); vv.y = fmaxf(vv.y, 0.f);
                vv.z = fmaxf(vv.z, 0.f); vv.w = fmaxf(vv.w, 0.f);
            }
            *(float4*)(C + row * N + col) = vv;
        }
    }
}

// ---------------------------------------------------------------------------
// Spatial attention: within each clip of 8 tokens, per head.
// grid = B*NCLIP*NHEAD = 8192 blocks, 64 threads.
// ---------------------------------------------------------------------------
__global__ void spatial_attn_kernel(const float* __restrict__ q,
                                    const float* __restrict__ k,
                                    const float* __restrict__ v,
                                    const int* __restrict__ mask,
                                    float* __restrict__ out)
{
    __shared__ float Qs[8][64], Ks[8][64], Vs[8][64], Ps[8][8];
    int u = blockIdx.x;
    int h = u & 15;
    int c = (u >> 4) & 63;
    int b = u >> 10;
    int tb = b * SEQ + c * 8;
    int tid = threadIdx.x;

    for (int idx = tid; idx < 512; idx += 64) {
        int r = idx >> 6, d = idx & 63;
        int g = (tb + r) * DMODEL + h * DKH + d;
        Qs[r][d] = q[g]; Ks[r][d] = k[g]; Vs[r][d] = v[g];
    }
    __syncthreads();

    int i = tid >> 3, j = tid & 7;
    float s = 0.f;
#pragma unroll
    for (int d = 0; d < 64; d++) s += Qs[i][d] * Ks[j][d];
    s *= 0.125f;
    if (mask[b * SEQ + c * 8 + j] == 0) s = -1e9f;

    float m = s;
    m = fmaxf(m, __shfl_xor_sync(0xffffffffu, m, 1));
    m = fmaxf(m, __shfl_xor_sync(0xffffffffu, m, 2));
    m = fmaxf(m, __shfl_xor_sync(0xffffffffu, m, 4));
    float p = expf(s - m);
    float sum = p;
    sum += __shfl_xor_sync(0xffffffffu, sum, 1);
    sum += __shfl_xor_sync(0xffffffffu, sum, 2);
    sum += __shfl_xor_sync(0xffffffffu, sum, 4);
    Ps[i][j] = p / sum;
    __syncthreads();

    for (int idx = tid; idx < 512; idx += 64) {
        int r = idx >> 6, d = idx & 63;
        float o = 0.f;
#pragma unroll
        for (int jj = 0; jj < 8; jj++) o += Ps[r][jj] * Vs[jj][d];
        out[(tb + r) * DMODEL + h * DKH + d] = o;
    }
}

// ---------------------------------------------------------------------------
// Temporal attention: across 64 clips at fixed within-clip position j, per head.
// grid = B*8*NHEAD = 1024 blocks, 256 threads. 48 KB static smem.
// ---------------------------------------------------------------------------
__global__ __launch_bounds__(256)
void temporal_attn_kernel(const float* __restrict__ q,
                          const float* __restrict__ k,
                          const float* __restrict__ v,
                          const int* __restrict__ mask,
                          float* __restrict__ out)
{
    __shared__ float QV[64][64];   // Q transposed [d][c]; later reused as V [c][d]
    __shared__ float Ks[64][64];   // K transposed [d][c]
    __shared__ float Pst[64][64];  // P transposed [key][query]

    int u = blockIdx.x;
    int h = u & 15;
    int jpos = (u >> 4) & 7;
    int b = u >> 7;
    int tid = threadIdx.x;
    int tx = tid & 15, ty = tid >> 4;

    for (int idx = tid; idx < 1024; idx += 256) {
        int r = idx >> 4;
        int d0 = (idx & 15) << 2;
        int g = (b * SEQ + r * 8 + jpos) * DMODEL + h * DKH + d0;
        float4 qv = *(const float4*)(q + g);
        QV[d0 + 0][r] = qv.x; QV[d0 + 1][r] = qv.y;
        QV[d0 + 2][r] = qv.z; QV[d0 + 3][r] = qv.w;
        float4 kv = *(const float4*)(k + g);
        Ks[d0 + 0][r] = kv.x; Ks[d0 + 1][r] = kv.y;
        Ks[d0 + 2][r] = kv.z; Ks[d0 + 3][r] = kv.w;
    }
    __syncthreads();

    float acc[4][4];
#pragma unroll
    for (int i = 0; i < 4; i++)
#pragma unroll
        for (int j = 0; j < 4; j++) acc[i][j] = 0.f;

    for (int d = 0; d < 64; d++) {
        float4 a = *(const float4*)&QV[d][ty * 4];
        float4 bb = *(const float4*)&Ks[d][tx * 4];
        float av[4] = {a.x, a.y, a.z, a.w};
        float bvv[4] = {bb.x, bb.y, bb.z, bb.w};
#pragma unroll
        for (int i = 0; i < 4; i++)
#pragma unroll
            for (int j = 0; j < 4; j++) acc[i][j] += av[i] * bvv[j];
    }
#pragma unroll
    for (int jj = 0; jj < 4; jj++) {
        int cc = tx * 4 + jj;
        float mv = (mask[b * SEQ + cc * 8 + jpos] == 0) ? -1e9f : 0.f;
#pragma unroll
        for (int i = 0; i < 4; i++)
            Pst[cc][ty * 4 + i] = acc[i][jj] * 0.125f + mv;
    }
    __syncthreads();

    if (tid < 64) {
        float m = -1e30f;
        for (int cc = 0; cc < 64; cc++) m = fmaxf(m, Pst[cc][tid]);
        float sum = 0.f;
        for (int cc = 0; cc < 64; cc++) {
            float p = expf(Pst[cc][tid] - m);
            Pst[cc][tid] = p; sum += p;
        }
        float inv = 1.f / sum;
        for (int cc = 0; cc < 64; cc++) Pst[cc][tid] *= inv;
    }
    __syncthreads();

    for (int idx = tid; idx < 1024; idx += 256) {
        int r = idx >> 4;
        int d0 = (idx & 15) << 2;
        float4 vv = *(const float4*)(v + (b * SEQ + r * 8 + jpos) * DMODEL + h * DKH + d0);
        *(float4*)&QV[r][d0] = vv;
    }
    __syncthreads();

    float oacc[4][4];
#pragma unroll
    for (int i = 0; i < 4; i++)
#pragma unroll
        for (int j = 0; j < 4; j++) oacc[i][j] = 0.f;

    for (int kk = 0; kk < 64; kk++) {
        float4 a = *(const float4*)&Pst[kk][ty * 4];
        float4 bb = *(const float4*)&QV[kk][tx * 4];
        float av[4] = {a.x, a.y, a.z, a.w};
        float bvv[4] = {bb.x, bb.y, bb.z, bb.w};
#pragma unroll
        for (int i = 0; i < 4; i++)
#pragma unroll
            for (int j = 0; j < 4; j++) oacc[i][j] += av[i] * bvv[j];
    }
#pragma unroll
    for (int i = 0; i < 4; i++)
#pragma unroll
        for (int jj = 0; jj < 4; jj++)
            out[(b * SEQ + (ty * 4 + i) * 8 + jpos) * DMODEL + h * DKH + tx * 4 + jj] =
                oacc[i][jj];
}

// ---------------------------------------------------------------------------
// Encoder attention scores: per (b,h) 512x512 = Q K^T / 8 (+mask)
// grid (8, 8, 128), 256 threads; each block computes a 64x64 tile.
// ---------------------------------------------------------------------------
__global__ __launch_bounds__(256)
void enc_scores_kernel(const float* __restrict__ q, const float* __restrict__ k,
                       const int* __restrict__ mask, float* __restrict__ scores)
{
    __shared__ float Qs[64][64];   // [d][r]
    __shared__ float Ks[64][64];   // [d][c]
    int bh = blockIdx.z;
    int b = bh >> 4, h = bh & 15;
    int r0 = blockIdx.y * 64, c0 = blockIdx.x * 64;
    int tid = threadIdx.x, tx = tid & 15, ty = tid >> 4;

    for (int idx = tid; idx < 1024; idx += 256) {
        int r = idx >> 4;
        int d0 = (idx & 15) << 2;
        float4 qv = *(const float4*)(q + (b * SEQ + r0 + r) * DMODEL + h * DKH + d0);
        Qs[d0 + 0][r] = qv.x; Qs[d0 + 1][r] = qv.y;
        Qs[d0 + 2][r] = qv.z; Qs[d0 + 3][r] = qv.w;
        float4 kv = *(const float4*)(k + (b * SEQ + c0 + r) * DMODEL + h * DKH + d0);
        Ks[d0 + 0][r] = kv.x; Ks[d0 + 1][r] = kv.y;
        Ks[d0 + 2][r] = kv.z; Ks[d0 + 3][r] = kv.w;
    }
    __syncthreads();

    float acc[4][4];
#pragma unroll
    for (int i = 0; i < 4; i++)
#pragma unroll
        for (int j = 0; j < 4; j++) acc[i][j] = 0.f;

    for (int d = 0; d < 64; d++) {
        float4 a = *(const float4*)&Qs[d][ty * 4];
        float4 bb = *(const float4*)&Ks[d][tx * 4];
        float av[4] = {a.x, a.y, a.z, a.w};
        float bvv[4] = {bb.x, bb.y, bb.z, bb.w};
#pragma unroll
        for (int i = 0; i < 4; i++)
#pragma unroll
            for (int j = 0; j < 4; j++) acc[i][j] += av[i] * bvv[j];
    }
    float* sc = scores + (size_t)bh * SEQ * SEQ;
#pragma unroll
    for (int jj = 0; jj < 4; jj++) {
        int col = c0 + tx * 4 + jj;
        float mv = (mask[b * SEQ + col] == 0) ? -1e9f : 0.f;
#pragma unroll
        for (int i = 0; i < 4; i++)
            sc[(r0 + ty * 4 + i) * SEQ + col] = acc[i][jj] * 0.125f + mv;
    }
}

// ---------------------------------------------------------------------------
// Row softmax over 512-wide rows. One warp per row, 8 rows per 256-thr block.
// ---------------------------------------------------------------------------
__global__ void softmax_rows_kernel(float* __restrict__ scores)
{
    int row = blockIdx.x * 8 + (threadIdx.x >> 5);
    int lane = threadIdx.x & 31;
    float* p = scores + (size_t)row * SEQ;
    float vals[16];
    float m = -1e30f;
#pragma unroll
    for (int i = 0; i < 16; i++) { vals[i] = p[lane + i * 32]; m = fmaxf(m, vals[i]); }
#pragma unroll
    for (int o = 16; o; o >>= 1) m = fmaxf(m, __shfl_xor_sync(0xffffffffu, m, o));
    float s = 0.f;
#pragma unroll
    for (int i = 0; i < 16; i++) { vals[i] = expf(vals[i] - m); s += vals[i]; }
#pragma unroll
    for (int o = 16; o; o >>= 1) s += __shfl_xor_sync(0xffffffffu, s, o);
    float inv = 1.f / s;
#pragma unroll
    for (int i = 0; i < 16; i++) p[lane + i * 32] = vals[i] * inv;
}

// ---------------------------------------------------------------------------
// Encoder P@V: per (b,h): [512,512] @ [512,64] -> out in concat-head layout.
// grid (8, 128), 256 threads; each block: 64 rows x 64 cols.
// ---------------------------------------------------------------------------
__global__ __launch_bounds__(256)
void enc_av_kernel(const float* __restrict__ scores, const float* __restrict__ v,
                   float* __restrict__ out)
{
    __shared__ float Pst[16][64];  // [k][r]
    __shared__ float Vs[16][64];   // [k][d]
    int bh = blockIdx.y;
    int b = bh >> 4, h = bh & 15;
    int r0 = blockIdx.x * 64;
    int tid = threadIdx.x, tx = tid & 15, ty = tid >> 4;
    const float* sc = scores + (size_t)bh * SEQ * SEQ;

    float acc[4][4];
#pragma unroll
    for (int i = 0; i < 4; i++)
#pragma unroll
        for (int j = 0; j < 4; j++) acc[i][j] = 0.f;

    for (int k0 = 0; k0 < SEQ; k0 += 16) {
        {
            int r = tid >> 2;
            int kk0 = (tid & 3) << 2;
            float4 pv = *(const float4*)(sc + (r0 + r) * SEQ + k0 + kk0);
            Pst[kk0 + 0][r] = pv.x; Pst[kk0 + 1][r] = pv.y;
            Pst[kk0 + 2][r] = pv.z; Pst[kk0 + 3][r] = pv.w;
        }
        {
            int kk = tid >> 4;
            int d0 = (tid & 15) << 2;
            float4 vv = *(const float4*)(v + (b * SEQ + k0 + kk) * DMODEL + h * DKH + d0);
            *(float4*)&Vs[kk][d0] = vv;
        }
        __syncthreads();
#pragma unroll
        for (int kk = 0; kk < 16; kk++) {
            float4 a = *(const float4*)&Pst[kk][ty * 4];
            float4 bb = *(const float4*)&Vs[kk][tx * 4];
            float av[4] = {a.x, a.y, a.z, a.w};
            float bvv[4] = {bb.x, bb.y, bb.z, bb.w};
#pragma unroll
            for (int i = 0; i < 4; i++)
#pragma unroll
                for (int j = 0; j < 4; j++) acc[i][j] += av[i] * bvv[j];
        }
        __syncthreads();
    }
#pragma unroll
    for (int i = 0; i < 4; i++)
#pragma unroll
        for (int jj = 0; jj < 4; jj++)
            out[(b * SEQ + r0 + ty * 4 + i) * DMODEL + h * DKH + tx * 4 + jj] = acc[i][jj];
}

// ---------------------------------------------------------------------------
// LayerNorm over last dim (1024). grid = 4096 rows, 256 threads.
// ---------------------------------------------------------------------------
__global__ void layernorm_kernel(const float* __restrict__ x,
                                 const float* __restrict__ gamma,
                                 const float* __restrict__ beta,
                                 float* __restrict__ out)
{
    __shared__ float sh1[8], sh2[8];
    int row = blockIdx.x;
    int tid = threadIdx.x;
    const float* xr = x + (size_t)row * DMODEL;
    float4 v = *(const float4*)(xr + tid * 4);
    float s1 = v.x + v.y + v.z + v.w;
    float s2 = v.x * v.x + v.y * v.y + v.z * v.z + v.w * v.w;
#pragma unroll
    for (int o = 16; o; o >>= 1) {
        s1 += __shfl_xor_sync(0xffffffffu, s1, o);
        s2 += __shfl_xor_sync(0xffffffffu, s2, o);
    }
    if ((tid & 31) == 0) { sh1[tid >> 5] = s1; sh2[tid >> 5] = s2; }
    __syncthreads();
    if (tid == 0) {
        float a = 0.f, b2 = 0.f;
        for (int i = 0; i < 8; i++) { a += sh1[i]; b2 += sh2[i]; }
        sh1[0] = a * (1.f / DMODEL);
        sh2[0] = b2 * (1.f / DMODEL);
    }
    __syncthreads();
    float mean = sh1[0];
    float var = sh2[0] - mean * mean;
    float inv = rsqrtf(var + LN_EPS);
    float4 g = *(const float4*)(gamma + tid * 4);
    float4 bb = *(const float4*)(beta + tid * 4);
    float4 o;
    o.x = (v.x - mean) * inv * g.x + bb.x;
    o.y = (v.y - mean) * inv * g.y + bb.y;
    o.z = (v.z - mean) * inv * g.z + bb.z;
    o.w = (v.w - mean) * inv * g.w + bb.w;
    *(float4*)(out + (size_t)row * DMODEL + tid * 4) = o;
}

// ---------------------------------------------------------------------------
// Host orchestration
// ---------------------------------------------------------------------------
static inline void run_gemm(const float* A, const float* B, const float* bias,
                            const float* R, float* C, int M, int N, int K, int relu)
{
    dim3 grid(N / 128, M / 128);
    gemm_kernel<<<grid, 256>>>(A, B, bias, R, C, M, N, K, relu);
}

extern "C" void kernel_launch(void* const* d_in, const int* in_sizes, int n_in,
                              void* d_out, int out_size)
{
    (void)n_in; (void)out_size;
    const float* x    = (const float*)d_in[0];
    const int*   mask = (const int*)  d_in[1];
    const float* sw   = (const float*)d_in[2];
    const float* sb   = (const float*)d_in[3];
    const float* tw   = (const float*)d_in[4];
    const float* tbias= (const float*)d_in[5];
    const float* fw   = (const float*)d_in[6];
    const float* fb   = (const float*)d_in[7];
    const float* aw   = (const float*)d_in[8];
    const float* ab   = (const float*)d_in[9];
    const float* w1   = (const float*)d_in[10];
    const float* b1   = (const float*)d_in[11];
    const float* w2   = (const float*)d_in[12];
    const float* b2   = (const float*)d_in[13];
    const float* lns  = (const float*)d_in[14];
    const float* lnb  = (const float*)d_in[15];
    float* out = (float*)d_out;

    float *q, *k, *v, *attn, *spa, *tem, *xb, *h, *ffn, *sc;
    cudaGetSymbolAddress((void**)&q,    g_q);
    cudaGetSymbolAddress((void**)&k,    g_k);
    cudaGetSymbolAddress((void**)&v,    g_v);
    cudaGetSymbolAddress((void**)&attn, g_attn);
    cudaGetSymbolAddress((void**)&spa,  g_spatial);
    cudaGetSymbolAddress((void**)&tem,  g_temporal);
    cudaGetSymbolAddress((void**)&xb,   g_x);
    cudaGetSymbolAddress((void**)&h,    g_h);
    cudaGetSymbolAddress((void**)&ffn,  g_ffn);
    cudaGetSymbolAddress((void**)&sc,   g_scores);

    const int DD = DMODEL * DMODEL;

    // ---- spatial attention ----
    run_gemm(x, sw + 0 * DD, sb + 0 * DMODEL, nullptr, q, MTOK, DMODEL, DMODEL, 0);
    run_gemm(x, sw + 1 * DD, sb + 1 * DMODEL, nullptr, k, MTOK, DMODEL, DMODEL, 0);
    run_gemm(x, sw + 2 * DD, sb + 2 * DMODEL, nullptr, v, MTOK, DMODEL, DMODEL, 0);
    spatial_attn_kernel<<<BATCH * NCLIP * NHEAD, 64>>>(q, k, v, mask, attn);
    run_gemm(attn, sw + 3 * DD, sb + 3 * DMODEL, nullptr, spa, MTOK, DMODEL, DMODEL, 0);

    // ---- temporal attention ----
    run_gemm(x, tw + 0 * DD, tbias + 0 * DMODEL, nullptr, q, MTOK, DMODEL, DMODEL, 0);
    run_gemm(x, tw + 1 * DD, tbias + 1 * DMODEL, nullptr, k, MTOK, DMODEL, DMODEL, 0);
    run_gemm(x, tw + 2 * DD, tbias + 2 * DMODEL, nullptr, v, MTOK, DMODEL, DMODEL, 0);
    temporal_attn_kernel<<<BATCH * 8 * NHEAD, 256>>>(q, k, v, mask, attn);
    run_gemm(attn, tw + 3 * DD, tbias + 3 * DMODEL, nullptr, tem, MTOK, DMODEL, DMODEL, 0);

    // ---- fusion: xb = spa @ fw[0:1024] + tem @ fw[1024:2048] + fb ----
    run_gemm(spa, fw, fb, nullptr, xb, MTOK, DMODEL, DMODEL, 0);
    run_gemm(tem, fw + DMODEL * DMODEL, nullptr, xb, xb, MTOK, DMODEL, DMODEL, 0);

    // ---- encoder layers ----
    int nlayers = in_sizes[8] / (4 * DD);
    for (int i = 0; i < nlayers; i++) {
        const float* awi = aw + (size_t)i * 4 * DD;
        const float* abi = ab + (size_t)i * 4 * DMODEL;

        layernorm_kernel<<<MTOK, 256>>>(xb, lns + (i * 2 + 0) * DMODEL,
                                        lnb + (i * 2 + 0) * DMODEL, h);
        run_gemm(h, awi + 0 * DD, abi + 0 * DMODEL, nullptr, q, MTOK, DMODEL, DMODEL, 0);
        run_gemm(h, awi + 1 * DD, abi + 1 * DMODEL, nullptr, k, MTOK, DMODEL, DMODEL, 0);
        run_gemm(h, awi + 2 * DD, abi + 2 * DMODEL, nullptr, v, MTOK, DMODEL, DMODEL, 0);

        enc_scores_kernel<<<dim3(8, 8, BATCH * NHEAD), 256>>>(q, k, mask, sc);
        softmax_rows_kernel<<<BATCH * NHEAD * SEQ / 8, 256>>>(sc);
        enc_av_kernel<<<dim3(8, BATCH * NHEAD), 256>>>(sc, v, attn);

        run_gemm(attn, awi + 3 * DD, abi + 3 * DMODEL, xb, xb, MTOK, DMODEL, DMODEL, 0);

        layernorm_kernel<<<MTOK, 256>>>(xb, lns + (i * 2 + 1) * DMODEL,
                                        lnb + (i * 2 + 1) * DMODEL, h);
        run_gemm(h, w1 + (size_t)i * DMODEL * DFF, b1 + i * DFF, nullptr, ffn,
                 MTOK, DFF, DMODEL, 1);
        float* dst = (i == nlayers - 1) ? out : xb;
        run_gemm(ffn, w2 + (size_t)i * DFF * DMODEL, b2 + i * DMODEL, xb, dst,
                 MTOK, DMODEL, DFF, 0);
    }
}

// round 3
// speedup vs baseline: 3.5288x; 3.5288x over previous
#include <cuda_runtime.h>
#include <cuda_fp16.h>
#include <cstdint>
#include <math.h>

#define DMODEL 1024
#define BATCH  8
#define SEQ    512
#define NHEAD  16
#define DKH    64
#define MTOK   4096
#define DFF    4096
#define NCLIP  64
#define LN_EPS 1e-5f

typedef __half half_t;

// ---------------------------------------------------------------------------
// PTX helpers (arch-agnostic: mma.sync / ldmatrix / cp.async only)
// ---------------------------------------------------------------------------
__device__ __forceinline__ uint32_t smem_u32(const void* p) {
    uint32_t a;
    asm("{ .reg .u64 t; cvta.to.shared.u64 t, %1; cvt.u32.u64 %0, t; }" : "=r"(a) : "l"(p));
    return a;
}

#define LDSM4(r, a) \
    asm volatile("ldmatrix.sync.aligned.m8n8.x4.shared.b16 {%0,%1,%2,%3}, [%4];" \
        : "=r"((r)[0]), "=r"((r)[1]), "=r"((r)[2]), "=r"((r)[3]) : "r"(a))

#define MMA16816(c, a, b0, b1) \
    asm volatile("mma.sync.aligned.m16n8k16.row.col.f32.f16.f16.f32 " \
        "{%0,%1,%2,%3}, {%4,%5,%6,%7}, {%8,%9}, {%0,%1,%2,%3};" \
        : "+f"((c)[0]), "+f"((c)[1]), "+f"((c)[2]), "+f"((c)[3]) \
        : "r"((a)[0]), "r"((a)[1]), "r"((a)[2]), "r"((a)[3]), "r"(b0), "r"(b1))

#define CPASYNC16(d, s) asm volatile("cp.async.cg.shared.global [%0], [%1], 16;" :: "r"(d), "l"(s))
#define CPCOMMIT()      asm volatile("cp.async.commit_group;" ::: "memory")
#define CPWAIT(n)       asm volatile("cp.async.wait_group %0;" :: "n"(n) : "memory")

// ---------------------------------------------------------------------------
// Device scratch
// ---------------------------------------------------------------------------
#define WT_TOT (34u * 1024u * 1024u)
__device__ half_t g_wt[WT_TOT];
__device__ half_t g_xh[MTOK * DMODEL];
__device__ half_t g_hh[MTOK * DMODEL];
__device__ half_t g_ah[MTOK * DMODEL];
__device__ half_t g_sph[MTOK * DMODEL];
__device__ half_t g_teh[MTOK * DMODEL];
__device__ half_t g_fh[MTOK * DFF];
__device__ float  g_q[MTOK * DMODEL];
__device__ float  g_k[MTOK * DMODEL];
__device__ float  g_v[MTOK * DMODEL];
__device__ float  g_xb[MTOK * DMODEL];
__device__ float  g_scores[BATCH * NHEAD * SEQ * SEQ];

// weight offsets (elements) inside g_wt
#define OFF_SW 0u
#define OFF_TW (4u*1024*1024)
#define OFF_FW (8u*1024*1024)
#define OFF_AW (10u*1024*1024)
#define OFF_W1 (18u*1024*1024)
#define OFF_W2 (26u*1024*1024)

// ---------------------------------------------------------------------------
// fp16 HMMA GEMM: C[M,N] = A[M,K] @ Wt[N,K]^T (+bias)(+R)(ReLU)
// 128x128 block, BK=32, 3-stage cp.async pipeline, 8 warps (2m x 4n).
// ---------------------------------------------------------------------------
#define STAGES 3
#define STAGE_BYTES 16384
#define SMEM_GEMM (STAGES * STAGE_BYTES)

__global__ __launch_bounds__(256)
void gemm_hmma(const half_t* __restrict__ A, const half_t* __restrict__ B,
               const float* __restrict__ bias, const float* __restrict__ R,
               float* Cf, half_t* Ch, int M, int N, int K, int relu)
{
    extern __shared__ char smem[];
    uint32_t sb = smem_u32(smem);
    const int tid = threadIdx.x;
    const int lane = tid & 31, warp = tid >> 5;
    const int row0 = blockIdx.y * 128, col0 = blockIdx.x * 128;
    const int wm = (warp >> 2) * 64;   // 0 / 64
    const int wn = (warp & 3) * 32;    // 0..96

    // cp.async segment assignment: 512 16B-segments per operand, 2 per thread
    int segr[2], segc[2];
#pragma unroll
    for (int i = 0; i < 2; i++) { int s = tid + i * 256; segr[i] = s >> 2; segc[i] = s & 3; }

    // ldmatrix address precompute
    int rA[4], swA[4];
#pragma unroll
    for (int mt = 0; mt < 4; mt++) {
        int r = wm + mt * 16 + (lane & 15);
        rA[mt] = r; swA[mt] = (r >> 1) & 3;
    }
    int rB[2], swB[2];
#pragma unroll
    for (int n2 = 0; n2 < 2; n2++) {
        int r = wn + n2 * 16 + (lane & 7) + ((lane >> 4) << 3);
        rB[n2] = r; swB[n2] = (r >> 1) & 3;
    }
    const int csA = lane >> 4;          // 0/1 : k 0-7 vs 8-15
    const int csB = (lane >> 3) & 1;

    float acc[4][4][4];
#pragma unroll
    for (int mt = 0; mt < 4; mt++)
#pragma unroll
        for (int nt = 0; nt < 4; nt++)
#pragma unroll
            for (int i = 0; i < 4; i++) acc[mt][nt][i] = 0.f;

    const int NT = K / 32;

#define GISSUE(kt, st) do { \
    uint32_t sA_ = sb + (st) * STAGE_BYTES; \
    uint32_t sB_ = sA_ + 8192; \
    _Pragma("unroll") for (int i = 0; i < 2; i++) { \
        int r_ = segr[i], c_ = segc[i]; \
        uint32_t sw_ = (uint32_t)((c_ ^ ((r_ >> 1) & 3)) << 4); \
        CPASYNC16(sA_ + r_ * 64 + sw_, A + (size_t)(row0 + r_) * K + (size_t)(kt) * 32 + c_ * 8); \
        CPASYNC16(sB_ + r_ * 64 + sw_, B + (size_t)(col0 + r_) * K + (size_t)(kt) * 32 + c_ * 8); \
    } \
    CPCOMMIT(); } while (0)

    GISSUE(0, 0);
    GISSUE(1, 1);

    for (int kt = 0; kt < NT; kt++) {
        if (kt == NT - 1) { CPWAIT(0); } else { CPWAIT(1); }
        __syncthreads();
        if (kt + 2 < NT) GISSUE(kt + 2, (kt + 2) % 3);

        uint32_t sA = sb + (kt % 3) * STAGE_BYTES;
        uint32_t sB = sA + 8192;
#pragma unroll
        for (int k16 = 0; k16 < 2; k16++) {
            uint32_t ra[4][4], rb[2][4];
#pragma unroll
            for (int mt = 0; mt < 4; mt++) {
                uint32_t addr = sA + rA[mt] * 64 + ((((k16 << 1) + csA) ^ swA[mt]) << 4);
                LDSM4(ra[mt], addr);
            }
#pragma unroll
            for (int n2 = 0; n2 < 2; n2++) {
                uint32_t addr = sB + rB[n2] * 64 + ((((k16 << 1) + csB) ^ swB[n2]) << 4);
                LDSM4(rb[n2], addr);
            }
#pragma unroll
            for (int mt = 0; mt < 4; mt++)
#pragma unroll
                for (int nt = 0; nt < 4; nt++)
                    MMA16816(acc[mt][nt], ra[mt],
                             rb[nt >> 1][(nt & 1) * 2], rb[nt >> 1][(nt & 1) * 2 + 1]);
        }
    }

    // Epilogue: direct register -> gmem
#pragma unroll
    for (int mt = 0; mt < 4; mt++) {
        int rg = row0 + wm + mt * 16 + (lane >> 2);
#pragma unroll
        for (int nt = 0; nt < 4; nt++) {
            int c = col0 + wn + nt * 8 + (lane & 3) * 2;
            float* a = acc[mt][nt];
#pragma unroll
            for (int h = 0; h < 2; h++) {
                int row = rg + h * 8;
                float v0 = a[h * 2], v1 = a[h * 2 + 1];
                if (bias) { v0 += bias[c]; v1 += bias[c + 1]; }
                if (R) {
                    float2 rr = *(const float2*)(R + (size_t)row * N + c);
                    v0 += rr.x; v1 += rr.y;
                }
                if (relu) { v0 = fmaxf(v0, 0.f); v1 = fmaxf(v1, 0.f); }
                if (Cf) {
                    float2 o; o.x = v0; o.y = v1;
                    *(float2*)(Cf + (size_t)row * N + c) = o;
                }
                if (Ch) {
                    *(__half2*)(Ch + (size_t)row * N + c) = __floats2half2_rn(v0, v1);
                }
            }
        }
    }
}

// ---------------------------------------------------------------------------
// Weight transpose + fp16 convert: W[K,N] -> Wt[N,K]
// ---------------------------------------------------------------------------
__global__ void wconv_kernel(const float* __restrict__ W, half_t* Wt, int K, int N)
{
    __shared__ float t[32][33];
    int n0 = blockIdx.x * 32, k0 = blockIdx.y * 32;
    int tx = threadIdx.x & 31, ty = threadIdx.x >> 5;
    for (int r = ty; r < 32; r += 8) t[r][tx] = W[(size_t)(k0 + r) * N + n0 + tx];
    __syncthreads();
    for (int r = ty; r < 32; r += 8)
        Wt[(size_t)(n0 + r) * K + k0 + tx] = __float2half_rn(t[tx][r]);
}

__global__ void aconv_kernel(const float* __restrict__ x, half_t* o, int n)
{
    int i = (blockIdx.x * blockDim.x + threadIdx.x) * 4;
    if (i >= n) return;
    float4 v = *(const float4*)(x + i);
    *(__half2*)(o + i)     = __floats2half2_rn(v.x, v.y);
    *(__half2*)(o + i + 2) = __floats2half2_rn(v.z, v.w);
}

// ---------------------------------------------------------------------------
// Spatial attention (clip=8), fp32 in, fp16 out
// ---------------------------------------------------------------------------
__global__ void spatial_attn_kernel(const float* __restrict__ q,
                                    const float* __restrict__ k,
                                    const float* __restrict__ v,
                                    const int* __restrict__ mask,
                                    half_t* __restrict__ oh)
{
    __shared__ float Qs[8][64], Ks[8][64], Vs[8][64], Ps[8][8];
    int u = blockIdx.x;
    int h = u & 15;
    int c = (u >> 4) & 63;
    int b = u >> 10;
    int tb = b * SEQ + c * 8;
    int tid = threadIdx.x;

    for (int idx = tid; idx < 512; idx += 64) {
        int r = idx >> 6, d = idx & 63;
        int g = (tb + r) * DMODEL + h * DKH + d;
        Qs[r][d] = q[g]; Ks[r][d] = k[g]; Vs[r][d] = v[g];
    }
    __syncthreads();

    int i = tid >> 3, j = tid & 7;
    float s = 0.f;
#pragma unroll
    for (int d = 0; d < 64; d++) s += Qs[i][d] * Ks[j][d];
    s *= 0.125f;
    if (mask[b * SEQ + c * 8 + j] == 0) s = -1e9f;

    float m = s;
    m = fmaxf(m, __shfl_xor_sync(0xffffffffu, m, 1));
    m = fmaxf(m, __shfl_xor_sync(0xffffffffu, m, 2));
    m = fmaxf(m, __shfl_xor_sync(0xffffffffu, m, 4));
    float p = expf(s - m);
    float sum = p;
    sum += __shfl_xor_sync(0xffffffffu, sum, 1);
    sum += __shfl_xor_sync(0xffffffffu, sum, 2);
    sum += __shfl_xor_sync(0xffffffffu, sum, 4);
    Ps[i][j] = p / sum;
    __syncthreads();

    for (int idx = tid; idx < 512; idx += 64) {
        int r = idx >> 6, d = idx & 63;
        float o = 0.f;
#pragma unroll
        for (int jj = 0; jj < 8; jj++) o += Ps[r][jj] * Vs[jj][d];
        oh[(size_t)(tb + r) * DMODEL + h * DKH + d] = __float2half_rn(o);
    }
}

// ---------------------------------------------------------------------------
// Temporal attention (64 clips), fp32 in, fp16 out
// ---------------------------------------------------------------------------
__global__ __launch_bounds__(256)
void temporal_attn_kernel(const float* __restrict__ q,
                          const float* __restrict__ k,
                          const float* __restrict__ v,
                          const int* __restrict__ mask,
                          half_t* __restrict__ oh)
{
    __shared__ float QV[64][64];
    __shared__ float Ks[64][64];
    __shared__ float Pst[64][64];

    int u = blockIdx.x;
    int h = u & 15;
    int jpos = (u >> 4) & 7;
    int b = u >> 7;
    int tid = threadIdx.x;
    int tx = tid & 15, ty = tid >> 4;

    for (int idx = tid; idx < 1024; idx += 256) {
        int r = idx >> 4;
        int d0 = (idx & 15) << 2;
        int g = (b * SEQ + r * 8 + jpos) * DMODEL + h * DKH + d0;
        float4 qv = *(const float4*)(q + g);
        QV[d0 + 0][r] = qv.x; QV[d0 + 1][r] = qv.y;
        QV[d0 + 2][r] = qv.z; QV[d0 + 3][r] = qv.w;
        float4 kv = *(const float4*)(k + g);
        Ks[d0 + 0][r] = kv.x; Ks[d0 + 1][r] = kv.y;
        Ks[d0 + 2][r] = kv.z; Ks[d0 + 3][r] = kv.w;
    }
    __syncthreads();

    float acc[4][4];
#pragma unroll
    for (int i = 0; i < 4; i++)
#pragma unroll
        for (int j = 0; j < 4; j++) acc[i][j] = 0.f;

    for (int d = 0; d < 64; d++) {
        float4 a = *(const float4*)&QV[d][ty * 4];
        float4 bb = *(const float4*)&Ks[d][tx * 4];
        float av[4] = {a.x, a.y, a.z, a.w};
        float bvv[4] = {bb.x, bb.y, bb.z, bb.w};
#pragma unroll
        for (int i = 0; i < 4; i++)
#pragma unroll
            for (int j = 0; j < 4; j++) acc[i][j] += av[i] * bvv[j];
    }
#pragma unroll
    for (int jj = 0; jj < 4; jj++) {
        int cc = tx * 4 + jj;
        float mv = (mask[b * SEQ + cc * 8 + jpos] == 0) ? -1e9f : 0.f;
#pragma unroll
        for (int i = 0; i < 4; i++)
            Pst[cc][ty * 4 + i] = acc[i][jj] * 0.125f + mv;
    }
    __syncthreads();

    if (tid < 64) {
        float m = -1e30f;
        for (int cc = 0; cc < 64; cc++) m = fmaxf(m, Pst[cc][tid]);
        float sum = 0.f;
        for (int cc = 0; cc < 64; cc++) {
            float p = expf(Pst[cc][tid] - m);
            Pst[cc][tid] = p; sum += p;
        }
        float inv = 1.f / sum;
        for (int cc = 0; cc < 64; cc++) Pst[cc][tid] *= inv;
    }
    __syncthreads();

    for (int idx = tid; idx < 1024; idx += 256) {
        int r = idx >> 4;
        int d0 = (idx & 15) << 2;
        float4 vv = *(const float4*)(v + (b * SEQ + r * 8 + jpos) * DMODEL + h * DKH + d0);
        *(float4*)&QV[r][d0] = vv;
    }
    __syncthreads();

    float oacc[4][4];
#pragma unroll
    for (int i = 0; i < 4; i++)
#pragma unroll
        for (int j = 0; j < 4; j++) oacc[i][j] = 0.f;

    for (int kk = 0; kk < 64; kk++) {
        float4 a = *(const float4*)&Pst[kk][ty * 4];
        float4 bb = *(const float4*)&QV[kk][tx * 4];
        float av[4] = {a.x, a.y, a.z, a.w};
        float bvv[4] = {bb.x, bb.y, bb.z, bb.w};
#pragma unroll
        for (int i = 0; i < 4; i++)
#pragma unroll
            for (int j = 0; j < 4; j++) oacc[i][j] += av[i] * bvv[j];
    }
#pragma unroll
    for (int i = 0; i < 4; i++)
#pragma unroll
        for (int jj = 0; jj < 4; jj++)
            oh[(size_t)(b * SEQ + (ty * 4 + i) * 8 + jpos) * DMODEL + h * DKH + tx * 4 + jj] =
                __float2half_rn(oacc[i][jj]);
}

// ---------------------------------------------------------------------------
// Encoder attention scores (fp32)
// ---------------------------------------------------------------------------
__global__ __launch_bounds__(256)
void enc_scores_kernel(const float* __restrict__ q, const float* __restrict__ k,
                       const int* __restrict__ mask, float* __restrict__ scores)
{
    __shared__ float Qs[64][64];
    __shared__ float Ks[64][64];
    int bh = blockIdx.z;
    int b = bh >> 4, h = bh & 15;
    int r0 = blockIdx.y * 64, c0 = blockIdx.x * 64;
    int tid = threadIdx.x, tx = tid & 15, ty = tid >> 4;

    for (int idx = tid; idx < 1024; idx += 256) {
        int r = idx >> 4;
        int d0 = (idx & 15) << 2;
        float4 qv = *(const float4*)(q + (b * SEQ + r0 + r) * DMODEL + h * DKH + d0);
        Qs[d0 + 0][r] = qv.x; Qs[d0 + 1][r] = qv.y;
        Qs[d0 + 2][r] = qv.z; Qs[d0 + 3][r] = qv.w;
        float4 kv = *(const float4*)(k + (b * SEQ + c0 + r) * DMODEL + h * DKH + d0);
        Ks[d0 + 0][r] = kv.x; Ks[d0 + 1][r] = kv.y;
        Ks[d0 + 2][r] = kv.z; Ks[d0 + 3][r] = kv.w;
    }
    __syncthreads();

    float acc[4][4];
#pragma unroll
    for (int i = 0; i < 4; i++)
#pragma unroll
        for (int j = 0; j < 4; j++) acc[i][j] = 0.f;

    for (int d = 0; d < 64; d++) {
        float4 a = *(const float4*)&Qs[d][ty * 4];
        float4 bb = *(const float4*)&Ks[d][tx * 4];
        float av[4] = {a.x, a.y, a.z, a.w};
        float bvv[4] = {bb.x, bb.y, bb.z, bb.w};
#pragma unroll
        for (int i = 0; i < 4; i++)
#pragma unroll
            for (int j = 0; j < 4; j++) acc[i][j] += av[i] * bvv[j];
    }
    float* sc = scores + (size_t)bh * SEQ * SEQ;
#pragma unroll
    for (int jj = 0; jj < 4; jj++) {
        int col = c0 + tx * 4 + jj;
        float mv = (mask[b * SEQ + col] == 0) ? -1e9f : 0.f;
#pragma unroll
        for (int i = 0; i < 4; i++)
            sc[(r0 + ty * 4 + i) * SEQ + col] = acc[i][jj] * 0.125f + mv;
    }
}

__global__ void softmax_rows_kernel(float* __restrict__ scores)
{
    int row = blockIdx.x * 8 + (threadIdx.x >> 5);
    int lane = threadIdx.x & 31;
    float* p = scores + (size_t)row * SEQ;
    float vals[16];
    float m = -1e30f;
#pragma unroll
    for (int i = 0; i < 16; i++) { vals[i] = p[lane + i * 32]; m = fmaxf(m, vals[i]); }
#pragma unroll
    for (int o = 16; o; o >>= 1) m = fmaxf(m, __shfl_xor_sync(0xffffffffu, m, o));
    float s = 0.f;
#pragma unroll
    for (int i = 0; i < 16; i++) { vals[i] = expf(vals[i] - m); s += vals[i]; }
#pragma unroll
    for (int o = 16; o; o >>= 1) s += __shfl_xor_sync(0xffffffffu, s, o);
    float inv = 1.f / s;
#pragma unroll
    for (int i = 0; i < 16; i++) p[lane + i * 32] = vals[i] * inv;
}

// Encoder P@V -> fp16 output
__global__ __launch_bounds__(256)
void enc_av_kernel(const float* __restrict__ scores, const float* __restrict__ v,
                   half_t* __restrict__ oh)
{
    __shared__ float Pst[16][64];
    __shared__ float Vs[16][64];
    int bh = blockIdx.y;
    int b = bh >> 4, h = bh & 15;
    int r0 = blockIdx.x * 64;
    int tid = threadIdx.x, tx = tid & 15, ty = tid >> 4;
    const float* sc = scores + (size_t)bh * SEQ * SEQ;

    float acc[4][4];
#pragma unroll
    for (int i = 0; i < 4; i++)
#pragma unroll
        for (int j = 0; j < 4; j++) acc[i][j] = 0.f;

    for (int k0 = 0; k0 < SEQ; k0 += 16) {
        {
            int r = tid >> 2;
            int kk0 = (tid & 3) << 2;
            float4 pv = *(const float4*)(sc + (r0 + r) * SEQ + k0 + kk0);
            Pst[kk0 + 0][r] = pv.x; Pst[kk0 + 1][r] = pv.y;
            Pst[kk0 + 2][r] = pv.z; Pst[kk0 + 3][r] = pv.w;
        }
        {
            int kk = tid >> 4;
            int d0 = (tid & 15) << 2;
            float4 vv = *(const float4*)(v + (b * SEQ + k0 + kk) * DMODEL + h * DKH + d0);
            *(float4*)&Vs[kk][d0] = vv;
        }
        __syncthreads();
#pragma unroll
        for (int kk = 0; kk < 16; kk++) {
            float4 a = *(const float4*)&Pst[kk][ty * 4];
            float4 bb = *(const float4*)&Vs[kk][tx * 4];
            float av[4] = {a.x, a.y, a.z, a.w};
            float bvv[4] = {bb.x, bb.y, bb.z, bb.w};
#pragma unroll
            for (int i = 0; i < 4; i++)
#pragma unroll
                for (int j = 0; j < 4; j++) acc[i][j] += av[i] * bvv[j];
        }
        __syncthreads();
    }
#pragma unroll
    for (int i = 0; i < 4; i++)
#pragma unroll
        for (int jj = 0; jj < 4; jj++)
            oh[(size_t)(b * SEQ + r0 + ty * 4 + i) * DMODEL + h * DKH + tx * 4 + jj] =
                __float2half_rn(acc[i][jj]);
}

// ---------------------------------------------------------------------------
// LayerNorm fp32 in -> fp16 out
// ---------------------------------------------------------------------------
__global__ void layernorm_kernel(const float* __restrict__ x,
                                 const float* __restrict__ gamma,
                                 const float* __restrict__ beta,
                                 half_t* __restrict__ oh)
{
    __shared__ float sh1[8], sh2[8];
    int row = blockIdx.x;
    int tid = threadIdx.x;
    const float* xr = x + (size_t)row * DMODEL;
    float4 v = *(const float4*)(xr + tid * 4);
    float s1 = v.x + v.y + v.z + v.w;
    float s2 = v.x * v.x + v.y * v.y + v.z * v.z + v.w * v.w;
#pragma unroll
    for (int o = 16; o; o >>= 1) {
        s1 += __shfl_xor_sync(0xffffffffu, s1, o);
        s2 += __shfl_xor_sync(0xffffffffu, s2, o);
    }
    if ((tid & 31) == 0) { sh1[tid >> 5] = s1; sh2[tid >> 5] = s2; }
    __syncthreads();
    if (tid == 0) {
        float a = 0.f, b2 = 0.f;
        for (int i = 0; i < 8; i++) { a += sh1[i]; b2 += sh2[i]; }
        sh1[0] = a * (1.f / DMODEL);
        sh2[0] = b2 * (1.f / DMODEL);
    }
    __syncthreads();
    float mean = sh1[0];
    float var = sh2[0] - mean * mean;
    float inv = rsqrtf(var + LN_EPS);
    float4 g = *(const float4*)(gamma + tid * 4);
    float4 bb = *(const float4*)(beta + tid * 4);
    size_t base = (size_t)row * DMODEL + tid * 4;
    *(__half2*)(oh + base) =
        __floats2half2_rn((v.x - mean) * inv * g.x + bb.x,
                          (v.y - mean) * inv * g.y + bb.y);
    *(__half2*)(oh + base + 2) =
        __floats2half2_rn((v.z - mean) * inv * g.z + bb.z,
                          (v.w - mean) * inv * g.w + bb.w);
}

// ---------------------------------------------------------------------------
// Host orchestration
// ---------------------------------------------------------------------------
static inline void run_gemm(const half_t* A, const half_t* W,
                            const float* bias, const float* R,
                            float* Cf, half_t* Ch, int M, int N, int K, int relu)
{
    dim3 grid(N / 128, M / 128);
    gemm_hmma<<<grid, 256, SMEM_GEMM>>>(A, W, bias, R, Cf, Ch, M, N, K, relu);
}

static inline void run_wconv(const float* W, half_t* Wt, int K, int N)
{
    wconv_kernel<<<dim3(N / 32, K / 32), 256>>>(W, Wt, K, N);
}

extern "C" void kernel_launch(void* const* d_in, const int* in_sizes, int n_in,
                              void* d_out, int out_size)
{
    (void)n_in; (void)out_size;
    const float* x    = (const float*)d_in[0];
    const int*   mask = (const int*)  d_in[1];
    const float* sw   = (const float*)d_in[2];
    const float* sb   = (const float*)d_in[3];
    const float* tw   = (const float*)d_in[4];
    const float* tbia = (const float*)d_in[5];
    const float* fw   = (const float*)d_in[6];
    const float* fb   = (const float*)d_in[7];
    const float* aw   = (const float*)d_in[8];
    const float* ab   = (const float*)d_in[9];
    const float* w1   = (const float*)d_in[10];
    const float* b1   = (const float*)d_in[11];
    const float* w2   = (const float*)d_in[12];
    const float* b2   = (const float*)d_in[13];
    const float* lns  = (const float*)d_in[14];
    const float* lnb  = (const float*)d_in[15];
    float* out = (float*)d_out;

    cudaFuncSetAttribute(gemm_hmma, cudaFuncAttributeMaxDynamicSharedMemorySize, SMEM_GEMM);

    half_t *wt, *xh, *hh, *ah, *sph, *teh, *fh;
    float *q, *k, *v, *xb, *sc;
    cudaGetSymbolAddress((void**)&wt,  g_wt);
    cudaGetSymbolAddress((void**)&xh,  g_xh);
    cudaGetSymbolAddress((void**)&hh,  g_hh);
    cudaGetSymbolAddress((void**)&ah,  g_ah);
    cudaGetSymbolAddress((void**)&sph, g_sph);
    cudaGetSymbolAddress((void**)&teh, g_teh);
    cudaGetSymbolAddress((void**)&fh,  g_fh);
    cudaGetSymbolAddress((void**)&q,   g_q);
    cudaGetSymbolAddress((void**)&k,   g_k);
    cudaGetSymbolAddress((void**)&v,   g_v);
    cudaGetSymbolAddress((void**)&xb,  g_xb);
    cudaGetSymbolAddress((void**)&sc,  g_scores);

    const size_t DD = (size_t)DMODEL * DMODEL;
    const size_t M1 = 1024u * 1024u;

    // ---- transpose+convert all weights to fp16 [N,K] ----
    for (int j = 0; j < 4; j++) {
        run_wconv(sw + j * DD, wt + OFF_SW + j * M1, DMODEL, DMODEL);
        run_wconv(tw + j * DD, wt + OFF_TW + j * M1, DMODEL, DMODEL);
    }
    run_wconv(fw,      wt + OFF_FW,      DMODEL, DMODEL);
    run_wconv(fw + DD, wt + OFF_FW + M1, DMODEL, DMODEL);
    int nlayers = in_sizes[8] / (int)(4 * DD);
    for (int i = 0; i < nlayers; i++) {
        for (int j = 0; j < 4; j++)
            run_wconv(aw + (i * 4 + j) * DD, wt + OFF_AW + (i * 4 + j) * M1, DMODEL, DMODEL);
        run_wconv(w1 + (size_t)i * DMODEL * DFF, wt + OFF_W1 + i * 4 * M1, DMODEL, DFF);
        run_wconv(w2 + (size_t)i * DFF * DMODEL, wt + OFF_W2 + i * 4 * M1, DFF, DMODEL);
    }

    aconv_kernel<<<(MTOK * DMODEL / 4 + 255) / 256, 256>>>(x, xh, MTOK * DMODEL);

    // ---- spatial attention ----
    run_gemm(xh, wt + OFF_SW + 0 * M1, sb + 0 * DMODEL, nullptr, q, nullptr, MTOK, DMODEL, DMODEL, 0);
    run_gemm(xh, wt + OFF_SW + 1 * M1, sb + 1 * DMODEL, nullptr, k, nullptr, MTOK, DMODEL, DMODEL, 0);
    run_gemm(xh, wt + OFF_SW + 2 * M1, sb + 2 * DMODEL, nullptr, v, nullptr, MTOK, DMODEL, DMODEL, 0);
    spatial_attn_kernel<<<BATCH * NCLIP * NHEAD, 64>>>(q, k, v, mask, ah);
    run_gemm(ah, wt + OFF_SW + 3 * M1, sb + 3 * DMODEL, nullptr, nullptr, sph, MTOK, DMODEL, DMODEL, 0);

    // ---- temporal attention ----
    run_gemm(xh, wt + OFF_TW + 0 * M1, tbia + 0 * DMODEL, nullptr, q, nullptr, MTOK, DMODEL, DMODEL, 0);
    run_gemm(xh, wt + OFF_TW + 1 * M1, tbia + 1 * DMODEL, nullptr, k, nullptr, MTOK, DMODEL, DMODEL, 0);
    run_gemm(xh, wt + OFF_TW + 2 * M1, tbia + 2 * DMODEL, nullptr, v, nullptr, MTOK, DMODEL, DMODEL, 0);
    temporal_attn_kernel<<<BATCH * 8 * NHEAD, 256>>>(q, k, v, mask, ah);
    run_gemm(ah, wt + OFF_TW + 3 * M1, tbia + 3 * DMODEL, nullptr, nullptr, teh, MTOK, DMODEL, DMODEL, 0);

    // ---- fusion ----
    run_gemm(sph, wt + OFF_FW,      fb,      nullptr, xb, nullptr, MTOK, DMODEL, DMODEL, 0);
    run_gemm(teh, wt + OFF_FW + M1, nullptr, xb,      xb, nullptr, MTOK, DMODEL, DMODEL, 0);

    // ---- encoder layers ----
    for (int i = 0; i < nlayers; i++) {
        const float* abi = ab + (size_t)i * 4 * DMODEL;
        const half_t* awi = wt + OFF_AW + (size_t)i * 4 * M1;

        layernorm_kernel<<<MTOK, 256>>>(xb, lns + (i * 2 + 0) * DMODEL,
                                        lnb + (i * 2 + 0) * DMODEL, hh);
        run_gemm(hh, awi + 0 * M1, abi + 0 * DMODEL, nullptr, q, nullptr, MTOK, DMODEL, DMODEL, 0);
        run_gemm(hh, awi + 1 * M1, abi + 1 * DMODEL, nullptr, k, nullptr, MTOK, DMODEL, DMODEL, 0);
        run_gemm(hh, awi + 2 * M1, abi + 2 * DMODEL, nullptr, v, nullptr, MTOK, DMODEL, DMODEL, 0);

        enc_scores_kernel<<<dim3(8, 8, BATCH * NHEAD), 256>>>(q, k, mask, sc);
        softmax_rows_kernel<<<BATCH * NHEAD * SEQ / 8, 256>>>(sc);
        enc_av_kernel<<<dim3(8, BATCH * NHEAD), 256>>>(sc, v, ah);

        run_gemm(ah, awi + 3 * M1, abi + 3 * DMODEL, xb, xb, nullptr, MTOK, DMODEL, DMODEL, 0);

        layernorm_kernel<<<MTOK, 256>>>(xb, lns + (i * 2 + 1) * DMODEL,
                                        lnb + (i * 2 + 1) * DMODEL, hh);
        run_gemm(hh, wt + OFF_W1 + (size_t)i * 4 * M1, b1 + i * DFF, nullptr,
                 nullptr, fh, MTOK, DFF, DMODEL, 1);
        float* dst = (i == nlayers - 1) ? out : xb;
        run_gemm(fh, wt + OFF_W2 + (size_t)i * 4 * M1, b2 + i * DMODEL, xb,
                 dst, nullptr, MTOK, DMODEL, DFF, 0);
    }
}

// round 4
// speedup vs baseline: 5.3813x; 1.5250x over previous
#include <cuda_runtime.h>
#include <cuda_fp16.h>
#include <cstdint>
#include <math.h>

#define DMODEL 1024
#define BATCH  8
#define SEQ    512
#define NHEAD  16
#define DKH    64
#define MTOK   4096
#define DFF    4096
#define NCLIP  64
#define LN_EPS 1e-5f

typedef __half half_t;

// ---------------------------------------------------------------------------
// PTX helpers (arch-agnostic: mma.sync / ldmatrix / cp.async only)
// ---------------------------------------------------------------------------
__device__ __forceinline__ uint32_t smem_u32(const void* p) {
    uint32_t a;
    asm("{ .reg .u64 t; cvta.to.shared.u64 t, %1; cvt.u32.u64 %0, t; }" : "=r"(a) : "l"(p));
    return a;
}

#define LDSM4(r, a) \
    asm volatile("ldmatrix.sync.aligned.m8n8.x4.shared.b16 {%0,%1,%2,%3}, [%4];" \
        : "=r"((r)[0]), "=r"((r)[1]), "=r"((r)[2]), "=r"((r)[3]) : "r"(a))

#define LDSM4T(r, a) \
    asm volatile("ldmatrix.sync.aligned.m8n8.x4.trans.shared.b16 {%0,%1,%2,%3}, [%4];" \
        : "=r"((r)[0]), "=r"((r)[1]), "=r"((r)[2]), "=r"((r)[3]) : "r"(a))

#define MMA16816(c, a, b0, b1) \
    asm volatile("mma.sync.aligned.m16n8k16.row.col.f32.f16.f16.f32 " \
        "{%0,%1,%2,%3}, {%4,%5,%6,%7}, {%8,%9}, {%0,%1,%2,%3};" \
        : "+f"((c)[0]), "+f"((c)[1]), "+f"((c)[2]), "+f"((c)[3]) \
        : "r"((a)[0]), "r"((a)[1]), "r"((a)[2]), "r"((a)[3]), "r"(b0), "r"(b1))

#define CPASYNC16(d, s) asm volatile("cp.async.cg.shared.global [%0], [%1], 16;" :: "r"(d), "l"(s))
#define CPCOMMIT()      asm volatile("cp.async.commit_group;" ::: "memory")
#define CPWAIT(n)       asm volatile("cp.async.wait_group %0;" :: "n"(n) : "memory")

__device__ __forceinline__ uint32_t packh2(float x, float y) {
    __half2 h = __floats2half2_rn(x, y);
    return *(uint32_t*)&h;
}

// ---------------------------------------------------------------------------
// Device scratch
// ---------------------------------------------------------------------------
#define WT_TOT (34u * 1024u * 1024u)
__device__ half_t g_wt[WT_TOT];
__device__ half_t g_xh[MTOK * DMODEL];
__device__ half_t g_hh[MTOK * DMODEL];
__device__ half_t g_ah[MTOK * DMODEL];
__device__ half_t g_fh[MTOK * DFF];
__device__ half_t g_qkvh[3 * 128 * SEQ * DKH];
__device__ float  g_q[MTOK * DMODEL];
__device__ float  g_k[MTOK * DMODEL];
__device__ float  g_v[MTOK * DMODEL];
__device__ float  g_t1[MTOK * DMODEL];
__device__ float  g_t2[MTOK * DMODEL];
__device__ float  g_t3[MTOK * DMODEL];
__device__ float  g_xb[MTOK * DMODEL];

// weight offsets (units of 1M elements) inside g_wt
#define M1 (1024u * 1024u)
#define OFF_ST  0u           // 6*M1 : sw0,sw1,sw2,tw0,tw1,tw2  [1024][1024] each
#define OFF_SW3 (6u * M1)
#define OFF_TW3 (7u * M1)
#define OFF_FW  (8u * M1)    // 2*M1 : fusion [1024][2048]
#define OFF_AW  (10u * M1)   // per layer 4*M1
#define OFF_W1  (18u * M1)   // per layer 4*M1 [4096][1024]
#define OFF_W2  (26u * M1)   // per layer 4*M1 [1024][4096]

// ---------------------------------------------------------------------------
// fp16 HMMA GEMM: C[M,N] = A[M,K] @ Wt[N,K]^T, templated epilogue.
// MODE 0: standard (bias, R, Cf fp32, Ch fp16 w/ ldC)
// MODE 1: QKV scatter -> fp16 [qkv][b*16+h][s][d]  (Ch = qkvh base)
// MODE 2: six fp32 buffers by col/1024 (bias for c<3072, bias2 after)
// ---------------------------------------------------------------------------
#define STAGES 3
#define STAGE_BYTES 16384
#define SMEM_GEMM (STAGES * STAGE_BYTES)

template<int MODE>
__global__ __launch_bounds__(256)
void gemm_hmma(const half_t* __restrict__ A, const half_t* __restrict__ B,
               const float* __restrict__ bias, const float* __restrict__ bias2,
               const float* __restrict__ R, float* Cf, half_t* Ch,
               int M, int N, int K, int relu, int ldC,
               float* q0, float* q1, float* q2, float* q3, float* q4, float* q5)
{
    extern __shared__ char smem[];
    uint32_t sb = smem_u32(smem);
    const int tid = threadIdx.x;
    const int lane = tid & 31, warp = tid >> 5;
    const int row0 = blockIdx.y * 128, col0 = blockIdx.x * 128;
    const int wm = (warp >> 2) * 64;
    const int wn = (warp & 3) * 32;

    int segr[2], segc[2];
#pragma unroll
    for (int i = 0; i < 2; i++) { int s = tid + i * 256; segr[i] = s >> 2; segc[i] = s & 3; }

    int rA[4], swA[4];
#pragma unroll
    for (int mt = 0; mt < 4; mt++) {
        int r = wm + mt * 16 + (lane & 15);
        rA[mt] = r; swA[mt] = (r >> 1) & 3;
    }
    int rB[2], swB[2];
#pragma unroll
    for (int n2 = 0; n2 < 2; n2++) {
        int r = wn + n2 * 16 + (lane & 7) + ((lane >> 4) << 3);
        rB[n2] = r; swB[n2] = (r >> 1) & 3;
    }
    const int csA = lane >> 4;
    const int csB = (lane >> 3) & 1;

    float acc[4][4][4];
#pragma unroll
    for (int mt = 0; mt < 4; mt++)
#pragma unroll
        for (int nt = 0; nt < 4; nt++)
#pragma unroll
            for (int i = 0; i < 4; i++) acc[mt][nt][i] = 0.f;

    const int NT = K / 32;

#define GISSUE(kt, st) do { \
    uint32_t sA_ = sb + (st) * STAGE_BYTES; \
    uint32_t sB_ = sA_ + 8192; \
    _Pragma("unroll") for (int i = 0; i < 2; i++) { \
        int r_ = segr[i], c_ = segc[i]; \
        uint32_t sw_ = (uint32_t)((c_ ^ ((r_ >> 1) & 3)) << 4); \
        CPASYNC16(sA_ + r_ * 64 + sw_, A + (size_t)(row0 + r_) * K + (size_t)(kt) * 32 + c_ * 8); \
        CPASYNC16(sB_ + r_ * 64 + sw_, B + (size_t)(col0 + r_) * K + (size_t)(kt) * 32 + c_ * 8); \
    } \
    CPCOMMIT(); } while (0)

    GISSUE(0, 0);
    GISSUE(1, 1);

    for (int kt = 0; kt < NT; kt++) {
        if (kt == NT - 1) { CPWAIT(0); } else { CPWAIT(1); }
        __syncthreads();
        if (kt + 2 < NT) GISSUE(kt + 2, (kt + 2) % 3);

        uint32_t sA = sb + (kt % 3) * STAGE_BYTES;
        uint32_t sB = sA + 8192;
#pragma unroll
        for (int k16 = 0; k16 < 2; k16++) {
            uint32_t ra[4][4], rb[2][4];
#pragma unroll
            for (int mt = 0; mt < 4; mt++)
                LDSM4(ra[mt], sA + rA[mt] * 64 + ((((k16 << 1) + csA) ^ swA[mt]) << 4));
#pragma unroll
            for (int n2 = 0; n2 < 2; n2++)
                LDSM4(rb[n2], sB + rB[n2] * 64 + ((((k16 << 1) + csB) ^ swB[n2]) << 4));
#pragma unroll
            for (int mt = 0; mt < 4; mt++)
#pragma unroll
                for (int nt = 0; nt < 4; nt++)
                    MMA16816(acc[mt][nt], ra[mt],
                             rb[nt >> 1][(nt & 1) * 2], rb[nt >> 1][(nt & 1) * 2 + 1]);
        }
    }

    // Epilogue
    float* obuf = nullptr;
    if (MODE == 2) {
        int bsel = col0 >> 10;
        obuf = (bsel == 0) ? q0 : (bsel == 1) ? q1 : (bsel == 2) ? q2 :
               (bsel == 3) ? q3 : (bsel == 4) ? q4 : q5;
    }
#pragma unroll
    for (int mt = 0; mt < 4; mt++) {
        int rg = row0 + wm + mt * 16 + (lane >> 2);
#pragma unroll
        for (int nt = 0; nt < 4; nt++) {
            int c = col0 + wn + nt * 8 + (lane & 3) * 2;
            float* a = acc[mt][nt];
#pragma unroll
            for (int h = 0; h < 2; h++) {
                int row = rg + h * 8;
                float v0 = a[h * 2], v1 = a[h * 2 + 1];
                if (MODE == 0) {
                    if (bias) { v0 += bias[c]; v1 += bias[c + 1]; }
                    if (R) {
                        float2 rr = *(const float2*)(R + (size_t)row * N + c);
                        v0 += rr.x; v1 += rr.y;
                    }
                    if (relu) { v0 = fmaxf(v0, 0.f); v1 = fmaxf(v1, 0.f); }
                    if (Cf) {
                        float2 o; o.x = v0; o.y = v1;
                        *(float2*)(Cf + (size_t)row * ldC + c) = o;
                    }
                    if (Ch)
                        *(__half2*)(Ch + (size_t)row * ldC + c) = __floats2half2_rn(v0, v1);
                } else if (MODE == 1) {
                    v0 += bias[c]; v1 += bias[c + 1];
                    int qkv = c >> 10, hh_ = (c >> 6) & 15, d = c & 63;
                    int b = row >> 9, srow = row & 511;
                    size_t dst = (((size_t)(qkv * 128 + b * 16 + hh_) * 512) + srow) * 64 + d;
                    *(__half2*)(Ch + dst) = __floats2half2_rn(v0, v1);
                } else {
                    float b0v = (c < 3072) ? bias[c] : bias2[c - 3072];
                    float b1v = (c + 1 < 3072) ? bias[c + 1] : bias2[c + 1 - 3072];
                    float2 o; o.x = v0 + b0v; o.y = v1 + b1v;
                    *(float2*)(obuf + (size_t)row * 1024 + (c & 1023)) = o;
                }
            }
        }
    }
}

// ---------------------------------------------------------------------------
// Flash attention (encoder): per (b,h) 512x512, fp16 mma, online softmax.
// grid (4, 128), 256 threads (8 warps x 16 q-rows).
// ---------------------------------------------------------------------------
#define FLD 72
#define SMEM_FLASH (3 * 128 * FLD * 2 + 512)

__global__ __launch_bounds__(256)
void flash_attn(const half_t* __restrict__ qkvh, const int* __restrict__ mask,
                half_t* __restrict__ out)
{
    extern __shared__ char sm[];
    half_t* Qs = (half_t*)sm;
    half_t* Ks = Qs + 128 * FLD;
    half_t* Vs = Ks + 128 * FLD;
    float*  mf = (float*)(Vs + 128 * FLD);

    const int bh = blockIdx.y, qt = blockIdx.x;
    const int b = bh >> 4, hd = bh & 15;
    const int tid = threadIdx.x, lane = tid & 31, warp = tid >> 5;
    const int m0 = warp * 16;

    const half_t* Qg = qkvh + (((size_t)(0 * 128 + bh) * 512) + qt * 128) * 64;
    const half_t* Kg = qkvh + ((size_t)(1 * 128 + bh) * 512) * 64;
    const half_t* Vg = qkvh + ((size_t)(2 * 128 + bh) * 512) * 64;

    for (int i = tid; i < 1024; i += 256) {
        int r = i >> 3, cs = i & 7;
        *(uint4*)(Qs + r * FLD + cs * 8) = *(const uint4*)(Qg + r * 64 + cs * 8);
    }
    __syncthreads();

    uint32_t qf[4][4];
#pragma unroll
    for (int kb = 0; kb < 4; kb++)
        LDSM4(qf[kb], smem_u32(Qs + (m0 + (lane & 15)) * FLD + kb * 16 + (lane >> 4) * 8));

    float mrow[2] = {-1e30f, -1e30f};
    float lrow[2] = {0.f, 0.f};
    float oacc[8][4];
#pragma unroll
    for (int i = 0; i < 8; i++)
#pragma unroll
        for (int j = 0; j < 4; j++) oacc[i][j] = 0.f;

    for (int kt = 0; kt < 4; kt++) {
        __syncthreads();
        for (int i = tid; i < 1024; i += 256) {
            int r = i >> 3, cs = i & 7;
            *(uint4*)(Ks + r * FLD + cs * 8) = *(const uint4*)(Kg + (kt * 128 + r) * 64 + cs * 8);
            *(uint4*)(Vs + r * FLD + cs * 8) = *(const uint4*)(Vg + (kt * 128 + r) * 64 + cs * 8);
        }
        if (tid < 128) mf[tid] = (mask[b * SEQ + kt * 128 + tid] == 0) ? 1.f : 0.f;
        __syncthreads();

        float s[16][4];
#pragma unroll
        for (int f = 0; f < 16; f++)
#pragma unroll
            for (int i = 0; i < 4; i++) s[f][i] = 0.f;

#pragma unroll
        for (int kb = 0; kb < 4; kb++) {
#pragma unroll
            for (int nb2 = 0; nb2 < 8; nb2++) {
                uint32_t bf[4];
                int krow = nb2 * 16 + (lane & 7) + ((lane >> 4) & 1) * 8;
                int kcol = kb * 16 + ((lane >> 3) & 1) * 8;
                LDSM4(bf, smem_u32(Ks + krow * FLD + kcol));
                MMA16816(s[2 * nb2],     qf[kb], bf[0], bf[1]);
                MMA16816(s[2 * nb2 + 1], qf[kb], bf[2], bf[3]);
            }
        }

        // mask + scale
#pragma unroll
        for (int f = 0; f < 16; f++) {
            int c0 = f * 8 + (lane & 3) * 2;
            float f0 = mf[c0], f1 = mf[c0 + 1];
            s[f][0] = (f0 != 0.f) ? -1e9f : s[f][0] * 0.125f;
            s[f][1] = (f1 != 0.f) ? -1e9f : s[f][1] * 0.125f;
            s[f][2] = (f0 != 0.f) ? -1e9f : s[f][2] * 0.125f;
            s[f][3] = (f1 != 0.f) ? -1e9f : s[f][3] * 0.125f;
        }

        // online softmax
        float mx0 = -1e30f, mx1 = -1e30f;
#pragma unroll
        for (int f = 0; f < 16; f++) {
            mx0 = fmaxf(mx0, fmaxf(s[f][0], s[f][1]));
            mx1 = fmaxf(mx1, fmaxf(s[f][2], s[f][3]));
        }
        mx0 = fmaxf(mx0, __shfl_xor_sync(0xffffffffu, mx0, 1));
        mx0 = fmaxf(mx0, __shfl_xor_sync(0xffffffffu, mx0, 2));
        mx1 = fmaxf(mx1, __shfl_xor_sync(0xffffffffu, mx1, 1));
        mx1 = fmaxf(mx1, __shfl_xor_sync(0xffffffffu, mx1, 2));

        float Mn0 = fmaxf(mrow[0], mx0), Mn1 = fmaxf(mrow[1], mx1);
        float sc0 = __expf(mrow[0] - Mn0), sc1 = __expf(mrow[1] - Mn1);
        mrow[0] = Mn0; mrow[1] = Mn1;

        float rs0 = 0.f, rs1 = 0.f;
#pragma unroll
        for (int f = 0; f < 16; f++) {
            s[f][0] = __expf(s[f][0] - Mn0); s[f][1] = __expf(s[f][1] - Mn0);
            s[f][2] = __expf(s[f][2] - Mn1); s[f][3] = __expf(s[f][3] - Mn1);
            rs0 += s[f][0] + s[f][1];
            rs1 += s[f][2] + s[f][3];
        }
        rs0 += __shfl_xor_sync(0xffffffffu, rs0, 1);
        rs0 += __shfl_xor_sync(0xffffffffu, rs0, 2);
        rs1 += __shfl_xor_sync(0xffffffffu, rs1, 1);
        rs1 += __shfl_xor_sync(0xffffffffu, rs1, 2);
        lrow[0] = lrow[0] * sc0 + rs0;
        lrow[1] = lrow[1] * sc1 + rs1;

#pragma unroll
        for (int nb = 0; nb < 8; nb++) {
            oacc[nb][0] *= sc0; oacc[nb][1] *= sc0;
            oacc[nb][2] *= sc1; oacc[nb][3] *= sc1;
        }

        // O += P @ V
#pragma unroll
        for (int kb = 0; kb < 8; kb++) {
            uint32_t a[4];
            a[0] = packh2(s[2 * kb][0],     s[2 * kb][1]);
            a[1] = packh2(s[2 * kb][2],     s[2 * kb][3]);
            a[2] = packh2(s[2 * kb + 1][0], s[2 * kb + 1][1]);
            a[3] = packh2(s[2 * kb + 1][2], s[2 * kb + 1][3]);
#pragma unroll
            for (int nb2 = 0; nb2 < 4; nb2++) {
                uint32_t vf[4];
                int srow = kb * 16 + (lane & 15);
                int dcol = nb2 * 16 + (lane >> 4) * 8;
                LDSM4T(vf, smem_u32(Vs + srow * FLD + dcol));
                MMA16816(oacc[2 * nb2],     a, vf[0], vf[1]);
                MMA16816(oacc[2 * nb2 + 1], a, vf[2], vf[3]);
            }
        }
    }

    float inv0 = 1.f / lrow[0], inv1 = 1.f / lrow[1];
    int r0 = qt * 128 + m0 + (lane >> 2);
#pragma unroll
    for (int nb = 0; nb < 8; nb++) {
        int c = hd * 64 + nb * 8 + (lane & 3) * 2;
        *(__half2*)(out + (size_t)(b * SEQ + r0) * DMODEL + c) =
            __floats2half2_rn(oacc[nb][0] * inv0, oacc[nb][1] * inv0);
        *(__half2*)(out + (size_t)(b * SEQ + r0 + 8) * DMODEL + c) =
            __floats2half2_rn(oacc[nb][2] * inv1, oacc[nb][3] * inv1);
    }
}

// ---------------------------------------------------------------------------
// Weight transpose + fp16 convert: W[K,N] -> Wt[N,K]
// ---------------------------------------------------------------------------
__global__ void wconv_kernel(const float* __restrict__ W, half_t* Wt, int K, int N)
{
    __shared__ float t[32][33];
    int n0 = blockIdx.x * 32, k0 = blockIdx.y * 32;
    int tx = threadIdx.x & 31, ty = threadIdx.x >> 5;
    for (int r = ty; r < 32; r += 8) t[r][tx] = W[(size_t)(k0 + r) * N + n0 + tx];
    __syncthreads();
    for (int r = ty; r < 32; r += 8)
        Wt[(size_t)(n0 + r) * K + k0 + tx] = __float2half_rn(t[tx][r]);
}

__global__ void aconv_kernel(const float* __restrict__ x, half_t* o, int n)
{
    int i = (blockIdx.x * blockDim.x + threadIdx.x) * 4;
    if (i >= n) return;
    float4 v = *(const float4*)(x + i);
    *(__half2*)(o + i)     = __floats2half2_rn(v.x, v.y);
    *(__half2*)(o + i + 2) = __floats2half2_rn(v.z, v.w);
}

// ---------------------------------------------------------------------------
// Spatial attention (clip=8), fp32 in, fp16 out
// ---------------------------------------------------------------------------
__global__ void spatial_attn_kernel(const float* __restrict__ q,
                                    const float* __restrict__ k,
                                    const float* __restrict__ v,
                                    const int* __restrict__ mask,
                                    half_t* __restrict__ oh)
{
    __shared__ float Qs[8][64], Ks[8][64], Vs[8][64], Ps[8][8];
    int u = blockIdx.x;
    int h = u & 15;
    int c = (u >> 4) & 63;
    int b = u >> 10;
    int tb = b * SEQ + c * 8;
    int tid = threadIdx.x;

    for (int idx = tid; idx < 512; idx += 64) {
        int r = idx >> 6, d = idx & 63;
        int g = (tb + r) * DMODEL + h * DKH + d;
        Qs[r][d] = q[g]; Ks[r][d] = k[g]; Vs[r][d] = v[g];
    }
    __syncthreads();

    int i = tid >> 3, j = tid & 7;
    float s = 0.f;
#pragma unroll
    for (int d = 0; d < 64; d++) s += Qs[i][d] * Ks[j][d];
    s *= 0.125f;
    if (mask[b * SEQ + c * 8 + j] == 0) s = -1e9f;

    float m = s;
    m = fmaxf(m, __shfl_xor_sync(0xffffffffu, m, 1));
    m = fmaxf(m, __shfl_xor_sync(0xffffffffu, m, 2));
    m = fmaxf(m, __shfl_xor_sync(0xffffffffu, m, 4));
    float p = expf(s - m);
    float sum = p;
    sum += __shfl_xor_sync(0xffffffffu, sum, 1);
    sum += __shfl_xor_sync(0xffffffffu, sum, 2);
    sum += __shfl_xor_sync(0xffffffffu, sum, 4);
    Ps[i][j] = p / sum;
    __syncthreads();

    for (int idx = tid; idx < 512; idx += 64) {
        int r = idx >> 6, d = idx & 63;
        float o = 0.f;
#pragma unroll
        for (int jj = 0; jj < 8; jj++) o += Ps[r][jj] * Vs[jj][d];
        oh[(size_t)(tb + r) * DMODEL + h * DKH + d] = __float2half_rn(o);
    }
}

// ---------------------------------------------------------------------------
// Temporal attention (64 clips), fp32 in, fp16 out
// ---------------------------------------------------------------------------
__global__ __launch_bounds__(256)
void temporal_attn_kernel(const float* __restrict__ q,
                          const float* __restrict__ k,
                          const float* __restrict__ v,
                          const int* __restrict__ mask,
                          half_t* __restrict__ oh)
{
    __shared__ float QV[64][64];
    __shared__ float Ks[64][64];
    __shared__ float Pst[64][64];

    int u = blockIdx.x;
    int h = u & 15;
    int jpos = (u >> 4) & 7;
    int b = u >> 7;
    int tid = threadIdx.x;
    int tx = tid & 15, ty = tid >> 4;

    for (int idx = tid; idx < 1024; idx += 256) {
        int r = idx >> 4;
        int d0 = (idx & 15) << 2;
        int g = (b * SEQ + r * 8 + jpos) * DMODEL + h * DKH + d0;
        float4 qv = *(const float4*)(q + g);
        QV[d0 + 0][r] = qv.x; QV[d0 + 1][r] = qv.y;
        QV[d0 + 2][r] = qv.z; QV[d0 + 3][r] = qv.w;
        float4 kv = *(const float4*)(k + g);
        Ks[d0 + 0][r] = kv.x; Ks[d0 + 1][r] = kv.y;
        Ks[d0 + 2][r] = kv.z; Ks[d0 + 3][r] = kv.w;
    }
    __syncthreads();

    float acc[4][4];
#pragma unroll
    for (int i = 0; i < 4; i++)
#pragma unroll
        for (int j = 0; j < 4; j++) acc[i][j] = 0.f;

    for (int d = 0; d < 64; d++) {
        float4 a = *(const float4*)&QV[d][ty * 4];
        float4 bb = *(const float4*)&Ks[d][tx * 4];
        float av[4] = {a.x, a.y, a.z, a.w};
        float bvv[4] = {bb.x, bb.y, bb.z, bb.w};
#pragma unroll
        for (int i = 0; i < 4; i++)
#pragma unroll
            for (int j = 0; j < 4; j++) acc[i][j] += av[i] * bvv[j];
    }
#pragma unroll
    for (int jj = 0; jj < 4; jj++) {
        int cc = tx * 4 + jj;
        float mv = (mask[b * SEQ + cc * 8 + jpos] == 0) ? -1e9f : 0.f;
#pragma unroll
        for (int i = 0; i < 4; i++)
            Pst[cc][ty * 4 + i] = (mv != 0.f) ? -1e9f : acc[i][jj] * 0.125f;
    }
    __syncthreads();

    if (tid < 64) {
        float m = -1e30f;
        for (int cc = 0; cc < 64; cc++) m = fmaxf(m, Pst[cc][tid]);
        float sum = 0.f;
        for (int cc = 0; cc < 64; cc++) {
            float p = expf(Pst[cc][tid] - m);
            Pst[cc][tid] = p; sum += p;
        }
        float inv = 1.f / sum;
        for (int cc = 0; cc < 64; cc++) Pst[cc][tid] *= inv;
    }
    __syncthreads();

    for (int idx = tid; idx < 1024; idx += 256) {
        int r = idx >> 4;
        int d0 = (idx & 15) << 2;
        float4 vv = *(const float4*)(v + (b * SEQ + r * 8 + jpos) * DMODEL + h * DKH + d0);
        *(float4*)&QV[r][d0] = vv;
    }
    __syncthreads();

    float oacc[4][4];
#pragma unroll
    for (int i = 0; i < 4; i++)
#pragma unroll
        for (int j = 0; j < 4; j++) oacc[i][j] = 0.f;

    for (int kk = 0; kk < 64; kk++) {
        float4 a = *(const float4*)&Pst[kk][ty * 4];
        float4 bb = *(const float4*)&QV[kk][tx * 4];
        float av[4] = {a.x, a.y, a.z, a.w};
        float bvv[4] = {bb.x, bb.y, bb.z, bb.w};
#pragma unroll
        for (int i = 0; i < 4; i++)
#pragma unroll
            for (int j = 0; j < 4; j++) oacc[i][j] += av[i] * bvv[j];
    }
#pragma unroll
    for (int i = 0; i < 4; i++)
#pragma unroll
        for (int jj = 0; jj < 4; jj++)
            oh[(size_t)(b * SEQ + (ty * 4 + i) * 8 + jpos) * DMODEL + h * DKH + tx * 4 + jj] =
                __float2half_rn(oacc[i][jj]);
}

// ---------------------------------------------------------------------------
// LayerNorm fp32 in -> fp16 out
// ---------------------------------------------------------------------------
__global__ void layernorm_kernel(const float* __restrict__ x,
                                 const float* __restrict__ gamma,
                                 const float* __restrict__ beta,
                                 half_t* __restrict__ oh)
{
    __shared__ float sh1[8], sh2[8];
    int row = blockIdx.x;
    int tid = threadIdx.x;
    const float* xr = x + (size_t)row * DMODEL;
    float4 v = *(const float4*)(xr + tid * 4);
    float s1 = v.x + v.y + v.z + v.w;
    float s2 = v.x * v.x + v.y * v.y + v.z * v.z + v.w * v.w;
#pragma unroll
    for (int o = 16; o; o >>= 1) {
        s1 += __shfl_xor_sync(0xffffffffu, s1, o);
        s2 += __shfl_xor_sync(0xffffffffu, s2, o);
    }
    if ((tid & 31) == 0) { sh1[tid >> 5] = s1; sh2[tid >> 5] = s2; }
    __syncthreads();
    if (tid == 0) {
        float a = 0.f, b2 = 0.f;
        for (int i = 0; i < 8; i++) { a += sh1[i]; b2 += sh2[i]; }
        sh1[0] = a * (1.f / DMODEL);
        sh2[0] = b2 * (1.f / DMODEL);
    }
    __syncthreads();
    float mean = sh1[0];
    float var = sh2[0] - mean * mean;
    float inv = rsqrtf(var + LN_EPS);
    float4 g = *(const float4*)(gamma + tid * 4);
    float4 bb = *(const float4*)(beta + tid * 4);
    size_t base = (size_t)row * DMODEL + tid * 4;
    *(__half2*)(oh + base) =
        __floats2half2_rn((v.x - mean) * inv * g.x + bb.x,
                          (v.y - mean) * inv * g.y + bb.y);
    *(__half2*)(oh + base + 2) =
        __floats2half2_rn((v.z - mean) * inv * g.z + bb.z,
                          (v.w - mean) * inv * g.w + bb.w);
}

// ---------------------------------------------------------------------------
// Host orchestration
// ---------------------------------------------------------------------------
static inline void run_wconv(const float* W, half_t* Wt, int K, int N)
{
    wconv_kernel<<<dim3(N / 32, K / 32), 256>>>(W, Wt, K, N);
}

extern "C" void kernel_launch(void* const* d_in, const int* in_sizes, int n_in,
                              void* d_out, int out_size)
{
    (void)n_in; (void)out_size;
    const float* x    = (const float*)d_in[0];
    const int*   mask = (const int*)  d_in[1];
    const float* sw   = (const float*)d_in[2];
    const float* sb   = (const float*)d_in[3];
    const float* tw   = (const float*)d_in[4];
    const float* tbia = (const float*)d_in[5];
    const float* fw   = (const float*)d_in[6];
    const float* fb   = (const float*)d_in[7];
    const float* aw   = (const float*)d_in[8];
    const float* ab   = (const float*)d_in[9];
    const float* w1   = (const float*)d_in[10];
    const float* b1   = (const float*)d_in[11];
    const float* w2   = (const float*)d_in[12];
    const float* b2   = (const float*)d_in[13];
    const float* lns  = (const float*)d_in[14];
    const float* lnb  = (const float*)d_in[15];
    float* out = (float*)d_out;

    cudaFuncSetAttribute(gemm_hmma<0>, cudaFuncAttributeMaxDynamicSharedMemorySize, SMEM_GEMM);
    cudaFuncSetAttribute(gemm_hmma<1>, cudaFuncAttributeMaxDynamicSharedMemorySize, SMEM_GEMM);
    cudaFuncSetAttribute(gemm_hmma<2>, cudaFuncAttributeMaxDynamicSharedMemorySize, SMEM_GEMM);
    cudaFuncSetAttribute(flash_attn,   cudaFuncAttributeMaxDynamicSharedMemorySize, SMEM_FLASH);

    half_t *wt, *xh, *hh, *ah, *fh, *qkvh;
    float *q, *k, *v, *t1, *t2, *t3, *xb;
    cudaGetSymbolAddress((void**)&wt,   g_wt);
    cudaGetSymbolAddress((void**)&xh,   g_xh);
    cudaGetSymbolAddress((void**)&hh,   g_hh);
    cudaGetSymbolAddress((void**)&ah,   g_ah);
    cudaGetSymbolAddress((void**)&fh,   g_fh);
    cudaGetSymbolAddress((void**)&qkvh, g_qkvh);
    cudaGetSymbolAddress((void**)&q,    g_q);
    cudaGetSymbolAddress((void**)&k,    g_k);
    cudaGetSymbolAddress((void**)&v,    g_v);
    cudaGetSymbolAddress((void**)&t1,   g_t1);
    cudaGetSymbolAddress((void**)&t2,   g_t2);
    cudaGetSymbolAddress((void**)&t3,   g_t3);
    cudaGetSymbolAddress((void**)&xb,   g_xb);

    const size_t DD = (size_t)DMODEL * DMODEL;

    // ---- transpose+convert all weights to fp16 [N,K] ----
    for (int j = 0; j < 3; j++) {
        run_wconv(sw + j * DD, wt + OFF_ST + j * M1,       DMODEL, DMODEL);
        run_wconv(tw + j * DD, wt + OFF_ST + (3 + j) * M1, DMODEL, DMODEL);
    }
    run_wconv(sw + 3 * DD, wt + OFF_SW3, DMODEL, DMODEL);
    run_wconv(tw + 3 * DD, wt + OFF_TW3, DMODEL, DMODEL);
    run_wconv(fw, wt + OFF_FW, 2 * DMODEL, DMODEL);
    int nlayers = in_sizes[8] / (int)(4 * DD);
    for (int i = 0; i < nlayers; i++) {
        for (int j = 0; j < 4; j++)
            run_wconv(aw + (i * 4 + j) * DD, wt + OFF_AW + (i * 4 + j) * M1, DMODEL, DMODEL);
        run_wconv(w1 + (size_t)i * DMODEL * DFF, wt + OFF_W1 + i * 4 * M1, DMODEL, DFF);
        run_wconv(w2 + (size_t)i * DFF * DMODEL, wt + OFF_W2 + i * 4 * M1, DFF, DMODEL);
    }

    aconv_kernel<<<(MTOK * DMODEL / 4 + 255) / 256, 256>>>(x, xh, MTOK * DMODEL);

    // ---- spatial+temporal QKV: one N=6144 GEMM into 6 fp32 buffers ----
    gemm_hmma<2><<<dim3(48, 32), 256, SMEM_GEMM>>>(
        xh, wt + OFF_ST, sb, tbia, nullptr, nullptr, nullptr,
        MTOK, 6144, DMODEL, 0, 0, q, k, v, t1, t2, t3);

    // ---- spatial ----
    spatial_attn_kernel<<<BATCH * NCLIP * NHEAD, 64>>>(q, k, v, mask, ah);
    gemm_hmma<0><<<dim3(8, 32), 256, SMEM_GEMM>>>(
        ah, wt + OFF_SW3, sb + 3 * DMODEL, nullptr, nullptr, nullptr, fh,
        MTOK, DMODEL, DMODEL, 0, 2048, nullptr, nullptr, nullptr, nullptr, nullptr, nullptr);

    // ---- temporal ----
    temporal_attn_kernel<<<BATCH * 8 * NHEAD, 256>>>(t1, t2, t3, mask, ah);
    gemm_hmma<0><<<dim3(8, 32), 256, SMEM_GEMM>>>(
        ah, wt + OFF_TW3, tbia + 3 * DMODEL, nullptr, nullptr, nullptr, fh + 1024,
        MTOK, DMODEL, DMODEL, 0, 2048, nullptr, nullptr, nullptr, nullptr, nullptr, nullptr);

    // ---- fusion: xb = concat(spa,tem) @ Fw^T + fb ----
    gemm_hmma<0><<<dim3(8, 32), 256, SMEM_GEMM>>>(
        fh, wt + OFF_FW, fb, nullptr, nullptr, xb, nullptr,
        MTOK, DMODEL, 2 * DMODEL, 0, DMODEL, nullptr, nullptr, nullptr, nullptr, nullptr, nullptr);

    // ---- encoder layers ----
    for (int i = 0; i < nlayers; i++) {
        const float* abi = ab + (size_t)i * 4 * DMODEL;
        const half_t* awi = wt + OFF_AW + (size_t)i * 4 * M1;

        layernorm_kernel<<<MTOK, 256>>>(xb, lns + (i * 2 + 0) * DMODEL,
                                        lnb + (i * 2 + 0) * DMODEL, hh);
        // fused QKV -> fp16 head-major
        gemm_hmma<1><<<dim3(24, 32), 256, SMEM_GEMM>>>(
            hh, awi, abi, nullptr, nullptr, nullptr, qkvh,
            MTOK, 3 * DMODEL, DMODEL, 0, 0, nullptr, nullptr, nullptr, nullptr, nullptr, nullptr);

        flash_attn<<<dim3(4, 128), 256, SMEM_FLASH>>>(qkvh, mask, ah);

        gemm_hmma<0><<<dim3(8, 32), 256, SMEM_GEMM>>>(
            ah, awi + 3 * M1, abi + 3 * DMODEL, nullptr, xb, xb, nullptr,
            MTOK, DMODEL, DMODEL, 0, DMODEL, nullptr, nullptr, nullptr, nullptr, nullptr, nullptr);

        layernorm_kernel<<<MTOK, 256>>>(xb, lns + (i * 2 + 1) * DMODEL,
                                        lnb + (i * 2 + 1) * DMODEL, hh);
        gemm_hmma<0><<<dim3(32, 32), 256, SMEM_GEMM>>>(
            hh, wt + OFF_W1 + (size_t)i * 4 * M1, b1 + i * DFF, nullptr, nullptr,
            nullptr, fh, MTOK, DFF, DMODEL, 1, DFF, nullptr, nullptr, nullptr, nullptr, nullptr, nullptr);
        float* dst = (i == nlayers - 1) ? out : xb;
        gemm_hmma<0><<<dim3(8, 32), 256, SMEM_GEMM>>>(
            fh, wt + OFF_W2 + (size_t)i * 4 * M1, b2 + i * DMODEL, nullptr, xb,
            dst, nullptr, MTOK, DMODEL, DFF, 0, DMODEL, nullptr, nullptr, nullptr, nullptr, nullptr, nullptr);
    }
}

// round 5
// speedup vs baseline: 5.5731x; 1.0356x over previous
#include <cuda_runtime.h>
#include <cuda_fp16.h>
#include <cstdint>
#include <math.h>

#define DMODEL 1024
#define BATCH  8
#define SEQ    512
#define NHEAD  16
#define DKH    64
#define MTOK   4096
#define DFF    4096
#define NCLIP  64
#define LN_EPS 1e-5f

typedef __half half_t;

// ---------------------------------------------------------------------------
// PTX helpers (arch-agnostic: mma.sync / ldmatrix / cp.async only)
// ---------------------------------------------------------------------------
__device__ __forceinline__ uint32_t smem_u32(const void* p) {
    uint32_t a;
    asm("{ .reg .u64 t; cvta.to.shared.u64 t, %1; cvt.u32.u64 %0, t; }" : "=r"(a) : "l"(p));
    return a;
}

#define LDSM4(r, a) \
    asm volatile("ldmatrix.sync.aligned.m8n8.x4.shared.b16 {%0,%1,%2,%3}, [%4];" \
        : "=r"((r)[0]), "=r"((r)[1]), "=r"((r)[2]), "=r"((r)[3]) : "r"(a))

#define LDSM4T(r, a) \
    asm volatile("ldmatrix.sync.aligned.m8n8.x4.trans.shared.b16 {%0,%1,%2,%3}, [%4];" \
        : "=r"((r)[0]), "=r"((r)[1]), "=r"((r)[2]), "=r"((r)[3]) : "r"(a))

#define MMA16816(c, a, b0, b1) \
    asm volatile("mma.sync.aligned.m16n8k16.row.col.f32.f16.f16.f32 " \
        "{%0,%1,%2,%3}, {%4,%5,%6,%7}, {%8,%9}, {%0,%1,%2,%3};" \
        : "+f"((c)[0]), "+f"((c)[1]), "+f"((c)[2]), "+f"((c)[3]) \
        : "r"((a)[0]), "r"((a)[1]), "r"((a)[2]), "r"((a)[3]), "r"(b0), "r"(b1))

#define CPASYNC16(d, s) asm volatile("cp.async.cg.shared.global [%0], [%1], 16;" :: "r"(d), "l"(s))
#define CPCOMMIT()      asm volatile("cp.async.commit_group;" ::: "memory")
#define CPWAIT(n)       asm volatile("cp.async.wait_group %0;" :: "n"(n) : "memory")

__device__ __forceinline__ uint32_t packh2(float x, float y) {
    __half2 h = __floats2half2_rn(x, y);
    return *(uint32_t*)&h;
}

// ---------------------------------------------------------------------------
// Device scratch
// ---------------------------------------------------------------------------
#define WT_TOT (34u * 1024u * 1024u)
__device__ half_t g_wt[WT_TOT];
__device__ half_t g_xh[MTOK * DMODEL];
__device__ half_t g_hh[MTOK * DMODEL];
__device__ half_t g_ah[MTOK * DMODEL];
__device__ half_t g_fh[MTOK * DFF];
__device__ half_t g_qkvh[3 * 128 * SEQ * DKH];
__device__ float  g_q[MTOK * DMODEL];
__device__ float  g_k[MTOK * DMODEL];
__device__ float  g_v[MTOK * DMODEL];
__device__ float  g_t1[MTOK * DMODEL];
__device__ float  g_t2[MTOK * DMODEL];
__device__ float  g_t3[MTOK * DMODEL];
__device__ float  g_xb[MTOK * DMODEL];

// weight offsets (units of 1M elements) inside g_wt
#define M1 (1024u * 1024u)
#define DDC (1024u * 1024u)
#define OFF_ST  0u           // 6*M1 : sw0,sw1,sw2,tw0,tw1,tw2
#define OFF_SW3 (6u * M1)
#define OFF_TW3 (7u * M1)
#define OFF_FW  (8u * M1)    // 2*M1 : fusion [1024][2048]
#define OFF_AW  (10u * M1)   // per layer 4*M1
#define OFF_W1  (18u * M1)   // per layer 4*M1 [4096][1024]
#define OFF_W2  (26u * M1)   // per layer 4*M1 [1024][4096]

// ---------------------------------------------------------------------------
// fp16 HMMA GEMM. MODE 0: standard; MODE 1: QKV head-major scatter;
// MODE 2: six fp32 buffers; MODE 3: z-batched (A/B/bias select by z,
// output column offset z*1024 into Ch w/ ldC).
// ---------------------------------------------------------------------------
#define STAGES 3
#define STAGE_BYTES 16384
#define SMEM_GEMM (STAGES * STAGE_BYTES)

template<int MODE>
__global__ __launch_bounds__(256)
void gemm_hmma(const half_t* __restrict__ A, const half_t* __restrict__ B,
               const half_t* __restrict__ A2, const half_t* __restrict__ B2,
               const float* __restrict__ bias, const float* __restrict__ bias2,
               const float* __restrict__ R, float* Cf, half_t* Ch,
               int M, int N, int K, int relu, int ldC,
               float* q0, float* q1, float* q2, float* q3, float* q4, float* q5)
{
    extern __shared__ char smem[];
    uint32_t sb = smem_u32(smem);
    const int tid = threadIdx.x;
    const int lane = tid & 31, warp = tid >> 5;
    const int row0 = blockIdx.y * 128, col0 = blockIdx.x * 128;
    const int wm = (warp >> 2) * 64;
    const int wn = (warp & 3) * 32;

    if (MODE == 3 && blockIdx.z == 1) { A = A2; B = B2; bias = bias2; }

    int segr[2], segc[2];
#pragma unroll
    for (int i = 0; i < 2; i++) { int s = tid + i * 256; segr[i] = s >> 2; segc[i] = s & 3; }

    int rA[4], swA[4];
#pragma unroll
    for (int mt = 0; mt < 4; mt++) {
        int r = wm + mt * 16 + (lane & 15);
        rA[mt] = r; swA[mt] = (r >> 1) & 3;
    }
    int rB[2], swB[2];
#pragma unroll
    for (int n2 = 0; n2 < 2; n2++) {
        int r = wn + n2 * 16 + (lane & 7) + ((lane >> 4) << 3);
        rB[n2] = r; swB[n2] = (r >> 1) & 3;
    }
    const int csA = lane >> 4;
    const int csB = (lane >> 3) & 1;

    float acc[4][4][4];
#pragma unroll
    for (int mt = 0; mt < 4; mt++)
#pragma unroll
        for (int nt = 0; nt < 4; nt++)
#pragma unroll
            for (int i = 0; i < 4; i++) acc[mt][nt][i] = 0.f;

    const int NT = K / 32;

#define GISSUE(kt, st) do { \
    uint32_t sA_ = sb + (st) * STAGE_BYTES; \
    uint32_t sB_ = sA_ + 8192; \
    _Pragma("unroll") for (int i = 0; i < 2; i++) { \
        int r_ = segr[i], c_ = segc[i]; \
        uint32_t sw_ = (uint32_t)((c_ ^ ((r_ >> 1) & 3)) << 4); \
        CPASYNC16(sA_ + r_ * 64 + sw_, A + (size_t)(row0 + r_) * K + (size_t)(kt) * 32 + c_ * 8); \
        CPASYNC16(sB_ + r_ * 64 + sw_, B + (size_t)(col0 + r_) * K + (size_t)(kt) * 32 + c_ * 8); \
    } \
    CPCOMMIT(); } while (0)

    GISSUE(0, 0);
    GISSUE(1, 1);

    for (int kt = 0; kt < NT; kt++) {
        if (kt == NT - 1) { CPWAIT(0); } else { CPWAIT(1); }
        __syncthreads();
        if (kt + 2 < NT) GISSUE(kt + 2, (kt + 2) % 3);

        uint32_t sA = sb + (kt % 3) * STAGE_BYTES;
        uint32_t sB = sA + 8192;
#pragma unroll
        for (int k16 = 0; k16 < 2; k16++) {
            uint32_t ra[4][4], rb[2][4];
#pragma unroll
            for (int mt = 0; mt < 4; mt++)
                LDSM4(ra[mt], sA + rA[mt] * 64 + ((((k16 << 1) + csA) ^ swA[mt]) << 4));
#pragma unroll
            for (int n2 = 0; n2 < 2; n2++)
                LDSM4(rb[n2], sB + rB[n2] * 64 + ((((k16 << 1) + csB) ^ swB[n2]) << 4));
#pragma unroll
            for (int mt = 0; mt < 4; mt++)
#pragma unroll
                for (int nt = 0; nt < 4; nt++)
                    MMA16816(acc[mt][nt], ra[mt],
                             rb[nt >> 1][(nt & 1) * 2], rb[nt >> 1][(nt & 1) * 2 + 1]);
        }
    }

    // Epilogue
    float* obuf = nullptr;
    if (MODE == 2) {
        int bsel = col0 >> 10;
        obuf = (bsel == 0) ? q0 : (bsel == 1) ? q1 : (bsel == 2) ? q2 :
               (bsel == 3) ? q3 : (bsel == 4) ? q4 : q5;
    }
    const int cbase = (MODE == 3) ? (int)blockIdx.z * 1024 : 0;
#pragma unroll
    for (int mt = 0; mt < 4; mt++) {
        int rg = row0 + wm + mt * 16 + (lane >> 2);
#pragma unroll
        for (int nt = 0; nt < 4; nt++) {
            int c = col0 + wn + nt * 8 + (lane & 3) * 2;
            float* a = acc[mt][nt];
#pragma unroll
            for (int h = 0; h < 2; h++) {
                int row = rg + h * 8;
                float v0 = a[h * 2], v1 = a[h * 2 + 1];
                if (MODE == 0) {
                    if (bias) { v0 += bias[c]; v1 += bias[c + 1]; }
                    if (R) {
                        float2 rr = *(const float2*)(R + (size_t)row * N + c);
                        v0 += rr.x; v1 += rr.y;
                    }
                    if (relu) { v0 = fmaxf(v0, 0.f); v1 = fmaxf(v1, 0.f); }
                    if (Cf) {
                        float2 o; o.x = v0; o.y = v1;
                        *(float2*)(Cf + (size_t)row * ldC + c) = o;
                    }
                    if (Ch)
                        *(__half2*)(Ch + (size_t)row * ldC + c) = __floats2half2_rn(v0, v1);
                } else if (MODE == 1) {
                    v0 += bias[c]; v1 += bias[c + 1];
                    int qkv = c >> 10, hh_ = (c >> 6) & 15, d = c & 63;
                    int b = row >> 9, srow = row & 511;
                    size_t dst = (((size_t)(qkv * 128 + b * 16 + hh_) * 512) + srow) * 64 + d;
                    *(__half2*)(Ch + dst) = __floats2half2_rn(v0, v1);
                } else if (MODE == 2) {
                    float b0v = (c < 3072) ? bias[c] : bias2[c - 3072];
                    float b1v = (c + 1 < 3072) ? bias[c + 1] : bias2[c + 1 - 3072];
                    float2 o; o.x = v0 + b0v; o.y = v1 + b1v;
                    *(float2*)(obuf + (size_t)row * 1024 + (c & 1023)) = o;
                } else { // MODE 3
                    v0 += bias[c]; v1 += bias[c + 1];
                    *(__half2*)(Ch + (size_t)row * ldC + cbase + c) = __floats2half2_rn(v0, v1);
                }
            }
        }
    }
}

// ---------------------------------------------------------------------------
// Flash attention (encoder): per (b,h) 512x512, fp16 mma, online softmax.
// ---------------------------------------------------------------------------
#define FLD 72
#define SMEM_FLASH (3 * 128 * FLD * 2 + 512)

__global__ __launch_bounds__(256)
void flash_attn(const half_t* __restrict__ qkvh, const int* __restrict__ mask,
                half_t* __restrict__ out)
{
    extern __shared__ char sm[];
    half_t* Qs = (half_t*)sm;
    half_t* Ks = Qs + 128 * FLD;
    half_t* Vs = Ks + 128 * FLD;
    float*  mf = (float*)(Vs + 128 * FLD);

    const int bh = blockIdx.y, qt = blockIdx.x;
    const int b = bh >> 4, hd = bh & 15;
    const int tid = threadIdx.x, lane = tid & 31, warp = tid >> 5;
    const int m0 = warp * 16;

    const half_t* Qg = qkvh + (((size_t)(0 * 128 + bh) * 512) + qt * 128) * 64;
    const half_t* Kg = qkvh + ((size_t)(1 * 128 + bh) * 512) * 64;
    const half_t* Vg = qkvh + ((size_t)(2 * 128 + bh) * 512) * 64;

    for (int i = tid; i < 1024; i += 256) {
        int r = i >> 3, cs = i & 7;
        *(uint4*)(Qs + r * FLD + cs * 8) = *(const uint4*)(Qg + r * 64 + cs * 8);
    }
    __syncthreads();

    uint32_t qf[4][4];
#pragma unroll
    for (int kb = 0; kb < 4; kb++)
        LDSM4(qf[kb], smem_u32(Qs + (m0 + (lane & 15)) * FLD + kb * 16 + (lane >> 4) * 8));

    float mrow[2] = {-1e30f, -1e30f};
    float lrow[2] = {0.f, 0.f};
    float oacc[8][4];
#pragma unroll
    for (int i = 0; i < 8; i++)
#pragma unroll
        for (int j = 0; j < 4; j++) oacc[i][j] = 0.f;

    for (int kt = 0; kt < 4; kt++) {
        __syncthreads();
        for (int i = tid; i < 1024; i += 256) {
            int r = i >> 3, cs = i & 7;
            *(uint4*)(Ks + r * FLD + cs * 8) = *(const uint4*)(Kg + (kt * 128 + r) * 64 + cs * 8);
            *(uint4*)(Vs + r * FLD + cs * 8) = *(const uint4*)(Vg + (kt * 128 + r) * 64 + cs * 8);
        }
        if (tid < 128) mf[tid] = (mask[b * SEQ + kt * 128 + tid] == 0) ? 1.f : 0.f;
        __syncthreads();

        float s[16][4];
#pragma unroll
        for (int f = 0; f < 16; f++)
#pragma unroll
            for (int i = 0; i < 4; i++) s[f][i] = 0.f;

#pragma unroll
        for (int kb = 0; kb < 4; kb++) {
#pragma unroll
            for (int nb2 = 0; nb2 < 8; nb2++) {
                uint32_t bf[4];
                int krow = nb2 * 16 + (lane & 7) + ((lane >> 4) & 1) * 8;
                int kcol = kb * 16 + ((lane >> 3) & 1) * 8;
                LDSM4(bf, smem_u32(Ks + krow * FLD + kcol));
                MMA16816(s[2 * nb2],     qf[kb], bf[0], bf[1]);
                MMA16816(s[2 * nb2 + 1], qf[kb], bf[2], bf[3]);
            }
        }

#pragma unroll
        for (int f = 0; f < 16; f++) {
            int c0 = f * 8 + (lane & 3) * 2;
            float f0 = mf[c0], f1 = mf[c0 + 1];
            s[f][0] = (f0 != 0.f) ? -1e9f : s[f][0] * 0.125f;
            s[f][1] = (f1 != 0.f) ? -1e9f : s[f][1] * 0.125f;
            s[f][2] = (f0 != 0.f) ? -1e9f : s[f][2] * 0.125f;
            s[f][3] = (f1 != 0.f) ? -1e9f : s[f][3] * 0.125f;
        }

        float mx0 = -1e30f, mx1 = -1e30f;
#pragma unroll
        for (int f = 0; f < 16; f++) {
            mx0 = fmaxf(mx0, fmaxf(s[f][0], s[f][1]));
            mx1 = fmaxf(mx1, fmaxf(s[f][2], s[f][3]));
        }
        mx0 = fmaxf(mx0, __shfl_xor_sync(0xffffffffu, mx0, 1));
        mx0 = fmaxf(mx0, __shfl_xor_sync(0xffffffffu, mx0, 2));
        mx1 = fmaxf(mx1, __shfl_xor_sync(0xffffffffu, mx1, 1));
        mx1 = fmaxf(mx1, __shfl_xor_sync(0xffffffffu, mx1, 2));

        float Mn0 = fmaxf(mrow[0], mx0), Mn1 = fmaxf(mrow[1], mx1);
        float sc0 = __expf(mrow[0] - Mn0), sc1 = __expf(mrow[1] - Mn1);
        mrow[0] = Mn0; mrow[1] = Mn1;

        float rs0 = 0.f, rs1 = 0.f;
#pragma unroll
        for (int f = 0; f < 16; f++) {
            s[f][0] = __expf(s[f][0] - Mn0); s[f][1] = __expf(s[f][1] - Mn0);
            s[f][2] = __expf(s[f][2] - Mn1); s[f][3] = __expf(s[f][3] - Mn1);
            rs0 += s[f][0] + s[f][1];
            rs1 += s[f][2] + s[f][3];
        }
        rs0 += __shfl_xor_sync(0xffffffffu, rs0, 1);
        rs0 += __shfl_xor_sync(0xffffffffu, rs0, 2);
        rs1 += __shfl_xor_sync(0xffffffffu, rs1, 1);
        rs1 += __shfl_xor_sync(0xffffffffu, rs1, 2);
        lrow[0] = lrow[0] * sc0 + rs0;
        lrow[1] = lrow[1] * sc1 + rs1;

#pragma unroll
        for (int nb = 0; nb < 8; nb++) {
            oacc[nb][0] *= sc0; oacc[nb][1] *= sc0;
            oacc[nb][2] *= sc1; oacc[nb][3] *= sc1;
        }

#pragma unroll
        for (int kb = 0; kb < 8; kb++) {
            uint32_t a[4];
            a[0] = packh2(s[2 * kb][0],     s[2 * kb][1]);
            a[1] = packh2(s[2 * kb][2],     s[2 * kb][3]);
            a[2] = packh2(s[2 * kb + 1][0], s[2 * kb + 1][1]);
            a[3] = packh2(s[2 * kb + 1][2], s[2 * kb + 1][3]);
#pragma unroll
            for (int nb2 = 0; nb2 < 4; nb2++) {
                uint32_t vf[4];
                int srow = kb * 16 + (lane & 15);
                int dcol = nb2 * 16 + (lane >> 4) * 8;
                LDSM4T(vf, smem_u32(Vs + srow * FLD + dcol));
                MMA16816(oacc[2 * nb2],     a, vf[0], vf[1]);
                MMA16816(oacc[2 * nb2 + 1], a, vf[2], vf[3]);
            }
        }
    }

    float inv0 = 1.f / lrow[0], inv1 = 1.f / lrow[1];
    int r0 = qt * 128 + m0 + (lane >> 2);
#pragma unroll
    for (int nb = 0; nb < 8; nb++) {
        int c = hd * 64 + nb * 8 + (lane & 3) * 2;
        *(__half2*)(out + (size_t)(b * SEQ + r0) * DMODEL + c) =
            __floats2half2_rn(oacc[nb][0] * inv0, oacc[nb][1] * inv0);
        *(__half2*)(out + (size_t)(b * SEQ + r0 + 8) * DMODEL + c) =
            __floats2half2_rn(oacc[nb][2] * inv1, oacc[nb][3] * inv1);
    }
}

// ---------------------------------------------------------------------------
// ALL weight conversions in one launch. Each z = one 1024x1024 transpose unit.
// dst[n*Kd + k] = src[k*Ns + n], fp32 -> fp16.
// ---------------------------------------------------------------------------
__global__ void wconv_all(const float* __restrict__ sw, const float* __restrict__ tw,
                          const float* __restrict__ fw, const float* __restrict__ aw,
                          const float* __restrict__ w1, const float* __restrict__ w2,
                          half_t* __restrict__ wt, int nlayers)
{
    __shared__ float t[32][33];
    int uid = blockIdx.z;
    const float* src;
    size_t dsto;
    int Ns, Kd;
    int A = 10 + 4 * nlayers;       // start of w1 units
    int Bu = A + 4 * nlayers;       // start of w2 units

    if (uid < 6) {
        src = (uid < 3) ? (sw + (size_t)uid * DDC) : (tw + (size_t)(uid - 3) * DDC);
        dsto = OFF_ST + (size_t)uid * M1; Ns = 1024; Kd = 1024;
    } else if (uid == 6) {
        src = sw + 3 * (size_t)DDC; dsto = OFF_SW3; Ns = 1024; Kd = 1024;
    } else if (uid == 7) {
        src = tw + 3 * (size_t)DDC; dsto = OFF_TW3; Ns = 1024; Kd = 1024;
    } else if (uid < 10) {
        int c = uid - 8;
        src = fw + (size_t)c * 1024 * 1024; dsto = OFF_FW + (size_t)c * 1024;
        Ns = 1024; Kd = 2048;
    } else if (uid < A) {
        int j = uid - 10;
        src = aw + (size_t)j * DDC; dsto = OFF_AW + (size_t)j * M1; Ns = 1024; Kd = 1024;
    } else if (uid < Bu) {
        int tix = uid - A; int i = tix >> 2, c = tix & 3;
        src = w1 + (size_t)i * 4 * M1 + (size_t)c * 1024;    // column chunk
        dsto = OFF_W1 + (size_t)i * 4 * M1 + (size_t)c * M1;
        Ns = 4096; Kd = 1024;
    } else {
        int tix = uid - Bu; int i = tix >> 2, c = tix & 3;
        src = w2 + (size_t)i * 4 * M1 + (size_t)c * M1;      // row chunk
        dsto = OFF_W2 + (size_t)i * 4 * M1 + (size_t)c * 1024;
        Ns = 1024; Kd = 4096;
    }

    int n0 = blockIdx.x * 32, k0 = blockIdx.y * 32;
    int tx = threadIdx.x & 31, ty = threadIdx.x >> 5;
    for (int r = ty; r < 32; r += 8) t[r][tx] = src[(size_t)(k0 + r) * Ns + n0 + tx];
    __syncthreads();
    for (int r = ty; r < 32; r += 8)
        wt[dsto + (size_t)(n0 + r) * Kd + k0 + tx] = __float2half_rn(t[tx][r]);
}

__global__ void aconv_kernel(const float* __restrict__ x, half_t* o, int n)
{
    int i = (blockIdx.x * blockDim.x + threadIdx.x) * 4;
    if (i >= n) return;
    float4 v = *(const float4*)(x + i);
    *(__half2*)(o + i)     = __floats2half2_rn(v.x, v.y);
    *(__half2*)(o + i + 2) = __floats2half2_rn(v.z, v.w);
}

// ---------------------------------------------------------------------------
// Merged spatial+temporal attention.
// blocks [0,2048): spatial (4 units of 64 threads each); [2048,3072): temporal.
// ---------------------------------------------------------------------------
#define SMEM_STA 49152

__global__ __launch_bounds__(256)
void st_attn(const float* __restrict__ q, const float* __restrict__ k,
             const float* __restrict__ v,
             const float* __restrict__ t1, const float* __restrict__ t2,
             const float* __restrict__ t3,
             const int* __restrict__ mask,
             half_t* __restrict__ osp, half_t* __restrict__ ote)
{
    extern __shared__ float S[];
    int tid = threadIdx.x;

    if (blockIdx.x < 2048) {
        // ---- spatial: clip of 8 tokens, per head. 4 units/block ----
        int unit = tid >> 6, tu = tid & 63;
        int u = blockIdx.x * 4 + unit;
        int h = u & 15;
        int c = (u >> 4) & 63;
        int b = u >> 10;
        int tb = b * SEQ + c * 8;
        float* Qs = S + unit * 1600;
        float* Ks = Qs + 512;
        float* Vs = Ks + 512;
        float* Ps = Vs + 512;

        for (int idx = tu; idx < 512; idx += 64) {
            int r = idx >> 6, d = idx & 63;
            int g = (tb + r) * DMODEL + h * DKH + d;
            Qs[r * 64 + d] = q[g]; Ks[r * 64 + d] = k[g]; Vs[r * 64 + d] = v[g];
        }
        __syncthreads();

        int i = tu >> 3, j = tu & 7;
        float s = 0.f;
#pragma unroll
        for (int d = 0; d < 64; d++) s += Qs[i * 64 + d] * Ks[j * 64 + d];
        s *= 0.125f;
        if (mask[b * SEQ + c * 8 + j] == 0) s = -1e9f;

        float m = s;
        m = fmaxf(m, __shfl_xor_sync(0xffffffffu, m, 1));
        m = fmaxf(m, __shfl_xor_sync(0xffffffffu, m, 2));
        m = fmaxf(m, __shfl_xor_sync(0xffffffffu, m, 4));
        float p = expf(s - m);
        float sum = p;
        sum += __shfl_xor_sync(0xffffffffu, sum, 1);
        sum += __shfl_xor_sync(0xffffffffu, sum, 2);
        sum += __shfl_xor_sync(0xffffffffu, sum, 4);
        Ps[i * 8 + j] = p / sum;
        __syncthreads();

        for (int idx = tu; idx < 512; idx += 64) {
            int r = idx >> 6, d = idx & 63;
            float o = 0.f;
#pragma unroll
            for (int jj = 0; jj < 8; jj++) o += Ps[r * 8 + jj] * Vs[jj * 64 + d];
            osp[(size_t)(tb + r) * DMODEL + h * DKH + d] = __float2half_rn(o);
        }
    } else {
        // ---- temporal: 64 clips at fixed within-clip position, per head ----
        int u = blockIdx.x - 2048;
        int h = u & 15;
        int jpos = (u >> 4) & 7;
        int b = u >> 7;
        int tx = tid & 15, ty = tid >> 4;
        float* QV  = S;
        float* Ks2 = S + 4096;
        float* Pst = S + 8192;

        for (int idx = tid; idx < 1024; idx += 256) {
            int r = idx >> 4;
            int d0 = (idx & 15) << 2;
            int g = (b * SEQ + r * 8 + jpos) * DMODEL + h * DKH + d0;
            float4 qv = *(const float4*)(t1 + g);
            QV[(d0 + 0) * 64 + r] = qv.x; QV[(d0 + 1) * 64 + r] = qv.y;
            QV[(d0 + 2) * 64 + r] = qv.z; QV[(d0 + 3) * 64 + r] = qv.w;
            float4 kv = *(const float4*)(t2 + g);
            Ks2[(d0 + 0) * 64 + r] = kv.x; Ks2[(d0 + 1) * 64 + r] = kv.y;
            Ks2[(d0 + 2) * 64 + r] = kv.z; Ks2[(d0 + 3) * 64 + r] = kv.w;
        }
        __syncthreads();

        float acc[4][4];
#pragma unroll
        for (int i = 0; i < 4; i++)
#pragma unroll
            for (int j = 0; j < 4; j++) acc[i][j] = 0.f;

        for (int d = 0; d < 64; d++) {
            float4 a = *(const float4*)&QV[d * 64 + ty * 4];
            float4 bb = *(const float4*)&Ks2[d * 64 + tx * 4];
            float av[4] = {a.x, a.y, a.z, a.w};
            float bvv[4] = {bb.x, bb.y, bb.z, bb.w};
#pragma unroll
            for (int i = 0; i < 4; i++)
#pragma unroll
                for (int j = 0; j < 4; j++) acc[i][j] += av[i] * bvv[j];
        }
#pragma unroll
        for (int jj = 0; jj < 4; jj++) {
            int cc = tx * 4 + jj;
            bool msk = (mask[b * SEQ + cc * 8 + jpos] == 0);
#pragma unroll
            for (int i = 0; i < 4; i++)
                Pst[cc * 64 + ty * 4 + i] = msk ? -1e9f : acc[i][jj] * 0.125f;
        }
        __syncthreads();

        if (tid < 64) {
            float m = -1e30f;
            for (int cc = 0; cc < 64; cc++) m = fmaxf(m, Pst[cc * 64 + tid]);
            float sum = 0.f;
            for (int cc = 0; cc < 64; cc++) {
                float p = expf(Pst[cc * 64 + tid] - m);
                Pst[cc * 64 + tid] = p; sum += p;
            }
            float inv = 1.f / sum;
            for (int cc = 0; cc < 64; cc++) Pst[cc * 64 + tid] *= inv;
        }
        __syncthreads();

        for (int idx = tid; idx < 1024; idx += 256) {
            int r = idx >> 4;
            int d0 = (idx & 15) << 2;
            float4 vv = *(const float4*)(t3 + (b * SEQ + r * 8 + jpos) * DMODEL + h * DKH + d0);
            *(float4*)&QV[r * 64 + d0] = vv;
        }
        __syncthreads();

        float oacc[4][4];
#pragma unroll
        for (int i = 0; i < 4; i++)
#pragma unroll
            for (int j = 0; j < 4; j++) oacc[i][j] = 0.f;

        for (int kk = 0; kk < 64; kk++) {
            float4 a = *(const float4*)&Pst[kk * 64 + ty * 4];
            float4 bb = *(const float4*)&QV[kk * 64 + tx * 4];
            float av[4] = {a.x, a.y, a.z, a.w};
            float bvv[4] = {bb.x, bb.y, bb.z, bb.w};
#pragma unroll
            for (int i = 0; i < 4; i++)
#pragma unroll
                for (int j = 0; j < 4; j++) oacc[i][j] += av[i] * bvv[j];
        }
#pragma unroll
        for (int i = 0; i < 4; i++)
#pragma unroll
            for (int jj = 0; jj < 4; jj++)
                ote[(size_t)(b * SEQ + (ty * 4 + i) * 8 + jpos) * DMODEL + h * DKH + tx * 4 + jj] =
                    __float2half_rn(oacc[i][jj]);
    }
}

// ---------------------------------------------------------------------------
// LayerNorm fp32 in -> fp16 out
// ---------------------------------------------------------------------------
__global__ void layernorm_kernel(const float* __restrict__ x,
                                 const float* __restrict__ gamma,
                                 const float* __restrict__ beta,
                                 half_t* __restrict__ oh)
{
    __shared__ float sh1[8], sh2[8];
    int row = blockIdx.x;
    int tid = threadIdx.x;
    const float* xr = x + (size_t)row * DMODEL;
    float4 v = *(const float4*)(xr + tid * 4);
    float s1 = v.x + v.y + v.z + v.w;
    float s2 = v.x * v.x + v.y * v.y + v.z * v.z + v.w * v.w;
#pragma unroll
    for (int o = 16; o; o >>= 1) {
        s1 += __shfl_xor_sync(0xffffffffu, s1, o);
        s2 += __shfl_xor_sync(0xffffffffu, s2, o);
    }
    if ((tid & 31) == 0) { sh1[tid >> 5] = s1; sh2[tid >> 5] = s2; }
    __syncthreads();
    if (tid == 0) {
        float a = 0.f, b2 = 0.f;
        for (int i = 0; i < 8; i++) { a += sh1[i]; b2 += sh2[i]; }
        sh1[0] = a * (1.f / DMODEL);
        sh2[0] = b2 * (1.f / DMODEL);
    }
    __syncthreads();
    float mean = sh1[0];
    float var = sh2[0] - mean * mean;
    float inv = rsqrtf(var + LN_EPS);
    float4 g = *(const float4*)(gamma + tid * 4);
    float4 bb = *(const float4*)(beta + tid * 4);
    size_t base = (size_t)row * DMODEL + tid * 4;
    *(__half2*)(oh + base) =
        __floats2half2_rn((v.x - mean) * inv * g.x + bb.x,
                          (v.y - mean) * inv * g.y + bb.y);
    *(__half2*)(oh + base + 2) =
        __floats2half2_rn((v.z - mean) * inv * g.z + bb.z,
                          (v.w - mean) * inv * g.w + bb.w);
}

// ---------------------------------------------------------------------------
// Host orchestration
// ---------------------------------------------------------------------------
extern "C" void kernel_launch(void* const* d_in, const int* in_sizes, int n_in,
                              void* d_out, int out_size)
{
    (void)n_in; (void)out_size;
    const float* x    = (const float*)d_in[0];
    const int*   mask = (const int*)  d_in[1];
    const float* sw   = (const float*)d_in[2];
    const float* sb   = (const float*)d_in[3];
    const float* tw   = (const float*)d_in[4];
    const float* tbia = (const float*)d_in[5];
    const float* fw   = (const float*)d_in[6];
    const float* fb   = (const float*)d_in[7];
    const float* aw   = (const float*)d_in[8];
    const float* ab   = (const float*)d_in[9];
    const float* w1   = (const float*)d_in[10];
    const float* b1   = (const float*)d_in[11];
    const float* w2   = (const float*)d_in[12];
    const float* b2   = (const float*)d_in[13];
    const float* lns  = (const float*)d_in[14];
    const float* lnb  = (const float*)d_in[15];
    float* out = (float*)d_out;

    cudaFuncSetAttribute(gemm_hmma<0>, cudaFuncAttributeMaxDynamicSharedMemorySize, SMEM_GEMM);
    cudaFuncSetAttribute(gemm_hmma<1>, cudaFuncAttributeMaxDynamicSharedMemorySize, SMEM_GEMM);
    cudaFuncSetAttribute(gemm_hmma<2>, cudaFuncAttributeMaxDynamicSharedMemorySize, SMEM_GEMM);
    cudaFuncSetAttribute(gemm_hmma<3>, cudaFuncAttributeMaxDynamicSharedMemorySize, SMEM_GEMM);
    cudaFuncSetAttribute(flash_attn,   cudaFuncAttributeMaxDynamicSharedMemorySize, SMEM_FLASH);
    cudaFuncSetAttribute(st_attn,      cudaFuncAttributeMaxDynamicSharedMemorySize, SMEM_STA);

    half_t *wt, *xh, *hh, *ah, *fh, *qkvh;
    float *q, *k, *v, *t1, *t2, *t3, *xb;
    cudaGetSymbolAddress((void**)&wt,   g_wt);
    cudaGetSymbolAddress((void**)&xh,   g_xh);
    cudaGetSymbolAddress((void**)&hh,   g_hh);
    cudaGetSymbolAddress((void**)&ah,   g_ah);
    cudaGetSymbolAddress((void**)&fh,   g_fh);
    cudaGetSymbolAddress((void**)&qkvh, g_qkvh);
    cudaGetSymbolAddress((void**)&q,    g_q);
    cudaGetSymbolAddress((void**)&k,    g_k);
    cudaGetSymbolAddress((void**)&v,    g_v);
    cudaGetSymbolAddress((void**)&t1,   g_t1);
    cudaGetSymbolAddress((void**)&t2,   g_t2);
    cudaGetSymbolAddress((void**)&t3,   g_t3);
    cudaGetSymbolAddress((void**)&xb,   g_xb);

    const size_t DD = (size_t)DMODEL * DMODEL;
    int nlayers = in_sizes[8] / (int)(4 * DD);

    // ---- ALL weight conversions in one launch ----
    wconv_all<<<dim3(32, 32, 10 + 12 * nlayers), 256>>>(sw, tw, fw, aw, w1, w2, wt, nlayers);

    aconv_kernel<<<(MTOK * DMODEL / 4 + 255) / 256, 256>>>(x, xh, MTOK * DMODEL);

    // ---- spatial+temporal QKV: one N=6144 GEMM into 6 fp32 buffers ----
    gemm_hmma<2><<<dim3(48, 32), 256, SMEM_GEMM>>>(
        xh, wt + OFF_ST, nullptr, nullptr, sb, tbia, nullptr, nullptr, nullptr,
        MTOK, 6144, DMODEL, 0, 0, q, k, v, t1, t2, t3);

    // ---- merged spatial + temporal attention ----
    st_attn<<<3072, 256, SMEM_STA>>>(q, k, v, t1, t2, t3, mask, ah, hh);

    // ---- batched out-projections into concat buffer ----
    gemm_hmma<3><<<dim3(8, 32, 2), 256, SMEM_GEMM>>>(
        ah, wt + OFF_SW3, hh, wt + OFF_TW3, sb + 3 * DMODEL, tbia + 3 * DMODEL,
        nullptr, nullptr, fh, MTOK, DMODEL, DMODEL, 0, 2048,
        nullptr, nullptr, nullptr, nullptr, nullptr, nullptr);

    // ---- fusion: xb = concat(spa,tem) @ Fw^T + fb ----
    gemm_hmma<0><<<dim3(8, 32), 256, SMEM_GEMM>>>(
        fh, wt + OFF_FW, nullptr, nullptr, fb, nullptr, nullptr, xb, nullptr,
        MTOK, DMODEL, 2 * DMODEL, 0, DMODEL, nullptr, nullptr, nullptr, nullptr, nullptr, nullptr);

    // ---- encoder layers ----
    for (int i = 0; i < nlayers; i++) {
        const float* abi = ab + (size_t)i * 4 * DMODEL;
        const half_t* awi = wt + OFF_AW + (size_t)i * 4 * M1;

        layernorm_kernel<<<MTOK, 256>>>(xb, lns + (i * 2 + 0) * DMODEL,
                                        lnb + (i * 2 + 0) * DMODEL, hh);
        gemm_hmma<1><<<dim3(24, 32), 256, SMEM_GEMM>>>(
            hh, awi, nullptr, nullptr, abi, nullptr, nullptr, nullptr, qkvh,
            MTOK, 3 * DMODEL, DMODEL, 0, 0, nullptr, nullptr, nullptr, nullptr, nullptr, nullptr);

        flash_attn<<<dim3(4, 128), 256, SMEM_FLASH>>>(qkvh, mask, ah);

        gemm_hmma<0><<<dim3(8, 32), 256, SMEM_GEMM>>>(
            ah, awi + 3 * M1, nullptr, nullptr, abi + 3 * DMODEL, nullptr, xb, xb, nullptr,
            MTOK, DMODEL, DMODEL, 0, DMODEL, nullptr, nullptr, nullptr, nullptr, nullptr, nullptr);

        layernorm_kernel<<<MTOK, 256>>>(xb, lns + (i * 2 + 1) * DMODEL,
                                        lnb + (i * 2 + 1) * DMODEL, hh);
        gemm_hmma<0><<<dim3(32, 32), 256, SMEM_GEMM>>>(
            hh, wt + OFF_W1 + (size_t)i * 4 * M1, nullptr, nullptr, b1 + i * DFF, nullptr,
            nullptr, nullptr, fh, MTOK, DFF, DMODEL, 1, DFF,
            nullptr, nullptr, nullptr, nullptr, nullptr, nullptr);
        float* dst = (i == nlayers - 1) ? out : xb;
        gemm_hmma<0><<<dim3(8, 32), 256, SMEM_GEMM>>>(
            fh, wt + OFF_W2 + (size_t)i * 4 * M1, nullptr, nullptr, b2 + i * DMODEL, nullptr,
            xb, dst, nullptr, MTOK, DMODEL, DFF, 0, DMODEL,
            nullptr, nullptr, nullptr, nullptr, nullptr, nullptr);
    }
}

// round 6
// speedup vs baseline: 5.7350x; 1.0290x over previous
#include <cuda_runtime.h>
#include <cuda_fp16.h>
#include <cstdint>
#include <math.h>

#define DMODEL 1024
#define BATCH  8
#define SEQ    512
#define NHEAD  16
#define DKH    64
#define MTOK   4096
#define DFF    4096
#define NCLIP  64
#define LN_EPS 1e-5f

typedef __half half_t;

// ---------------------------------------------------------------------------
// PTX helpers (arch-agnostic: mma.sync / ldmatrix / cp.async only)
// ---------------------------------------------------------------------------
__device__ __forceinline__ uint32_t smem_u32(const void* p) {
    uint32_t a;
    asm("{ .reg .u64 t; cvta.to.shared.u64 t, %1; cvt.u32.u64 %0, t; }" : "=r"(a) : "l"(p));
    return a;
}

#define LDSM4(r, a) \
    asm volatile("ldmatrix.sync.aligned.m8n8.x4.shared.b16 {%0,%1,%2,%3}, [%4];" \
        : "=r"((r)[0]), "=r"((r)[1]), "=r"((r)[2]), "=r"((r)[3]) : "r"(a))

#define LDSM4T(r, a) \
    asm volatile("ldmatrix.sync.aligned.m8n8.x4.trans.shared.b16 {%0,%1,%2,%3}, [%4];" \
        : "=r"((r)[0]), "=r"((r)[1]), "=r"((r)[2]), "=r"((r)[3]) : "r"(a))

#define MMA16816(c, a, b0, b1) \
    asm volatile("mma.sync.aligned.m16n8k16.row.col.f32.f16.f16.f32 " \
        "{%0,%1,%2,%3}, {%4,%5,%6,%7}, {%8,%9}, {%0,%1,%2,%3};" \
        : "+f"((c)[0]), "+f"((c)[1]), "+f"((c)[2]), "+f"((c)[3]) \
        : "r"((a)[0]), "r"((a)[1]), "r"((a)[2]), "r"((a)[3]), "r"(b0), "r"(b1))

#define CPASYNC16(d, s) asm volatile("cp.async.cg.shared.global [%0], [%1], 16;" :: "r"(d), "l"(s))
#define CPCOMMIT()      asm volatile("cp.async.commit_group;" ::: "memory")
#define CPWAIT(n)       asm volatile("cp.async.wait_group %0;" :: "n"(n) : "memory")

__device__ __forceinline__ uint32_t packh2(float x, float y) {
    __half2 h = __floats2half2_rn(x, y);
    return *(uint32_t*)&h;
}

// ---------------------------------------------------------------------------
// Device scratch
// ---------------------------------------------------------------------------
#define WT_TOT (34u * 1024u * 1024u)
__device__ half_t g_wt[WT_TOT];
__device__ half_t g_xh[MTOK * DMODEL];
__device__ half_t g_hh[MTOK * DMODEL];
__device__ half_t g_ah[MTOK * DMODEL];
__device__ half_t g_fh[MTOK * DFF];
__device__ half_t g_qkvh[3 * 128 * SEQ * DKH];
__device__ half_t g_q[MTOK * DMODEL];
__device__ half_t g_k[MTOK * DMODEL];
__device__ half_t g_v[MTOK * DMODEL];
__device__ half_t g_t1[MTOK * DMODEL];
__device__ half_t g_t2[MTOK * DMODEL];
__device__ half_t g_t3[MTOK * DMODEL];
__device__ float  g_xb[MTOK * DMODEL];

// weight offsets (units of 1M elements) inside g_wt
#define M1 (1024u * 1024u)
#define DDC (1024u * 1024u)
#define OFF_ST  0u           // 6*M1 : sw0,sw1,sw2,tw0,tw1,tw2
#define OFF_SW3 (6u * M1)
#define OFF_TW3 (7u * M1)
#define OFF_FW  (8u * M1)    // 2*M1 : fusion [1024][2048]
#define OFF_AW  (10u * M1)   // per layer 4*M1
#define OFF_W1  (18u * M1)   // per layer 4*M1 [4096][1024]
#define OFF_W2  (26u * M1)   // per layer 4*M1 [1024][4096]

// ---------------------------------------------------------------------------
// fp16 HMMA GEMM. MODE 0: standard; MODE 1: QKV head-major scatter;
// MODE 2: six fp16 buffers by col/1024; MODE 3: z-batched out-proj.
// ---------------------------------------------------------------------------
#define STAGES 3
#define STAGE_BYTES 16384
#define SMEM_GEMM (STAGES * STAGE_BYTES)

template<int MODE>
__global__ __launch_bounds__(256)
void gemm_hmma(const half_t* __restrict__ A, const half_t* __restrict__ B,
               const half_t* __restrict__ A2, const half_t* __restrict__ B2,
               const float* __restrict__ bias, const float* __restrict__ bias2,
               const float* __restrict__ R, float* Cf, half_t* Ch,
               int M, int N, int K, int relu, int ldC,
               half_t* q0, half_t* q1, half_t* q2, half_t* q3, half_t* q4, half_t* q5)
{
    extern __shared__ char smem[];
    uint32_t sb = smem_u32(smem);
    const int tid = threadIdx.x;
    const int lane = tid & 31, warp = tid >> 5;
    const int row0 = blockIdx.y * 128, col0 = blockIdx.x * 128;
    const int wm = (warp >> 2) * 64;
    const int wn = (warp & 3) * 32;

    if (MODE == 3 && blockIdx.z == 1) { A = A2; B = B2; bias = bias2; }

    int segr[2], segc[2];
#pragma unroll
    for (int i = 0; i < 2; i++) { int s = tid + i * 256; segr[i] = s >> 2; segc[i] = s & 3; }

    int rA[4], swA[4];
#pragma unroll
    for (int mt = 0; mt < 4; mt++) {
        int r = wm + mt * 16 + (lane & 15);
        rA[mt] = r; swA[mt] = (r >> 1) & 3;
    }
    int rB[2], swB[2];
#pragma unroll
    for (int n2 = 0; n2 < 2; n2++) {
        int r = wn + n2 * 16 + (lane & 7) + ((lane >> 4) << 3);
        rB[n2] = r; swB[n2] = (r >> 1) & 3;
    }
    const int csA = lane >> 4;
    const int csB = (lane >> 3) & 1;

    float acc[4][4][4];
#pragma unroll
    for (int mt = 0; mt < 4; mt++)
#pragma unroll
        for (int nt = 0; nt < 4; nt++)
#pragma unroll
            for (int i = 0; i < 4; i++) acc[mt][nt][i] = 0.f;

    const int NT = K / 32;

#define GISSUE(kt, st) do { \
    uint32_t sA_ = sb + (st) * STAGE_BYTES; \
    uint32_t sB_ = sA_ + 8192; \
    _Pragma("unroll") for (int i = 0; i < 2; i++) { \
        int r_ = segr[i], c_ = segc[i]; \
        uint32_t sw_ = (uint32_t)((c_ ^ ((r_ >> 1) & 3)) << 4); \
        CPASYNC16(sA_ + r_ * 64 + sw_, A + (size_t)(row0 + r_) * K + (size_t)(kt) * 32 + c_ * 8); \
        CPASYNC16(sB_ + r_ * 64 + sw_, B + (size_t)(col0 + r_) * K + (size_t)(kt) * 32 + c_ * 8); \
    } \
    CPCOMMIT(); } while (0)

    GISSUE(0, 0);
    GISSUE(1, 1);

    for (int kt = 0; kt < NT; kt++) {
        if (kt == NT - 1) { CPWAIT(0); } else { CPWAIT(1); }
        __syncthreads();
        if (kt + 2 < NT) GISSUE(kt + 2, (kt + 2) % 3);

        uint32_t sA = sb + (kt % 3) * STAGE_BYTES;
        uint32_t sB = sA + 8192;
#pragma unroll
        for (int k16 = 0; k16 < 2; k16++) {
            uint32_t ra[4][4], rb[2][4];
#pragma unroll
            for (int mt = 0; mt < 4; mt++)
                LDSM4(ra[mt], sA + rA[mt] * 64 + ((((k16 << 1) + csA) ^ swA[mt]) << 4));
#pragma unroll
            for (int n2 = 0; n2 < 2; n2++)
                LDSM4(rb[n2], sB + rB[n2] * 64 + ((((k16 << 1) + csB) ^ swB[n2]) << 4));
#pragma unroll
            for (int mt = 0; mt < 4; mt++)
#pragma unroll
                for (int nt = 0; nt < 4; nt++)
                    MMA16816(acc[mt][nt], ra[mt],
                             rb[nt >> 1][(nt & 1) * 2], rb[nt >> 1][(nt & 1) * 2 + 1]);
        }
    }

    // Epilogue
    half_t* obuf = nullptr;
    if (MODE == 2) {
        int bsel = col0 >> 10;
        obuf = (bsel == 0) ? q0 : (bsel == 1) ? q1 : (bsel == 2) ? q2 :
               (bsel == 3) ? q3 : (bsel == 4) ? q4 : q5;
    }
    const int cbase = (MODE == 3) ? (int)blockIdx.z * 1024 : 0;
#pragma unroll
    for (int mt = 0; mt < 4; mt++) {
        int rg = row0 + wm + mt * 16 + (lane >> 2);
#pragma unroll
        for (int nt = 0; nt < 4; nt++) {
            int c = col0 + wn + nt * 8 + (lane & 3) * 2;
            float* a = acc[mt][nt];
#pragma unroll
            for (int h = 0; h < 2; h++) {
                int row = rg + h * 8;
                float v0 = a[h * 2], v1 = a[h * 2 + 1];
                if (MODE == 0) {
                    if (bias) { v0 += bias[c]; v1 += bias[c + 1]; }
                    if (R) {
                        float2 rr = *(const float2*)(R + (size_t)row * N + c);
                        v0 += rr.x; v1 += rr.y;
                    }
                    if (relu) { v0 = fmaxf(v0, 0.f); v1 = fmaxf(v1, 0.f); }
                    if (Cf) {
                        float2 o; o.x = v0; o.y = v1;
                        *(float2*)(Cf + (size_t)row * ldC + c) = o;
                    }
                    if (Ch)
                        *(__half2*)(Ch + (size_t)row * ldC + c) = __floats2half2_rn(v0, v1);
                } else if (MODE == 1) {
                    v0 += bias[c]; v1 += bias[c + 1];
                    int qkv = c >> 10, hh_ = (c >> 6) & 15, d = c & 63;
                    int b = row >> 9, srow = row & 511;
                    size_t dst = (((size_t)(qkv * 128 + b * 16 + hh_) * 512) + srow) * 64 + d;
                    *(__half2*)(Ch + dst) = __floats2half2_rn(v0, v1);
                } else if (MODE == 2) {
                    float b0v = (c < 3072) ? bias[c] : bias2[c - 3072];
                    float b1v = (c + 1 < 3072) ? bias[c + 1] : bias2[c + 1 - 3072];
                    *(__half2*)(obuf + (size_t)row * 1024 + (c & 1023)) =
                        __floats2half2_rn(v0 + b0v, v1 + b1v);
                } else { // MODE 3
                    v0 += bias[c]; v1 += bias[c + 1];
                    *(__half2*)(Ch + (size_t)row * ldC + cbase + c) = __floats2half2_rn(v0, v1);
                }
            }
        }
    }
}

// ---------------------------------------------------------------------------
// Flash attention (encoder): per (b,h) 512x512, fp16 mma, online softmax.
// ---------------------------------------------------------------------------
#define FLD 72
#define SMEM_FLASH (3 * 128 * FLD * 2 + 512)

__global__ __launch_bounds__(256)
void flash_attn(const half_t* __restrict__ qkvh, const int* __restrict__ mask,
                half_t* __restrict__ out)
{
    extern __shared__ char sm[];
    half_t* Qs = (half_t*)sm;
    half_t* Ks = Qs + 128 * FLD;
    half_t* Vs = Ks + 128 * FLD;
    float*  mf = (float*)(Vs + 128 * FLD);

    const int bh = blockIdx.y, qt = blockIdx.x;
    const int b = bh >> 4, hd = bh & 15;
    const int tid = threadIdx.x, lane = tid & 31, warp = tid >> 5;
    const int m0 = warp * 16;

    const half_t* Qg = qkvh + (((size_t)(0 * 128 + bh) * 512) + qt * 128) * 64;
    const half_t* Kg = qkvh + ((size_t)(1 * 128 + bh) * 512) * 64;
    const half_t* Vg = qkvh + ((size_t)(2 * 128 + bh) * 512) * 64;

    for (int i = tid; i < 1024; i += 256) {
        int r = i >> 3, cs = i & 7;
        *(uint4*)(Qs + r * FLD + cs * 8) = *(const uint4*)(Qg + r * 64 + cs * 8);
    }
    __syncthreads();

    uint32_t qf[4][4];
#pragma unroll
    for (int kb = 0; kb < 4; kb++)
        LDSM4(qf[kb], smem_u32(Qs + (m0 + (lane & 15)) * FLD + kb * 16 + (lane >> 4) * 8));

    float mrow[2] = {-1e30f, -1e30f};
    float lrow[2] = {0.f, 0.f};
    float oacc[8][4];
#pragma unroll
    for (int i = 0; i < 8; i++)
#pragma unroll
        for (int j = 0; j < 4; j++) oacc[i][j] = 0.f;

    for (int kt = 0; kt < 4; kt++) {
        __syncthreads();
        for (int i = tid; i < 1024; i += 256) {
            int r = i >> 3, cs = i & 7;
            *(uint4*)(Ks + r * FLD + cs * 8) = *(const uint4*)(Kg + (kt * 128 + r) * 64 + cs * 8);
            *(uint4*)(Vs + r * FLD + cs * 8) = *(const uint4*)(Vg + (kt * 128 + r) * 64 + cs * 8);
        }
        if (tid < 128) mf[tid] = (mask[b * SEQ + kt * 128 + tid] == 0) ? 1.f : 0.f;
        __syncthreads();

        float s[16][4];
#pragma unroll
        for (int f = 0; f < 16; f++)
#pragma unroll
            for (int i = 0; i < 4; i++) s[f][i] = 0.f;

#pragma unroll
        for (int kb = 0; kb < 4; kb++) {
#pragma unroll
            for (int nb2 = 0; nb2 < 8; nb2++) {
                uint32_t bf[4];
                int krow = nb2 * 16 + (lane & 7) + ((lane >> 4) & 1) * 8;
                int kcol = kb * 16 + ((lane >> 3) & 1) * 8;
                LDSM4(bf, smem_u32(Ks + krow * FLD + kcol));
                MMA16816(s[2 * nb2],     qf[kb], bf[0], bf[1]);
                MMA16816(s[2 * nb2 + 1], qf[kb], bf[2], bf[3]);
            }
        }

#pragma unroll
        for (int f = 0; f < 16; f++) {
            int c0 = f * 8 + (lane & 3) * 2;
            float f0 = mf[c0], f1 = mf[c0 + 1];
            s[f][0] = (f0 != 0.f) ? -1e9f : s[f][0] * 0.125f;
            s[f][1] = (f1 != 0.f) ? -1e9f : s[f][1] * 0.125f;
            s[f][2] = (f0 != 0.f) ? -1e9f : s[f][2] * 0.125f;
            s[f][3] = (f1 != 0.f) ? -1e9f : s[f][3] * 0.125f;
        }

        float mx0 = -1e30f, mx1 = -1e30f;
#pragma unroll
        for (int f = 0; f < 16; f++) {
            mx0 = fmaxf(mx0, fmaxf(s[f][0], s[f][1]));
            mx1 = fmaxf(mx1, fmaxf(s[f][2], s[f][3]));
        }
        mx0 = fmaxf(mx0, __shfl_xor_sync(0xffffffffu, mx0, 1));
        mx0 = fmaxf(mx0, __shfl_xor_sync(0xffffffffu, mx0, 2));
        mx1 = fmaxf(mx1, __shfl_xor_sync(0xffffffffu, mx1, 1));
        mx1 = fmaxf(mx1, __shfl_xor_sync(0xffffffffu, mx1, 2));

        float Mn0 = fmaxf(mrow[0], mx0), Mn1 = fmaxf(mrow[1], mx1);
        float sc0 = __expf(mrow[0] - Mn0), sc1 = __expf(mrow[1] - Mn1);
        mrow[0] = Mn0; mrow[1] = Mn1;

        float rs0 = 0.f, rs1 = 0.f;
#pragma unroll
        for (int f = 0; f < 16; f++) {
            s[f][0] = __expf(s[f][0] - Mn0); s[f][1] = __expf(s[f][1] - Mn0);
            s[f][2] = __expf(s[f][2] - Mn1); s[f][3] = __expf(s[f][3] - Mn1);
            rs0 += s[f][0] + s[f][1];
            rs1 += s[f][2] + s[f][3];
        }
        rs0 += __shfl_xor_sync(0xffffffffu, rs0, 1);
        rs0 += __shfl_xor_sync(0xffffffffu, rs0, 2);
        rs1 += __shfl_xor_sync(0xffffffffu, rs1, 1);
        rs1 += __shfl_xor_sync(0xffffffffu, rs1, 2);
        lrow[0] = lrow[0] * sc0 + rs0;
        lrow[1] = lrow[1] * sc1 + rs1;

#pragma unroll
        for (int nb = 0; nb < 8; nb++) {
            oacc[nb][0] *= sc0; oacc[nb][1] *= sc0;
            oacc[nb][2] *= sc1; oacc[nb][3] *= sc1;
        }

#pragma unroll
        for (int kb = 0; kb < 8; kb++) {
            uint32_t a[4];
            a[0] = packh2(s[2 * kb][0],     s[2 * kb][1]);
            a[1] = packh2(s[2 * kb][2],     s[2 * kb][3]);
            a[2] = packh2(s[2 * kb + 1][0], s[2 * kb + 1][1]);
            a[3] = packh2(s[2 * kb + 1][2], s[2 * kb + 1][3]);
#pragma unroll
            for (int nb2 = 0; nb2 < 4; nb2++) {
                uint32_t vf[4];
                int srow = kb * 16 + (lane & 15);
                int dcol = nb2 * 16 + (lane >> 4) * 8;
                LDSM4T(vf, smem_u32(Vs + srow * FLD + dcol));
                MMA16816(oacc[2 * nb2],     a, vf[0], vf[1]);
                MMA16816(oacc[2 * nb2 + 1], a, vf[2], vf[3]);
            }
        }
    }

    float inv0 = 1.f / lrow[0], inv1 = 1.f / lrow[1];
    int r0 = qt * 128 + m0 + (lane >> 2);
#pragma unroll
    for (int nb = 0; nb < 8; nb++) {
        int c = hd * 64 + nb * 8 + (lane & 3) * 2;
        *(__half2*)(out + (size_t)(b * SEQ + r0) * DMODEL + c) =
            __floats2half2_rn(oacc[nb][0] * inv0, oacc[nb][1] * inv0);
        *(__half2*)(out + (size_t)(b * SEQ + r0 + 8) * DMODEL + c) =
            __floats2half2_rn(oacc[nb][2] * inv1, oacc[nb][3] * inv1);
    }
}

// ---------------------------------------------------------------------------
// ALL weight conversions in one launch.
// ---------------------------------------------------------------------------
__global__ void wconv_all(const float* __restrict__ sw, const float* __restrict__ tw,
                          const float* __restrict__ fw, const float* __restrict__ aw,
                          const float* __restrict__ w1, const float* __restrict__ w2,
                          half_t* __restrict__ wt, int nlayers)
{
    __shared__ float t[32][33];
    int uid = blockIdx.z;
    const float* src;
    size_t dsto;
    int Ns, Kd;
    int A = 10 + 4 * nlayers;
    int Bu = A + 4 * nlayers;

    if (uid < 6) {
        src = (uid < 3) ? (sw + (size_t)uid * DDC) : (tw + (size_t)(uid - 3) * DDC);
        dsto = OFF_ST + (size_t)uid * M1; Ns = 1024; Kd = 1024;
    } else if (uid == 6) {
        src = sw + 3 * (size_t)DDC; dsto = OFF_SW3; Ns = 1024; Kd = 1024;
    } else if (uid == 7) {
        src = tw + 3 * (size_t)DDC; dsto = OFF_TW3; Ns = 1024; Kd = 1024;
    } else if (uid < 10) {
        int c = uid - 8;
        src = fw + (size_t)c * 1024 * 1024; dsto = OFF_FW + (size_t)c * 1024;
        Ns = 1024; Kd = 2048;
    } else if (uid < A) {
        int j = uid - 10;
        src = aw + (size_t)j * DDC; dsto = OFF_AW + (size_t)j * M1; Ns = 1024; Kd = 1024;
    } else if (uid < Bu) {
        int tix = uid - A; int i = tix >> 2, c = tix & 3;
        src = w1 + (size_t)i * 4 * M1 + (size_t)c * 1024;
        dsto = OFF_W1 + (size_t)i * 4 * M1 + (size_t)c * M1;
        Ns = 4096; Kd = 1024;
    } else {
        int tix = uid - Bu; int i = tix >> 2, c = tix & 3;
        src = w2 + (size_t)i * 4 * M1 + (size_t)c * M1;
        dsto = OFF_W2 + (size_t)i * 4 * M1 + (size_t)c * 1024;
        Ns = 1024; Kd = 4096;
    }

    int n0 = blockIdx.x * 32, k0 = blockIdx.y * 32;
    int tx = threadIdx.x & 31, ty = threadIdx.x >> 5;
    for (int r = ty; r < 32; r += 8) t[r][tx] = src[(size_t)(k0 + r) * Ns + n0 + tx];
    __syncthreads();
    for (int r = ty; r < 32; r += 8)
        wt[dsto + (size_t)(n0 + r) * Kd + k0 + tx] = __float2half_rn(t[tx][r]);
}

__global__ void aconv_kernel(const float* __restrict__ x, half_t* o, int n)
{
    int i = (blockIdx.x * blockDim.x + threadIdx.x) * 4;
    if (i >= n) return;
    float4 v = *(const float4*)(x + i);
    *(__half2*)(o + i)     = __floats2half2_rn(v.x, v.y);
    *(__half2*)(o + i + 2) = __floats2half2_rn(v.z, v.w);
}

// ---------------------------------------------------------------------------
// Merged spatial+temporal attention, fp16 inputs, conflict-free smem (stride 65).
// blocks [0,2048): spatial (4 units/block); [2048,3072): temporal.
// ---------------------------------------------------------------------------
#define SPAD 65
#define SMEM_STA (3 * 64 * SPAD * 4 + 256)

__global__ __launch_bounds__(256)
void st_attn(const half_t* __restrict__ q, const half_t* __restrict__ k,
             const half_t* __restrict__ v,
             const half_t* __restrict__ t1, const half_t* __restrict__ t2,
             const half_t* __restrict__ t3,
             const int* __restrict__ mask,
             half_t* __restrict__ osp, half_t* __restrict__ ote)
{
    extern __shared__ float S[];
    int tid = threadIdx.x;

    if (blockIdx.x < 2048) {
        // ---- spatial: clip of 8 tokens, per head. 4 units of 64 threads ----
        int unit = tid >> 6, tu = tid & 63;
        int u = blockIdx.x * 4 + unit;
        int h = u & 15;
        int c = (u >> 4) & 63;
        int b = u >> 10;
        int tb = b * SEQ + c * 8;
        float* Qs = S + unit * 1632;        // 8*65 = 520 each
        float* Ks = Qs + 520;
        float* Vs = Ks + 520;
        float* Ps = Vs + 520;               // 64

        for (int idx = tu; idx < 512; idx += 64) {
            int r = idx >> 6, d = idx & 63;
            size_t g = (size_t)(tb + r) * DMODEL + h * DKH + d;
            Qs[r * SPAD + d] = __half2float(q[g]);
            Ks[r * SPAD + d] = __half2float(k[g]);
            Vs[r * SPAD + d] = __half2float(v[g]);
        }
        __syncthreads();

        int i = tu >> 3, j = tu & 7;
        float s = 0.f;
#pragma unroll
        for (int d = 0; d < 64; d++) s += Qs[i * SPAD + d] * Ks[j * SPAD + d];
        s *= 0.125f;
        if (mask[b * SEQ + c * 8 + j] == 0) s = -1e9f;

        float m = s;
        m = fmaxf(m, __shfl_xor_sync(0xffffffffu, m, 1));
        m = fmaxf(m, __shfl_xor_sync(0xffffffffu, m, 2));
        m = fmaxf(m, __shfl_xor_sync(0xffffffffu, m, 4));
        float p = expf(s - m);
        float sum = p;
        sum += __shfl_xor_sync(0xffffffffu, sum, 1);
        sum += __shfl_xor_sync(0xffffffffu, sum, 2);
        sum += __shfl_xor_sync(0xffffffffu, sum, 4);
        Ps[i * 8 + j] = p / sum;
        __syncthreads();

        for (int idx = tu; idx < 512; idx += 64) {
            int r = idx >> 6, d = idx & 63;
            float o = 0.f;
#pragma unroll
            for (int jj = 0; jj < 8; jj++) o += Ps[r * 8 + jj] * Vs[jj * SPAD + d];
            osp[(size_t)(tb + r) * DMODEL + h * DKH + d] = __float2half_rn(o);
        }
    } else {
        // ---- temporal: 64 clips at fixed within-clip position, per head ----
        int u = blockIdx.x - 2048;
        int h = u & 15;
        int jpos = (u >> 4) & 7;
        int b = u >> 7;
        int tx = tid & 15, ty = tid >> 4;
        float* QV  = S;                     // [d][c] stride 65, later V as [c][d]
        float* Ks2 = S + 64 * SPAD;
        float* Pst = S + 2 * 64 * SPAD;     // [key][query] stride 65

        for (int idx = tid; idx < 1024; idx += 256) {
            int r = idx >> 4;
            int d0 = (idx & 15) << 2;
            size_t g = (size_t)(b * SEQ + r * 8 + jpos) * DMODEL + h * DKH + d0;
            __half2 a0 = *(const __half2*)(t1 + g);
            __half2 a1 = *(const __half2*)(t1 + g + 2);
            QV[(d0 + 0) * SPAD + r] = __low2float(a0);
            QV[(d0 + 1) * SPAD + r] = __high2float(a0);
            QV[(d0 + 2) * SPAD + r] = __low2float(a1);
            QV[(d0 + 3) * SPAD + r] = __high2float(a1);
            __half2 k0h = *(const __half2*)(t2 + g);
            __half2 k1h = *(const __half2*)(t2 + g + 2);
            Ks2[(d0 + 0) * SPAD + r] = __low2float(k0h);
            Ks2[(d0 + 1) * SPAD + r] = __high2float(k0h);
            Ks2[(d0 + 2) * SPAD + r] = __low2float(k1h);
            Ks2[(d0 + 3) * SPAD + r] = __high2float(k1h);
        }
        __syncthreads();

        float acc[4][4];
#pragma unroll
        for (int i = 0; i < 4; i++)
#pragma unroll
            for (int j = 0; j < 4; j++) acc[i][j] = 0.f;

        for (int d = 0; d < 64; d++) {
            float av[4], bv[4];
#pragma unroll
            for (int i = 0; i < 4; i++) av[i] = QV[d * SPAD + ty * 4 + i];
#pragma unroll
            for (int j = 0; j < 4; j++) bv[j] = Ks2[d * SPAD + tx * 4 + j];
#pragma unroll
            for (int i = 0; i < 4; i++)
#pragma unroll
                for (int j = 0; j < 4; j++) acc[i][j] += av[i] * bv[j];
        }
#pragma unroll
        for (int jj = 0; jj < 4; jj++) {
            int cc = tx * 4 + jj;
            bool msk = (mask[b * SEQ + cc * 8 + jpos] == 0);
#pragma unroll
            for (int i = 0; i < 4; i++)
                Pst[cc * SPAD + ty * 4 + i] = msk ? -1e9f : acc[i][jj] * 0.125f;
        }
        __syncthreads();

        if (tid < 64) {
            float m = -1e30f;
            for (int cc = 0; cc < 64; cc++) m = fmaxf(m, Pst[cc * SPAD + tid]);
            float sum = 0.f;
            for (int cc = 0; cc < 64; cc++) {
                float p = expf(Pst[cc * SPAD + tid] - m);
                Pst[cc * SPAD + tid] = p; sum += p;
            }
            float inv = 1.f / sum;
            for (int cc = 0; cc < 64; cc++) Pst[cc * SPAD + tid] *= inv;
        }
        __syncthreads();

        for (int idx = tid; idx < 1024; idx += 256) {
            int r = idx >> 4;
            int d0 = (idx & 15) << 2;
            size_t g = (size_t)(b * SEQ + r * 8 + jpos) * DMODEL + h * DKH + d0;
            __half2 v0h = *(const __half2*)(t3 + g);
            __half2 v1h = *(const __half2*)(t3 + g + 2);
            QV[r * SPAD + d0 + 0] = __low2float(v0h);
            QV[r * SPAD + d0 + 1] = __high2float(v0h);
            QV[r * SPAD + d0 + 2] = __low2float(v1h);
            QV[r * SPAD + d0 + 3] = __high2float(v1h);
        }
        __syncthreads();

        float oacc[4][4];
#pragma unroll
        for (int i = 0; i < 4; i++)
#pragma unroll
            for (int j = 0; j < 4; j++) oacc[i][j] = 0.f;

        for (int kk = 0; kk < 64; kk++) {
            float av[4], bv[4];
#pragma unroll
            for (int i = 0; i < 4; i++) av[i] = Pst[kk * SPAD + ty * 4 + i];
#pragma unroll
            for (int j = 0; j < 4; j++) bv[j] = QV[kk * SPAD + tx * 4 + j];
#pragma unroll
            for (int i = 0; i < 4; i++)
#pragma unroll
                for (int j = 0; j < 4; j++) oacc[i][j] += av[i] * bv[j];
        }
#pragma unroll
        for (int i = 0; i < 4; i++)
#pragma unroll
            for (int jj = 0; jj < 4; jj++)
                ote[(size_t)(b * SEQ + (ty * 4 + i) * 8 + jpos) * DMODEL + h * DKH + tx * 4 + jj] =
                    __float2half_rn(oacc[i][jj]);
    }
}

// ---------------------------------------------------------------------------
// LayerNorm fp32 in -> fp16 out
// ---------------------------------------------------------------------------
__global__ void layernorm_kernel(const float* __restrict__ x,
                                 const float* __restrict__ gamma,
                                 const float* __restrict__ beta,
                                 half_t* __restrict__ oh)
{
    __shared__ float sh1[8], sh2[8];
    int row = blockIdx.x;
    int tid = threadIdx.x;
    const float* xr = x + (size_t)row * DMODEL;
    float4 v = *(const float4*)(xr + tid * 4);
    float s1 = v.x + v.y + v.z + v.w;
    float s2 = v.x * v.x + v.y * v.y + v.z * v.z + v.w * v.w;
#pragma unroll
    for (int o = 16; o; o >>= 1) {
        s1 += __shfl_xor_sync(0xffffffffu, s1, o);
        s2 += __shfl_xor_sync(0xffffffffu, s2, o);
    }
    if ((tid & 31) == 0) { sh1[tid >> 5] = s1; sh2[tid >> 5] = s2; }
    __syncthreads();
    if (tid == 0) {
        float a = 0.f, b2 = 0.f;
        for (int i = 0; i < 8; i++) { a += sh1[i]; b2 += sh2[i]; }
        sh1[0] = a * (1.f / DMODEL);
        sh2[0] = b2 * (1.f / DMODEL);
    }
    __syncthreads();
    float mean = sh1[0];
    float var = sh2[0] - mean * mean;
    float inv = rsqrtf(var + LN_EPS);
    float4 g = *(const float4*)(gamma + tid * 4);
    float4 bb = *(const float4*)(beta + tid * 4);
    size_t base = (size_t)row * DMODEL + tid * 4;
    *(__half2*)(oh + base) =
        __floats2half2_rn((v.x - mean) * inv * g.x + bb.x,
                          (v.y - mean) * inv * g.y + bb.y);
    *(__half2*)(oh + base + 2) =
        __floats2half2_rn((v.z - mean) * inv * g.z + bb.z,
                          (v.w - mean) * inv * g.w + bb.w);
}

// ---------------------------------------------------------------------------
// Host orchestration
// ---------------------------------------------------------------------------
extern "C" void kernel_launch(void* const* d_in, const int* in_sizes, int n_in,
                              void* d_out, int out_size)
{
    (void)n_in; (void)out_size;
    const float* x    = (const float*)d_in[0];
    const int*   mask = (const int*)  d_in[1];
    const float* sw   = (const float*)d_in[2];
    const float* sb   = (const float*)d_in[3];
    const float* tw   = (const float*)d_in[4];
    const float* tbia = (const float*)d_in[5];
    const float* fw   = (const float*)d_in[6];
    const float* fb   = (const float*)d_in[7];
    const float* aw   = (const float*)d_in[8];
    const float* ab   = (const float*)d_in[9];
    const float* w1   = (const float*)d_in[10];
    const float* b1   = (const float*)d_in[11];
    const float* w2   = (const float*)d_in[12];
    const float* b2   = (const float*)d_in[13];
    const float* lns  = (const float*)d_in[14];
    const float* lnb  = (const float*)d_in[15];
    float* out = (float*)d_out;

    cudaFuncSetAttribute(gemm_hmma<0>, cudaFuncAttributeMaxDynamicSharedMemorySize, SMEM_GEMM);
    cudaFuncSetAttribute(gemm_hmma<1>, cudaFuncAttributeMaxDynamicSharedMemorySize, SMEM_GEMM);
    cudaFuncSetAttribute(gemm_hmma<2>, cudaFuncAttributeMaxDynamicSharedMemorySize, SMEM_GEMM);
    cudaFuncSetAttribute(gemm_hmma<3>, cudaFuncAttributeMaxDynamicSharedMemorySize, SMEM_GEMM);
    cudaFuncSetAttribute(flash_attn,   cudaFuncAttributeMaxDynamicSharedMemorySize, SMEM_FLASH);
    cudaFuncSetAttribute(st_attn,      cudaFuncAttributeMaxDynamicSharedMemorySize, SMEM_STA);

    half_t *wt, *xh, *hh, *ah, *fh, *qkvh, *q, *k, *v, *t1, *t2, *t3;
    float *xb;
    cudaGetSymbolAddress((void**)&wt,   g_wt);
    cudaGetSymbolAddress((void**)&xh,   g_xh);
    cudaGetSymbolAddress((void**)&hh,   g_hh);
    cudaGetSymbolAddress((void**)&ah,   g_ah);
    cudaGetSymbolAddress((void**)&fh,   g_fh);
    cudaGetSymbolAddress((void**)&qkvh, g_qkvh);
    cudaGetSymbolAddress((void**)&q,    g_q);
    cudaGetSymbolAddress((void**)&k,    g_k);
    cudaGetSymbolAddress((void**)&v,    g_v);
    cudaGetSymbolAddress((void**)&t1,   g_t1);
    cudaGetSymbolAddress((void**)&t2,   g_t2);
    cudaGetSymbolAddress((void**)&t3,   g_t3);
    cudaGetSymbolAddress((void**)&xb,   g_xb);

    const size_t DD = (size_t)DMODEL * DMODEL;
    int nlayers = in_sizes[8] / (int)(4 * DD);

    // ---- ALL weight conversions in one launch ----
    wconv_all<<<dim3(32, 32, 10 + 12 * nlayers), 256>>>(sw, tw, fw, aw, w1, w2, wt, nlayers);

    aconv_kernel<<<(MTOK * DMODEL / 4 + 255) / 256, 256>>>(x, xh, MTOK * DMODEL);

    // ---- spatial+temporal QKV: one N=6144 GEMM into 6 fp16 buffers ----
    gemm_hmma<2><<<dim3(48, 32), 256, SMEM_GEMM>>>(
        xh, wt + OFF_ST, nullptr, nullptr, sb, tbia, nullptr, nullptr, nullptr,
        MTOK, 6144, DMODEL, 0, 0, q, k, v, t1, t2, t3);

    // ---- merged spatial + temporal attention ----
    st_attn<<<3072, 256, SMEM_STA>>>(q, k, v, t1, t2, t3, mask, ah, hh);

    // ---- batched out-projections into concat buffer ----
    gemm_hmma<3><<<dim3(8, 32, 2), 256, SMEM_GEMM>>>(
        ah, wt + OFF_SW3, hh, wt + OFF_TW3, sb + 3 * DMODEL, tbia + 3 * DMODEL,
        nullptr, nullptr, fh, MTOK, DMODEL, DMODEL, 0, 2048,
        nullptr, nullptr, nullptr, nullptr, nullptr, nullptr);

    // ---- fusion: xb = concat(spa,tem) @ Fw^T + fb ----
    gemm_hmma<0><<<dim3(8, 32), 256, SMEM_GEMM>>>(
        fh, wt + OFF_FW, nullptr, nullptr, fb, nullptr, nullptr, xb, nullptr,
        MTOK, DMODEL, 2 * DMODEL, 0, DMODEL, nullptr, nullptr, nullptr, nullptr, nullptr, nullptr);

    // ---- encoder layers ----
    for (int i = 0; i < nlayers; i++) {
        const float* abi = ab + (size_t)i * 4 * DMODEL;
        const half_t* awi = wt + OFF_AW + (size_t)i * 4 * M1;

        layernorm_kernel<<<MTOK, 256>>>(xb, lns + (i * 2 + 0) * DMODEL,
                                        lnb + (i * 2 + 0) * DMODEL, hh);
        gemm_hmma<1><<<dim3(24, 32), 256, SMEM_GEMM>>>(
            hh, awi, nullptr, nullptr, abi, nullptr, nullptr, nullptr, qkvh,
            MTOK, 3 * DMODEL, DMODEL, 0, 0, nullptr, nullptr, nullptr, nullptr, nullptr, nullptr);

        flash_attn<<<dim3(4, 128), 256, SMEM_FLASH>>>(qkvh, mask, ah);

        gemm_hmma<0><<<dim3(8, 32), 256, SMEM_GEMM>>>(
            ah, awi + 3 * M1, nullptr, nullptr, abi + 3 * DMODEL, nullptr, xb, xb, nullptr,
            MTOK, DMODEL, DMODEL, 0, DMODEL, nullptr, nullptr, nullptr, nullptr, nullptr, nullptr);

        layernorm_kernel<<<MTOK, 256>>>(xb, lns + (i * 2 + 1) * DMODEL,
                                        lnb + (i * 2 + 1) * DMODEL, hh);
        gemm_hmma<0><<<dim3(32, 32), 256, SMEM_GEMM>>>(
            hh, wt + OFF_W1 + (size_t)i * 4 * M1, nullptr, nullptr, b1 + i * DFF, nullptr,
            nullptr, nullptr, fh, MTOK, DFF, DMODEL, 1, DFF,
            nullptr, nullptr, nullptr, nullptr, nullptr, nullptr);
        float* dst = (i == nlayers - 1) ? out : xb;
        gemm_hmma<0><<<dim3(8, 32), 256, SMEM_GEMM>>>(
            fh, wt + OFF_W2 + (size_t)i * 4 * M1, nullptr, nullptr, b2 + i * DMODEL, nullptr,
            xb, dst, nullptr, MTOK, DMODEL, DFF, 0, DMODEL,
            nullptr, nullptr, nullptr, nullptr, nullptr, nullptr);
    }
}

// round 7
// speedup vs baseline: 6.2655x; 1.0925x over previous
#include <cuda_runtime.h>
#include <cuda_fp16.h>
#include <cstdint>
#include <math.h>

#define DMODEL 1024
#define BATCH  8
#define SEQ    512
#define NHEAD  16
#define DKH    64
#define MTOK   4096
#define DFF    4096
#define NCLIP  64
#define LN_EPS 1e-5f

typedef __half half_t;

// ---------------------------------------------------------------------------
// PTX helpers (arch-agnostic: mma.sync / ldmatrix / cp.async only)
// ---------------------------------------------------------------------------
__device__ __forceinline__ uint32_t smem_u32(const void* p) {
    uint32_t a;
    asm("{ .reg .u64 t; cvta.to.shared.u64 t, %1; cvt.u32.u64 %0, t; }" : "=r"(a) : "l"(p));
    return a;
}

#define LDSM4(r, a) \
    asm volatile("ldmatrix.sync.aligned.m8n8.x4.shared.b16 {%0,%1,%2,%3}, [%4];" \
        : "=r"((r)[0]), "=r"((r)[1]), "=r"((r)[2]), "=r"((r)[3]) : "r"(a))

#define LDSM4T(r, a) \
    asm volatile("ldmatrix.sync.aligned.m8n8.x4.trans.shared.b16 {%0,%1,%2,%3}, [%4];" \
        : "=r"((r)[0]), "=r"((r)[1]), "=r"((r)[2]), "=r"((r)[3]) : "r"(a))

#define MMA16816(c, a, b0, b1) \
    asm volatile("mma.sync.aligned.m16n8k16.row.col.f32.f16.f16.f32 " \
        "{%0,%1,%2,%3}, {%4,%5,%6,%7}, {%8,%9}, {%0,%1,%2,%3};" \
        : "+f"((c)[0]), "+f"((c)[1]), "+f"((c)[2]), "+f"((c)[3]) \
        : "r"((a)[0]), "r"((a)[1]), "r"((a)[2]), "r"((a)[3]), "r"(b0), "r"(b1))

#define CPASYNC16(d, s) asm volatile("cp.async.cg.shared.global [%0], [%1], 16;" :: "r"(d), "l"(s))
#define CPCOMMIT()      asm volatile("cp.async.commit_group;" ::: "memory")
#define CPWAIT(n)       asm volatile("cp.async.wait_group %0;" :: "n"(n) : "memory")

__device__ __forceinline__ uint32_t packh2(float x, float y) {
    __half2 h = __floats2half2_rn(x, y);
    return *(uint32_t*)&h;
}

// ---------------------------------------------------------------------------
// Device scratch
// ---------------------------------------------------------------------------
#define WT_TOT (34u * 1024u * 1024u)
__device__ half_t g_wt[WT_TOT];
__device__ half_t g_xh[MTOK * DMODEL];
__device__ half_t g_hh[MTOK * DMODEL];
__device__ half_t g_ah[MTOK * DMODEL];
__device__ half_t g_fh[MTOK * DFF];
__device__ half_t g_qkvh[3 * 128 * SEQ * DKH];
__device__ half_t g_q[MTOK * DMODEL];
__device__ half_t g_k[MTOK * DMODEL];
__device__ half_t g_v[MTOK * DMODEL];
__device__ half_t g_t1[MTOK * DMODEL];
__device__ half_t g_t2[MTOK * DMODEL];
__device__ half_t g_t3[MTOK * DMODEL];
__device__ float  g_xb[MTOK * DMODEL];

// weight offsets (units of 1M elements) inside g_wt
#define M1 (1024u * 1024u)
#define DDC (1024u * 1024u)
#define OFF_ST  0u
#define OFF_SW3 (6u * M1)
#define OFF_TW3 (7u * M1)
#define OFF_FW  (8u * M1)
#define OFF_AW  (10u * M1)
#define OFF_W1  (18u * M1)
#define OFF_W2  (26u * M1)

// ---------------------------------------------------------------------------
// fp16 HMMA GEMM, BK=64 (128B rows, 3-bit XOR swizzle), 3-stage cp.async.
// MODE 0: standard; MODE 1: QKV head-major scatter;
// MODE 2: six fp16 buffers by col/1024; MODE 3: z-batched out-proj.
// ---------------------------------------------------------------------------
#define STAGES 3
#define STAGE_BYTES 32768            /* A 128x64x2 + B 128x64x2 */
#define SMEM_GEMM (STAGES * STAGE_BYTES)

template<int MODE>
__global__ __launch_bounds__(256)
void gemm_hmma(const half_t* __restrict__ A, const half_t* __restrict__ B,
               const half_t* __restrict__ A2, const half_t* __restrict__ B2,
               const float* __restrict__ bias, const float* __restrict__ bias2,
               const float* __restrict__ R, float* Cf, half_t* Ch,
               int M, int N, int K, int relu, int ldC,
               half_t* q0, half_t* q1, half_t* q2, half_t* q3, half_t* q4, half_t* q5)
{
    extern __shared__ char smem[];
    uint32_t sb = smem_u32(smem);
    const int tid = threadIdx.x;
    const int lane = tid & 31, warp = tid >> 5;
    const int row0 = blockIdx.y * 128, col0 = blockIdx.x * 128;
    const int wm = (warp >> 2) * 64;
    const int wn = (warp & 3) * 32;

    if (MODE == 3 && blockIdx.z == 1) { A = A2; B = B2; bias = bias2; }

    // cp.async: 1024 16B-chunks per operand per stage; 4 A + 4 B per thread
    int segr[4], segc[4];
#pragma unroll
    for (int i = 0; i < 4; i++) { int s = tid + i * 256; segr[i] = s >> 3; segc[i] = s & 7; }

    int rA[4], swA[4];
#pragma unroll
    for (int mt = 0; mt < 4; mt++) {
        int r = wm + mt * 16 + (lane & 15);
        rA[mt] = r; swA[mt] = r & 7;
    }
    int rB[2], swB[2];
#pragma unroll
    for (int n2 = 0; n2 < 2; n2++) {
        int r = wn + n2 * 16 + (lane & 7) + ((lane >> 4) << 3);
        rB[n2] = r; swB[n2] = r & 7;
    }
    const int csA = lane >> 4;
    const int csB = (lane >> 3) & 1;

    float acc[4][4][4];
#pragma unroll
    for (int mt = 0; mt < 4; mt++)
#pragma unroll
        for (int nt = 0; nt < 4; nt++)
#pragma unroll
            for (int i = 0; i < 4; i++) acc[mt][nt][i] = 0.f;

    const int NT = K >> 6;

#define GISSUE(kt, st) do { \
    uint32_t sA_ = sb + (st) * STAGE_BYTES; \
    uint32_t sB_ = sA_ + 16384; \
    _Pragma("unroll") for (int i = 0; i < 4; i++) { \
        int r_ = segr[i], c_ = segc[i]; \
        uint32_t sw_ = (uint32_t)((c_ ^ (r_ & 7)) << 4); \
        CPASYNC16(sA_ + r_ * 128 + sw_, A + (size_t)(row0 + r_) * K + (size_t)(kt) * 64 + c_ * 8); \
        CPASYNC16(sB_ + r_ * 128 + sw_, B + (size_t)(col0 + r_) * K + (size_t)(kt) * 64 + c_ * 8); \
    } \
    CPCOMMIT(); } while (0)

    GISSUE(0, 0);
    GISSUE(1, 1);

    for (int kt = 0; kt < NT; kt++) {
        if (kt == NT - 1) { CPWAIT(0); } else { CPWAIT(1); }
        __syncthreads();
        if (kt + 2 < NT) GISSUE(kt + 2, (kt + 2) % 3);

        uint32_t sA = sb + (kt % 3) * STAGE_BYTES;
        uint32_t sB = sA + 16384;
#pragma unroll
        for (int k16 = 0; k16 < 4; k16++) {
            uint32_t ra[4][4], rb[2][4];
#pragma unroll
            for (int mt = 0; mt < 4; mt++)
                LDSM4(ra[mt], sA + rA[mt] * 128 + ((((k16 << 1) + csA) ^ swA[mt]) << 4));
#pragma unroll
            for (int n2 = 0; n2 < 2; n2++)
                LDSM4(rb[n2], sB + rB[n2] * 128 + ((((k16 << 1) + csB) ^ swB[n2]) << 4));
#pragma unroll
            for (int mt = 0; mt < 4; mt++)
#pragma unroll
                for (int nt = 0; nt < 4; nt++)
                    MMA16816(acc[mt][nt], ra[mt],
                             rb[nt >> 1][(nt & 1) * 2], rb[nt >> 1][(nt & 1) * 2 + 1]);
        }
    }

    // Epilogue
    half_t* obuf = nullptr;
    if (MODE == 2) {
        int bsel = col0 >> 10;
        obuf = (bsel == 0) ? q0 : (bsel == 1) ? q1 : (bsel == 2) ? q2 :
               (bsel == 3) ? q3 : (bsel == 4) ? q4 : q5;
    }
    const int cbase = (MODE == 3) ? (int)blockIdx.z * 1024 : 0;
#pragma unroll
    for (int mt = 0; mt < 4; mt++) {
        int rg = row0 + wm + mt * 16 + (lane >> 2);
#pragma unroll
        for (int nt = 0; nt < 4; nt++) {
            int c = col0 + wn + nt * 8 + (lane & 3) * 2;
            float* a = acc[mt][nt];
#pragma unroll
            for (int h = 0; h < 2; h++) {
                int row = rg + h * 8;
                float v0 = a[h * 2], v1 = a[h * 2 + 1];
                if (MODE == 0) {
                    if (bias) { v0 += bias[c]; v1 += bias[c + 1]; }
                    if (R) {
                        float2 rr = *(const float2*)(R + (size_t)row * N + c);
                        v0 += rr.x; v1 += rr.y;
                    }
                    if (relu) { v0 = fmaxf(v0, 0.f); v1 = fmaxf(v1, 0.f); }
                    if (Cf) {
                        float2 o; o.x = v0; o.y = v1;
                        *(float2*)(Cf + (size_t)row * ldC + c) = o;
                    }
                    if (Ch)
                        *(__half2*)(Ch + (size_t)row * ldC + c) = __floats2half2_rn(v0, v1);
                } else if (MODE == 1) {
                    v0 += bias[c]; v1 += bias[c + 1];
                    int qkv = c >> 10, hh_ = (c >> 6) & 15, d = c & 63;
                    int b = row >> 9, srow = row & 511;
                    size_t dst = (((size_t)(qkv * 128 + b * 16 + hh_) * 512) + srow) * 64 + d;
                    *(__half2*)(Ch + dst) = __floats2half2_rn(v0, v1);
                } else if (MODE == 2) {
                    float b0v = (c < 3072) ? bias[c] : bias2[c - 3072];
                    float b1v = (c + 1 < 3072) ? bias[c + 1] : bias2[c + 1 - 3072];
                    *(__half2*)(obuf + (size_t)row * 1024 + (c & 1023)) =
                        __floats2half2_rn(v0 + b0v, v1 + b1v);
                } else { // MODE 3
                    v0 += bias[c]; v1 += bias[c + 1];
                    *(__half2*)(Ch + (size_t)row * ldC + cbase + c) = __floats2half2_rn(v0, v1);
                }
            }
        }
    }
}

// ---------------------------------------------------------------------------
// Flash attention (encoder): per (b,h) 512x512, fp16 mma, online softmax.
// ---------------------------------------------------------------------------
#define FLD 72
#define SMEM_FLASH (3 * 128 * FLD * 2 + 512)

__global__ __launch_bounds__(256)
void flash_attn(const half_t* __restrict__ qkvh, const int* __restrict__ mask,
                half_t* __restrict__ out)
{
    extern __shared__ char sm[];
    half_t* Qs = (half_t*)sm;
    half_t* Ks = Qs + 128 * FLD;
    half_t* Vs = Ks + 128 * FLD;
    float*  mf = (float*)(Vs + 128 * FLD);

    const int bh = blockIdx.y, qt = blockIdx.x;
    const int b = bh >> 4, hd = bh & 15;
    const int tid = threadIdx.x, lane = tid & 31, warp = tid >> 5;
    const int m0 = warp * 16;

    const half_t* Qg = qkvh + (((size_t)(0 * 128 + bh) * 512) + qt * 128) * 64;
    const half_t* Kg = qkvh + ((size_t)(1 * 128 + bh) * 512) * 64;
    const half_t* Vg = qkvh + ((size_t)(2 * 128 + bh) * 512) * 64;

    for (int i = tid; i < 1024; i += 256) {
        int r = i >> 3, cs = i & 7;
        *(uint4*)(Qs + r * FLD + cs * 8) = *(const uint4*)(Qg + r * 64 + cs * 8);
    }
    __syncthreads();

    uint32_t qf[4][4];
#pragma unroll
    for (int kb = 0; kb < 4; kb++)
        LDSM4(qf[kb], smem_u32(Qs + (m0 + (lane & 15)) * FLD + kb * 16 + (lane >> 4) * 8));

    float mrow[2] = {-1e30f, -1e30f};
    float lrow[2] = {0.f, 0.f};
    float oacc[8][4];
#pragma unroll
    for (int i = 0; i < 8; i++)
#pragma unroll
        for (int j = 0; j < 4; j++) oacc[i][j] = 0.f;

    for (int kt = 0; kt < 4; kt++) {
        __syncthreads();
        for (int i = tid; i < 1024; i += 256) {
            int r = i >> 3, cs = i & 7;
            *(uint4*)(Ks + r * FLD + cs * 8) = *(const uint4*)(Kg + (kt * 128 + r) * 64 + cs * 8);
            *(uint4*)(Vs + r * FLD + cs * 8) = *(const uint4*)(Vg + (kt * 128 + r) * 64 + cs * 8);
        }
        if (tid < 128) mf[tid] = (mask[b * SEQ + kt * 128 + tid] == 0) ? 1.f : 0.f;
        __syncthreads();

        float s[16][4];
#pragma unroll
        for (int f = 0; f < 16; f++)
#pragma unroll
            for (int i = 0; i < 4; i++) s[f][i] = 0.f;

#pragma unroll
        for (int kb = 0; kb < 4; kb++) {
#pragma unroll
            for (int nb2 = 0; nb2 < 8; nb2++) {
                uint32_t bf[4];
                int krow = nb2 * 16 + (lane & 7) + ((lane >> 4) & 1) * 8;
                int kcol = kb * 16 + ((lane >> 3) & 1) * 8;
                LDSM4(bf, smem_u32(Ks + krow * FLD + kcol));
                MMA16816(s[2 * nb2],     qf[kb], bf[0], bf[1]);
                MMA16816(s[2 * nb2 + 1], qf[kb], bf[2], bf[3]);
            }
        }

#pragma unroll
        for (int f = 0; f < 16; f++) {
            int c0 = f * 8 + (lane & 3) * 2;
            float f0 = mf[c0], f1 = mf[c0 + 1];
            s[f][0] = (f0 != 0.f) ? -1e9f : s[f][0] * 0.125f;
            s[f][1] = (f1 != 0.f) ? -1e9f : s[f][1] * 0.125f;
            s[f][2] = (f0 != 0.f) ? -1e9f : s[f][2] * 0.125f;
            s[f][3] = (f1 != 0.f) ? -1e9f : s[f][3] * 0.125f;
        }

        float mx0 = -1e30f, mx1 = -1e30f;
#pragma unroll
        for (int f = 0; f < 16; f++) {
            mx0 = fmaxf(mx0, fmaxf(s[f][0], s[f][1]));
            mx1 = fmaxf(mx1, fmaxf(s[f][2], s[f][3]));
        }
        mx0 = fmaxf(mx0, __shfl_xor_sync(0xffffffffu, mx0, 1));
        mx0 = fmaxf(mx0, __shfl_xor_sync(0xffffffffu, mx0, 2));
        mx1 = fmaxf(mx1, __shfl_xor_sync(0xffffffffu, mx1, 1));
        mx1 = fmaxf(mx1, __shfl_xor_sync(0xffffffffu, mx1, 2));

        float Mn0 = fmaxf(mrow[0], mx0), Mn1 = fmaxf(mrow[1], mx1);
        float sc0 = __expf(mrow[0] - Mn0), sc1 = __expf(mrow[1] - Mn1);
        mrow[0] = Mn0; mrow[1] = Mn1;

        float rs0 = 0.f, rs1 = 0.f;
#pragma unroll
        for (int f = 0; f < 16; f++) {
            s[f][0] = __expf(s[f][0] - Mn0); s[f][1] = __expf(s[f][1] - Mn0);
            s[f][2] = __expf(s[f][2] - Mn1); s[f][3] = __expf(s[f][3] - Mn1);
            rs0 += s[f][0] + s[f][1];
            rs1 += s[f][2] + s[f][3];
        }
        rs0 += __shfl_xor_sync(0xffffffffu, rs0, 1);
        rs0 += __shfl_xor_sync(0xffffffffu, rs0, 2);
        rs1 += __shfl_xor_sync(0xffffffffu, rs1, 1);
        rs1 += __shfl_xor_sync(0xffffffffu, rs1, 2);
        lrow[0] = lrow[0] * sc0 + rs0;
        lrow[1] = lrow[1] * sc1 + rs1;

#pragma unroll
        for (int nb = 0; nb < 8; nb++) {
            oacc[nb][0] *= sc0; oacc[nb][1] *= sc0;
            oacc[nb][2] *= sc1; oacc[nb][3] *= sc1;
        }

#pragma unroll
        for (int kb = 0; kb < 8; kb++) {
            uint32_t a[4];
            a[0] = packh2(s[2 * kb][0],     s[2 * kb][1]);
            a[1] = packh2(s[2 * kb][2],     s[2 * kb][3]);
            a[2] = packh2(s[2 * kb + 1][0], s[2 * kb + 1][1]);
            a[3] = packh2(s[2 * kb + 1][2], s[2 * kb + 1][3]);
#pragma unroll
            for (int nb2 = 0; nb2 < 4; nb2++) {
                uint32_t vf[4];
                int srow = kb * 16 + (lane & 15);
                int dcol = nb2 * 16 + (lane >> 4) * 8;
                LDSM4T(vf, smem_u32(Vs + srow * FLD + dcol));
                MMA16816(oacc[2 * nb2],     a, vf[0], vf[1]);
                MMA16816(oacc[2 * nb2 + 1], a, vf[2], vf[3]);
            }
        }
    }

    float inv0 = 1.f / lrow[0], inv1 = 1.f / lrow[1];
    int r0 = qt * 128 + m0 + (lane >> 2);
#pragma unroll
    for (int nb = 0; nb < 8; nb++) {
        int c = hd * 64 + nb * 8 + (lane & 3) * 2;
        *(__half2*)(out + (size_t)(b * SEQ + r0) * DMODEL + c) =
            __floats2half2_rn(oacc[nb][0] * inv0, oacc[nb][1] * inv0);
        *(__half2*)(out + (size_t)(b * SEQ + r0 + 8) * DMODEL + c) =
            __floats2half2_rn(oacc[nb][2] * inv1, oacc[nb][3] * inv1);
    }
}

// ---------------------------------------------------------------------------
// ALL weight conversions in one launch.
// ---------------------------------------------------------------------------
__global__ void wconv_all(const float* __restrict__ sw, const float* __restrict__ tw,
                          const float* __restrict__ fw, const float* __restrict__ aw,
                          const float* __restrict__ w1, const float* __restrict__ w2,
                          half_t* __restrict__ wt, int nlayers)
{
    __shared__ float t[32][33];
    int uid = blockIdx.z;
    const float* src;
    size_t dsto;
    int Ns, Kd;
    int A = 10 + 4 * nlayers;
    int Bu = A + 4 * nlayers;

    if (uid < 6) {
        src = (uid < 3) ? (sw + (size_t)uid * DDC) : (tw + (size_t)(uid - 3) * DDC);
        dsto = OFF_ST + (size_t)uid * M1; Ns = 1024; Kd = 1024;
    } else if (uid == 6) {
        src = sw + 3 * (size_t)DDC; dsto = OFF_SW3; Ns = 1024; Kd = 1024;
    } else if (uid == 7) {
        src = tw + 3 * (size_t)DDC; dsto = OFF_TW3; Ns = 1024; Kd = 1024;
    } else if (uid < 10) {
        int c = uid - 8;
        src = fw + (size_t)c * 1024 * 1024; dsto = OFF_FW + (size_t)c * 1024;
        Ns = 1024; Kd = 2048;
    } else if (uid < A) {
        int j = uid - 10;
        src = aw + (size_t)j * DDC; dsto = OFF_AW + (size_t)j * M1; Ns = 1024; Kd = 1024;
    } else if (uid < Bu) {
        int tix = uid - A; int i = tix >> 2, c = tix & 3;
        src = w1 + (size_t)i * 4 * M1 + (size_t)c * 1024;
        dsto = OFF_W1 + (size_t)i * 4 * M1 + (size_t)c * M1;
        Ns = 4096; Kd = 1024;
    } else {
        int tix = uid - Bu; int i = tix >> 2, c = tix & 3;
        src = w2 + (size_t)i * 4 * M1 + (size_t)c * M1;
        dsto = OFF_W2 + (size_t)i * 4 * M1 + (size_t)c * 1024;
        Ns = 1024; Kd = 4096;
    }

    int n0 = blockIdx.x * 32, k0 = blockIdx.y * 32;
    int tx = threadIdx.x & 31, ty = threadIdx.x >> 5;
    for (int r = ty; r < 32; r += 8) t[r][tx] = src[(size_t)(k0 + r) * Ns + n0 + tx];
    __syncthreads();
    for (int r = ty; r < 32; r += 8)
        wt[dsto + (size_t)(n0 + r) * Kd + k0 + tx] = __float2half_rn(t[tx][r]);
}

__global__ void aconv_kernel(const float* __restrict__ x, half_t* o, int n)
{
    int i = (blockIdx.x * blockDim.x + threadIdx.x) * 4;
    if (i >= n) return;
    float4 v = *(const float4*)(x + i);
    *(__half2*)(o + i)     = __floats2half2_rn(v.x, v.y);
    *(__half2*)(o + i + 2) = __floats2half2_rn(v.z, v.w);
}

// ---------------------------------------------------------------------------
// Merged spatial+temporal attention, vectorized, reduced smem.
// blocks [0,2048): spatial (4 units/block); [2048,3072): temporal.
// Spatial: fp32 smem, stride 68 floats. Temporal: fp16 smem for Q/K/V
// (lossless), fp32 Pst, stride 68.
// ---------------------------------------------------------------------------
#define SP68 68
#define SMEM_STA 34816

__global__ __launch_bounds__(256)
void st_attn(const half_t* __restrict__ q, const half_t* __restrict__ k,
             const half_t* __restrict__ v,
             const half_t* __restrict__ t1, const half_t* __restrict__ t2,
             const half_t* __restrict__ t3,
             const int* __restrict__ mask,
             half_t* __restrict__ osp, half_t* __restrict__ ote)
{
    extern __shared__ float S[];
    int tid = threadIdx.x;

    if (blockIdx.x < 2048) {
        // ---- spatial: clip of 8 tokens, per head. 4 units of 64 threads ----
        int unit = tid >> 6, tu = tid & 63;
        int u = blockIdx.x * 4 + unit;
        int h = u & 15;
        int c = (u >> 4) & 63;
        int b = u >> 10;
        int tb = b * SEQ + c * 8;
        float* Qs = S + unit * 1696;        // 8*68 floats each
        float* Ks = Qs + 544;
        float* Vs = Ks + 544;
        float* Ps = Vs + 544;               // 64 floats

        // vector load: each thread 1 uint4 (8 halves) per array
        {
            int r = tu >> 3, d0 = (tu & 7) * 8;
            size_t g = (size_t)(tb + r) * DMODEL + h * DKH + d0;
            uint4 qv = *(const uint4*)(q + g);
            uint4 kv = *(const uint4*)(k + g);
            uint4 vv = *(const uint4*)(v + g);
            const __half2* qh = (const __half2*)&qv;
            const __half2* kh = (const __half2*)&kv;
            const __half2* vh = (const __half2*)&vv;
#pragma unroll
            for (int j = 0; j < 4; j++) {
                float2 f = __half22float2(qh[j]);
                Qs[r * SP68 + d0 + 2 * j] = f.x; Qs[r * SP68 + d0 + 2 * j + 1] = f.y;
                f = __half22float2(kh[j]);
                Ks[r * SP68 + d0 + 2 * j] = f.x; Ks[r * SP68 + d0 + 2 * j + 1] = f.y;
                f = __half22float2(vh[j]);
                Vs[r * SP68 + d0 + 2 * j] = f.x; Vs[r * SP68 + d0 + 2 * j + 1] = f.y;
            }
        }
        __syncthreads();

        int i = tu >> 3, j = tu & 7;
        float4 a4; a4.x = 0.f; a4.y = 0.f; a4.z = 0.f; a4.w = 0.f;
#pragma unroll
        for (int d = 0; d < 64; d += 4) {
            float4 qa = *(const float4*)&Qs[i * SP68 + d];
            float4 kb = *(const float4*)&Ks[j * SP68 + d];
            a4.x += qa.x * kb.x; a4.y += qa.y * kb.y;
            a4.z += qa.z * kb.z; a4.w += qa.w * kb.w;
        }
        float s = (a4.x + a4.y + a4.z + a4.w) * 0.125f;
        if (mask[b * SEQ + c * 8 + j] == 0) s = -1e9f;

        float m = s;
        m = fmaxf(m, __shfl_xor_sync(0xffffffffu, m, 1));
        m = fmaxf(m, __shfl_xor_sync(0xffffffffu, m, 2));
        m = fmaxf(m, __shfl_xor_sync(0xffffffffu, m, 4));
        float p = expf(s - m);
        float sum = p;
        sum += __shfl_xor_sync(0xffffffffu, sum, 1);
        sum += __shfl_xor_sync(0xffffffffu, sum, 2);
        sum += __shfl_xor_sync(0xffffffffu, sum, 4);
        Ps[i * 8 + j] = p / sum;
        __syncthreads();

        {
            int r = tu >> 3, d0 = (tu & 7) * 8;
            float4 o0, o1;
            o0.x = o0.y = o0.z = o0.w = 0.f;
            o1.x = o1.y = o1.z = o1.w = 0.f;
#pragma unroll
            for (int jj = 0; jj < 8; jj++) {
                float pv = Ps[r * 8 + jj];
                float4 v0 = *(const float4*)&Vs[jj * SP68 + d0];
                float4 v1 = *(const float4*)&Vs[jj * SP68 + d0 + 4];
                o0.x += pv * v0.x; o0.y += pv * v0.y; o0.z += pv * v0.z; o0.w += pv * v0.w;
                o1.x += pv * v1.x; o1.y += pv * v1.y; o1.z += pv * v1.z; o1.w += pv * v1.w;
            }
            uint4 ov;
            ((uint32_t*)&ov)[0] = packh2(o0.x, o0.y);
            ((uint32_t*)&ov)[1] = packh2(o0.z, o0.w);
            ((uint32_t*)&ov)[2] = packh2(o1.x, o1.y);
            ((uint32_t*)&ov)[3] = packh2(o1.z, o1.w);
            *(uint4*)(osp + (size_t)(tb + r) * DMODEL + h * DKH + d0) = ov;
        }
    } else {
        // ---- temporal: 64 clips at fixed within-clip position, per head ----
        int u = blockIdx.x - 2048;
        int h = u & 15;
        int jpos = (u >> 4) & 7;
        int b = u >> 7;
        int tx = tid & 15, ty = tid >> 4;
        half_t* QVh  = (half_t*)S;               // [d][c] stride 68 halves; later V [c][d]
        half_t* Ks2h = QVh + 64 * SP68;
        float*  Pst  = (float*)(Ks2h + 64 * SP68); // [key][query] stride 68 floats

        for (int idx = tid; idx < 1024; idx += 256) {
            int r = idx >> 4;
            int d0 = (idx & 15) << 2;
            size_t g = (size_t)(b * SEQ + r * 8 + jpos) * DMODEL + h * DKH + d0;
            uint2 av = *(const uint2*)(t1 + g);
            const half_t* ah = (const half_t*)&av;
            QVh[(d0 + 0) * SP68 + r] = ah[0];
            QVh[(d0 + 1) * SP68 + r] = ah[1];
            QVh[(d0 + 2) * SP68 + r] = ah[2];
            QVh[(d0 + 3) * SP68 + r] = ah[3];
            uint2 kv = *(const uint2*)(t2 + g);
            const half_t* kh = (const half_t*)&kv;
            Ks2h[(d0 + 0) * SP68 + r] = kh[0];
            Ks2h[(d0 + 1) * SP68 + r] = kh[1];
            Ks2h[(d0 + 2) * SP68 + r] = kh[2];
            Ks2h[(d0 + 3) * SP68 + r] = kh[3];
        }
        __syncthreads();

        float acc[4][4];
#pragma unroll
        for (int i = 0; i < 4; i++)
#pragma unroll
            for (int j = 0; j < 4; j++) acc[i][j] = 0.f;

        for (int d = 0; d < 64; d++) {
            uint2 au = *(const uint2*)&QVh[d * SP68 + ty * 4];
            uint2 bu = *(const uint2*)&Ks2h[d * SP68 + tx * 4];
            const __half2* ah = (const __half2*)&au;
            const __half2* bh = (const __half2*)&bu;
            float2 a01 = __half22float2(ah[0]), a23 = __half22float2(ah[1]);
            float2 b01 = __half22float2(bh[0]), b23 = __half22float2(bh[1]);
            float av[4] = {a01.x, a01.y, a23.x, a23.y};
            float bv[4] = {b01.x, b01.y, b23.x, b23.y};
#pragma unroll
            for (int i = 0; i < 4; i++)
#pragma unroll
                for (int j = 0; j < 4; j++) acc[i][j] += av[i] * bv[j];
        }
#pragma unroll
        for (int jj = 0; jj < 4; jj++) {
            int cc = tx * 4 + jj;
            bool msk = (mask[b * SEQ + cc * 8 + jpos] == 0);
#pragma unroll
            for (int i = 0; i < 4; i++)
                Pst[cc * SP68 + ty * 4 + i] = msk ? -1e9f : acc[i][jj] * 0.125f;
        }
        __syncthreads();

        if (tid < 64) {
            float m = -1e30f;
            for (int cc = 0; cc < 64; cc++) m = fmaxf(m, Pst[cc * SP68 + tid]);
            float sum = 0.f;
            for (int cc = 0; cc < 64; cc++) {
                float p = expf(Pst[cc * SP68 + tid] - m);
                Pst[cc * SP68 + tid] = p; sum += p;
            }
            float inv = 1.f / sum;
            for (int cc = 0; cc < 64; cc++) Pst[cc * SP68 + tid] *= inv;
        }
        __syncthreads();

        // V into QVh as [c][d]
        for (int idx = tid; idx < 1024; idx += 256) {
            int r = idx >> 4;
            int d0 = (idx & 15) << 2;
            size_t g = (size_t)(b * SEQ + r * 8 + jpos) * DMODEL + h * DKH + d0;
            *(uint2*)&QVh[r * SP68 + d0] = *(const uint2*)(t3 + g);
        }
        __syncthreads();

        float oacc[4][4];
#pragma unroll
        for (int i = 0; i < 4; i++)
#pragma unroll
            for (int j = 0; j < 4; j++) oacc[i][j] = 0.f;

        for (int kk = 0; kk < 64; kk++) {
            float4 av4 = *(const float4*)&Pst[kk * SP68 + ty * 4];
            uint2 bu = *(const uint2*)&QVh[kk * SP68 + tx * 4];
            const __half2* bh = (const __half2*)&bu;
            float2 b01 = __half22float2(bh[0]), b23 = __half22float2(bh[1]);
            float av[4] = {av4.x, av4.y, av4.z, av4.w};
            float bv[4] = {b01.x, b01.y, b23.x, b23.y};
#pragma unroll
            for (int i = 0; i < 4; i++)
#pragma unroll
                for (int j = 0; j < 4; j++) oacc[i][j] += av[i] * bv[j];
        }
#pragma unroll
        for (int i = 0; i < 4; i++) {
            uint2 ov;
            ((uint32_t*)&ov)[0] = packh2(oacc[i][0], oacc[i][1]);
            ((uint32_t*)&ov)[1] = packh2(oacc[i][2], oacc[i][3]);
            *(uint2*)(ote + (size_t)(b * SEQ + (ty * 4 + i) * 8 + jpos) * DMODEL +
                      h * DKH + tx * 4) = ov;
        }
    }
}

// ---------------------------------------------------------------------------
// LayerNorm fp32 in -> fp16 out
// ---------------------------------------------------------------------------
__global__ void layernorm_kernel(const float* __restrict__ x,
                                 const float* __restrict__ gamma,
                                 const float* __restrict__ beta,
                                 half_t* __restrict__ oh)
{
    __shared__ float sh1[8], sh2[8];
    int row = blockIdx.x;
    int tid = threadIdx.x;
    const float* xr = x + (size_t)row * DMODEL;
    float4 v = *(const float4*)(xr + tid * 4);
    float s1 = v.x + v.y + v.z + v.w;
    float s2 = v.x * v.x + v.y * v.y + v.z * v.z + v.w * v.w;
#pragma unroll
    for (int o = 16; o; o >>= 1) {
        s1 += __shfl_xor_sync(0xffffffffu, s1, o);
        s2 += __shfl_xor_sync(0xffffffffu, s2, o);
    }
    if ((tid & 31) == 0) { sh1[tid >> 5] = s1; sh2[tid >> 5] = s2; }
    __syncthreads();
    if (tid == 0) {
        float a = 0.f, b2 = 0.f;
        for (int i = 0; i < 8; i++) { a += sh1[i]; b2 += sh2[i]; }
        sh1[0] = a * (1.f / DMODEL);
        sh2[0] = b2 * (1.f / DMODEL);
    }
    __syncthreads();
    float mean = sh1[0];
    float var = sh2[0] - mean * mean;
    float inv = rsqrtf(var + LN_EPS);
    float4 g = *(const float4*)(gamma + tid * 4);
    float4 bb = *(const float4*)(beta + tid * 4);
    size_t base = (size_t)row * DMODEL + tid * 4;
    *(__half2*)(oh + base) =
        __floats2half2_rn((v.x - mean) * inv * g.x + bb.x,
                          (v.y - mean) * inv * g.y + bb.y);
    *(__half2*)(oh + base + 2) =
        __floats2half2_rn((v.z - mean) * inv * g.z + bb.z,
                          (v.w - mean) * inv * g.w + bb.w);
}

// ---------------------------------------------------------------------------
// Host orchestration
// ---------------------------------------------------------------------------
extern "C" void kernel_launch(void* const* d_in, const int* in_sizes, int n_in,
                              void* d_out, int out_size)
{
    (void)n_in; (void)out_size;
    const float* x    = (const float*)d_in[0];
    const int*   mask = (const int*)  d_in[1];
    const float* sw   = (const float*)d_in[2];
    const float* sb   = (const float*)d_in[3];
    const float* tw   = (const float*)d_in[4];
    const float* tbia = (const float*)d_in[5];
    const float* fw   = (const float*)d_in[6];
    const float* fb   = (const float*)d_in[7];
    const float* aw   = (const float*)d_in[8];
    const float* ab   = (const float*)d_in[9];
    const float* w1   = (const float*)d_in[10];
    const float* b1   = (const float*)d_in[11];
    const float* w2   = (const float*)d_in[12];
    const float* b2   = (const float*)d_in[13];
    const float* lns  = (const float*)d_in[14];
    const float* lnb  = (const float*)d_in[15];
    float* out = (float*)d_out;

    cudaFuncSetAttribute(gemm_hmma<0>, cudaFuncAttributeMaxDynamicSharedMemorySize, SMEM_GEMM);
    cudaFuncSetAttribute(gemm_hmma<1>, cudaFuncAttributeMaxDynamicSharedMemorySize, SMEM_GEMM);
    cudaFuncSetAttribute(gemm_hmma<2>, cudaFuncAttributeMaxDynamicSharedMemorySize, SMEM_GEMM);
    cudaFuncSetAttribute(gemm_hmma<3>, cudaFuncAttributeMaxDynamicSharedMemorySize, SMEM_GEMM);
    cudaFuncSetAttribute(flash_attn,   cudaFuncAttributeMaxDynamicSharedMemorySize, SMEM_FLASH);
    cudaFuncSetAttribute(st_attn,      cudaFuncAttributeMaxDynamicSharedMemorySize, SMEM_STA);

    half_t *wt, *xh, *hh, *ah, *fh, *qkvh, *q, *k, *v, *t1, *t2, *t3;
    float *xb;
    cudaGetSymbolAddress((void**)&wt,   g_wt);
    cudaGetSymbolAddress((void**)&xh,   g_xh);
    cudaGetSymbolAddress((void**)&hh,   g_hh);
    cudaGetSymbolAddress((void**)&ah,   g_ah);
    cudaGetSymbolAddress((void**)&fh,   g_fh);
    cudaGetSymbolAddress((void**)&qkvh, g_qkvh);
    cudaGetSymbolAddress((void**)&q,    g_q);
    cudaGetSymbolAddress((void**)&k,    g_k);
    cudaGetSymbolAddress((void**)&v,    g_v);
    cudaGetSymbolAddress((void**)&t1,   g_t1);
    cudaGetSymbolAddress((void**)&t2,   g_t2);
    cudaGetSymbolAddress((void**)&t3,   g_t3);
    cudaGetSymbolAddress((void**)&xb,   g_xb);

    const size_t DD = (size_t)DMODEL * DMODEL;
    int nlayers = in_sizes[8] / (int)(4 * DD);

    wconv_all<<<dim3(32, 32, 10 + 12 * nlayers), 256>>>(sw, tw, fw, aw, w1, w2, wt, nlayers);
    aconv_kernel<<<(MTOK * DMODEL / 4 + 255) / 256, 256>>>(x, xh, MTOK * DMODEL);

    // spatial+temporal QKV: one N=6144 GEMM into 6 fp16 buffers
    gemm_hmma<2><<<dim3(48, 32), 256, SMEM_GEMM>>>(
        xh, wt + OFF_ST, nullptr, nullptr, sb, tbia, nullptr, nullptr, nullptr,
        MTOK, 6144, DMODEL, 0, 0, q, k, v, t1, t2, t3);

    st_attn<<<3072, 256, SMEM_STA>>>(q, k, v, t1, t2, t3, mask, ah, hh);

    gemm_hmma<3><<<dim3(8, 32, 2), 256, SMEM_GEMM>>>(
        ah, wt + OFF_SW3, hh, wt + OFF_TW3, sb + 3 * DMODEL, tbia + 3 * DMODEL,
        nullptr, nullptr, fh, MTOK, DMODEL, DMODEL, 0, 2048,
        nullptr, nullptr, nullptr, nullptr, nullptr, nullptr);

    gemm_hmma<0><<<dim3(8, 32), 256, SMEM_GEMM>>>(
        fh, wt + OFF_FW, nullptr, nullptr, fb, nullptr, nullptr, xb, nullptr,
        MTOK, DMODEL, 2 * DMODEL, 0, DMODEL, nullptr, nullptr, nullptr, nullptr, nullptr, nullptr);

    for (int i = 0; i < nlayers; i++) {
        const float* abi = ab + (size_t)i * 4 * DMODEL;
        const half_t* awi = wt + OFF_AW + (size_t)i * 4 * M1;

        layernorm_kernel<<<MTOK, 256>>>(xb, lns + (i * 2 + 0) * DMODEL,
                                        lnb + (i * 2 + 0) * DMODEL, hh);
        gemm_hmma<1><<<dim3(24, 32), 256, SMEM_GEMM>>>(
            hh, awi, nullptr, nullptr, abi, nullptr, nullptr, nullptr, qkvh,
            MTOK, 3 * DMODEL, DMODEL, 0, 0, nullptr, nullptr, nullptr, nullptr, nullptr, nullptr);

        flash_attn<<<dim3(4, 128), 256, SMEM_FLASH>>>(qkvh, mask, ah);

        gemm_hmma<0><<<dim3(8, 32), 256, SMEM_GEMM>>>(
            ah, awi + 3 * M1, nullptr, nullptr, abi + 3 * DMODEL, nullptr, xb, xb, nullptr,
            MTOK, DMODEL, DMODEL, 0, DMODEL, nullptr, nullptr, nullptr, nullptr, nullptr, nullptr);

        layernorm_kernel<<<MTOK, 256>>>(xb, lns + (i * 2 + 1) * DMODEL,
                                        lnb + (i * 2 + 1) * DMODEL, hh);
        gemm_hmma<0><<<dim3(32, 32), 256, SMEM_GEMM>>>(
            hh, wt + OFF_W1 + (size_t)i * 4 * M1, nullptr, nullptr, b1 + i * DFF, nullptr,
            nullptr, nullptr, fh, MTOK, DFF, DMODEL, 1, DFF,
            nullptr, nullptr, nullptr, nullptr, nullptr, nullptr);
        float* dst = (i == nlayers - 1) ? out : xb;
        gemm_hmma<0><<<dim3(8, 32), 256, SMEM_GEMM>>>(
            fh, wt + OFF_W2 + (size_t)i * 4 * M1, nullptr, nullptr, b2 + i * DMODEL, nullptr,
            xb, dst, nullptr, MTOK, DMODEL, DFF, 0, DMODEL,
            nullptr, nullptr, nullptr, nullptr, nullptr, nullptr);
    }
}

// round 8
// speedup vs baseline: 6.7708x; 1.0806x over previous
#include <cuda_runtime.h>
#include <cuda_fp16.h>
#include <cstdint>
#include <math.h>

#define DMODEL 1024
#define BATCH  8
#define SEQ    512
#define NHEAD  16
#define DKH    64
#define MTOK   4096
#define DFF    4096
#define NCLIP  64
#define LN_EPS 1e-5f

typedef __half half_t;

// ---------------------------------------------------------------------------
// PTX helpers (arch-agnostic: mma.sync / ldmatrix / cp.async only)
// ---------------------------------------------------------------------------
__device__ __forceinline__ uint32_t smem_u32(const void* p) {
    uint32_t a;
    asm("{ .reg .u64 t; cvta.to.shared.u64 t, %1; cvt.u32.u64 %0, t; }" : "=r"(a) : "l"(p));
    return a;
}

#define LDSM4(r, a) \
    asm volatile("ldmatrix.sync.aligned.m8n8.x4.shared.b16 {%0,%1,%2,%3}, [%4];" \
        : "=r"((r)[0]), "=r"((r)[1]), "=r"((r)[2]), "=r"((r)[3]) : "r"(a))

#define LDSM4T(r, a) \
    asm volatile("ldmatrix.sync.aligned.m8n8.x4.trans.shared.b16 {%0,%1,%2,%3}, [%4];" \
        : "=r"((r)[0]), "=r"((r)[1]), "=r"((r)[2]), "=r"((r)[3]) : "r"(a))

#define MMA16816(c, a, b0, b1) \
    asm volatile("mma.sync.aligned.m16n8k16.row.col.f32.f16.f16.f32 " \
        "{%0,%1,%2,%3}, {%4,%5,%6,%7}, {%8,%9}, {%0,%1,%2,%3};" \
        : "+f"((c)[0]), "+f"((c)[1]), "+f"((c)[2]), "+f"((c)[3]) \
        : "r"((a)[0]), "r"((a)[1]), "r"((a)[2]), "r"((a)[3]), "r"(b0), "r"(b1))

#define CPASYNC16(d, s) asm volatile("cp.async.cg.shared.global [%0], [%1], 16;" :: "r"(d), "l"(s))
#define CPCOMMIT()      asm volatile("cp.async.commit_group;" ::: "memory")
#define CPWAIT(n)       asm volatile("cp.async.wait_group %0;" :: "n"(n) : "memory")

__device__ __forceinline__ uint32_t packh2(float x, float y) {
    __half2 h = __floats2half2_rn(x, y);
    return *(uint32_t*)&h;
}

// ---------------------------------------------------------------------------
// Device scratch
// ---------------------------------------------------------------------------
#define WT_TOT (34u * 1024u * 1024u)
__device__ half_t g_wt[WT_TOT];
__device__ half_t g_xh[MTOK * DMODEL];
__device__ half_t g_hh[MTOK * DMODEL];
__device__ half_t g_ah[MTOK * DMODEL];
__device__ half_t g_fh[MTOK * DFF];
__device__ half_t g_qkvh[3 * 128 * SEQ * DKH];
__device__ half_t g_q[MTOK * DMODEL];
__device__ half_t g_k[MTOK * DMODEL];
__device__ half_t g_v[MTOK * DMODEL];
__device__ half_t g_t1[MTOK * DMODEL];
__device__ half_t g_t2[MTOK * DMODEL];
__device__ half_t g_t3[MTOK * DMODEL];
__device__ float  g_xb[MTOK * DMODEL];

// weight offsets (units of 1M elements) inside g_wt
#define M1 (1024u * 1024u)
#define DDC (1024u * 1024u)
#define OFF_ST  0u
#define OFF_SW3 (6u * M1)
#define OFF_TW3 (7u * M1)
#define OFF_FW  (8u * M1)
#define OFF_AW  (10u * M1)
#define OFF_W1  (18u * M1)
#define OFF_W2  (26u * M1)

// ---------------------------------------------------------------------------
// fp16 HMMA GEMM, BK=64 (128B rows, 3-bit XOR swizzle), 3-stage cp.async.
// Forced 2 CTAs/SM via launch_bounds (regs <= 128).
// MODE 0: standard; MODE 1: QKV head-major scatter;
// MODE 2: six fp16 buffers by col/1024; MODE 3: z-batched out-proj.
// ---------------------------------------------------------------------------
#define STAGES 3
#define STAGE_BYTES 32768
#define SMEM_GEMM (STAGES * STAGE_BYTES)

template<int MODE>
__global__ __launch_bounds__(256, 2)
void gemm_hmma(const half_t* __restrict__ A, const half_t* __restrict__ B,
               const half_t* __restrict__ A2, const half_t* __restrict__ B2,
               const float* __restrict__ bias, const float* __restrict__ bias2,
               const float* __restrict__ R, float* Cf, half_t* Ch,
               int M, int N, int K, int relu, int ldC,
               half_t* q0, half_t* q1, half_t* q2, half_t* q3, half_t* q4, half_t* q5)
{
    extern __shared__ char smem[];
    uint32_t sb = smem_u32(smem);
    const int tid = threadIdx.x;
    const int lane = tid & 31, warp = tid >> 5;
    const int row0 = blockIdx.y * 128, col0 = blockIdx.x * 128;
    const int wm = (warp >> 2) * 64;
    const int wn = (warp & 3) * 32;

    if (MODE == 3 && blockIdx.z == 1) { A = A2; B = B2; bias = bias2; }

    int segr[4], segc[4];
#pragma unroll
    for (int i = 0; i < 4; i++) { int s = tid + i * 256; segr[i] = s >> 3; segc[i] = s & 7; }

    int rA[4], swA[4];
#pragma unroll
    for (int mt = 0; mt < 4; mt++) {
        int r = wm + mt * 16 + (lane & 15);
        rA[mt] = r; swA[mt] = r & 7;
    }
    int rB[2], swB[2];
#pragma unroll
    for (int n2 = 0; n2 < 2; n2++) {
        int r = wn + n2 * 16 + (lane & 7) + ((lane >> 4) << 3);
        rB[n2] = r; swB[n2] = r & 7;
    }
    const int csA = lane >> 4;
    const int csB = (lane >> 3) & 1;

    float acc[4][4][4];
#pragma unroll
    for (int mt = 0; mt < 4; mt++)
#pragma unroll
        for (int nt = 0; nt < 4; nt++)
#pragma unroll
            for (int i = 0; i < 4; i++) acc[mt][nt][i] = 0.f;

    const int NT = K >> 6;

#define GISSUE(kt, st) do { \
    uint32_t sA_ = sb + (st) * STAGE_BYTES; \
    uint32_t sB_ = sA_ + 16384; \
    _Pragma("unroll") for (int i = 0; i < 4; i++) { \
        int r_ = segr[i], c_ = segc[i]; \
        uint32_t sw_ = (uint32_t)((c_ ^ (r_ & 7)) << 4); \
        CPASYNC16(sA_ + r_ * 128 + sw_, A + (size_t)(row0 + r_) * K + (size_t)(kt) * 64 + c_ * 8); \
        CPASYNC16(sB_ + r_ * 128 + sw_, B + (size_t)(col0 + r_) * K + (size_t)(kt) * 64 + c_ * 8); \
    } \
    CPCOMMIT(); } while (0)

    GISSUE(0, 0);
    GISSUE(1, 1);

    for (int kt = 0; kt < NT; kt++) {
        if (kt == NT - 1) { CPWAIT(0); } else { CPWAIT(1); }
        __syncthreads();
        if (kt + 2 < NT) GISSUE(kt + 2, (kt + 2) % 3);

        uint32_t sA = sb + (kt % 3) * STAGE_BYTES;
        uint32_t sB = sA + 16384;
#pragma unroll
        for (int k16 = 0; k16 < 4; k16++) {
            uint32_t ra[4][4], rb[2][4];
#pragma unroll
            for (int mt = 0; mt < 4; mt++)
                LDSM4(ra[mt], sA + rA[mt] * 128 + ((((k16 << 1) + csA) ^ swA[mt]) << 4));
#pragma unroll
            for (int n2 = 0; n2 < 2; n2++)
                LDSM4(rb[n2], sB + rB[n2] * 128 + ((((k16 << 1) + csB) ^ swB[n2]) << 4));
#pragma unroll
            for (int mt = 0; mt < 4; mt++)
#pragma unroll
                for (int nt = 0; nt < 4; nt++)
                    MMA16816(acc[mt][nt], ra[mt],
                             rb[nt >> 1][(nt & 1) * 2], rb[nt >> 1][(nt & 1) * 2 + 1]);
        }
    }

    // Epilogue
    half_t* obuf = nullptr;
    if (MODE == 2) {
        int bsel = col0 >> 10;
        obuf = (bsel == 0) ? q0 : (bsel == 1) ? q1 : (bsel == 2) ? q2 :
               (bsel == 3) ? q3 : (bsel == 4) ? q4 : q5;
    }
    const int cbase = (MODE == 3) ? (int)blockIdx.z * 1024 : 0;
#pragma unroll
    for (int mt = 0; mt < 4; mt++) {
        int rg = row0 + wm + mt * 16 + (lane >> 2);
#pragma unroll
        for (int nt = 0; nt < 4; nt++) {
            int c = col0 + wn + nt * 8 + (lane & 3) * 2;
            float* a = acc[mt][nt];
#pragma unroll
            for (int h = 0; h < 2; h++) {
                int row = rg + h * 8;
                float v0 = a[h * 2], v1 = a[h * 2 + 1];
                if (MODE == 0) {
                    if (bias) { v0 += bias[c]; v1 += bias[c + 1]; }
                    if (R) {
                        float2 rr = *(const float2*)(R + (size_t)row * N + c);
                        v0 += rr.x; v1 += rr.y;
                    }
                    if (relu) { v0 = fmaxf(v0, 0.f); v1 = fmaxf(v1, 0.f); }
                    if (Cf) {
                        float2 o; o.x = v0; o.y = v1;
                        *(float2*)(Cf + (size_t)row * ldC + c) = o;
                    }
                    if (Ch)
                        *(__half2*)(Ch + (size_t)row * ldC + c) = __floats2half2_rn(v0, v1);
                } else if (MODE == 1) {
                    v0 += bias[c]; v1 += bias[c + 1];
                    int qkv = c >> 10, hh_ = (c >> 6) & 15, d = c & 63;
                    int b = row >> 9, srow = row & 511;
                    size_t dst = (((size_t)(qkv * 128 + b * 16 + hh_) * 512) + srow) * 64 + d;
                    *(__half2*)(Ch + dst) = __floats2half2_rn(v0, v1);
                } else if (MODE == 2) {
                    float b0v = (c < 3072) ? bias[c] : bias2[c - 3072];
                    float b1v = (c + 1 < 3072) ? bias[c + 1] : bias2[c + 1 - 3072];
                    *(__half2*)(obuf + (size_t)row * 1024 + (c & 1023)) =
                        __floats2half2_rn(v0 + b0v, v1 + b1v);
                } else { // MODE 3
                    v0 += bias[c]; v1 += bias[c + 1];
                    *(__half2*)(Ch + (size_t)row * ldC + cbase + c) = __floats2half2_rn(v0, v1);
                }
            }
        }
    }
}

// ---------------------------------------------------------------------------
// Flash attention (encoder): per (b,h) 512x512, fp16 mma, online softmax.
// ---------------------------------------------------------------------------
#define FLD 72
#define SMEM_FLASH (3 * 128 * FLD * 2 + 512)

__global__ __launch_bounds__(256)
void flash_attn(const half_t* __restrict__ qkvh, const int* __restrict__ mask,
                half_t* __restrict__ out)
{
    extern __shared__ char sm[];
    half_t* Qs = (half_t*)sm;
    half_t* Ks = Qs + 128 * FLD;
    half_t* Vs = Ks + 128 * FLD;
    float*  mf = (float*)(Vs + 128 * FLD);

    const int bh = blockIdx.y, qt = blockIdx.x;
    const int b = bh >> 4, hd = bh & 15;
    const int tid = threadIdx.x, lane = tid & 31, warp = tid >> 5;
    const int m0 = warp * 16;

    const half_t* Qg = qkvh + (((size_t)(0 * 128 + bh) * 512) + qt * 128) * 64;
    const half_t* Kg = qkvh + ((size_t)(1 * 128 + bh) * 512) * 64;
    const half_t* Vg = qkvh + ((size_t)(2 * 128 + bh) * 512) * 64;

    for (int i = tid; i < 1024; i += 256) {
        int r = i >> 3, cs = i & 7;
        *(uint4*)(Qs + r * FLD + cs * 8) = *(const uint4*)(Qg + r * 64 + cs * 8);
    }
    __syncthreads();

    uint32_t qf[4][4];
#pragma unroll
    for (int kb = 0; kb < 4; kb++)
        LDSM4(qf[kb], smem_u32(Qs + (m0 + (lane & 15)) * FLD + kb * 16 + (lane >> 4) * 8));

    float mrow[2] = {-1e30f, -1e30f};
    float lrow[2] = {0.f, 0.f};
    float oacc[8][4];
#pragma unroll
    for (int i = 0; i < 8; i++)
#pragma unroll
        for (int j = 0; j < 4; j++) oacc[i][j] = 0.f;

    for (int kt = 0; kt < 4; kt++) {
        __syncthreads();
        for (int i = tid; i < 1024; i += 256) {
            int r = i >> 3, cs = i & 7;
            *(uint4*)(Ks + r * FLD + cs * 8) = *(const uint4*)(Kg + (kt * 128 + r) * 64 + cs * 8);
            *(uint4*)(Vs + r * FLD + cs * 8) = *(const uint4*)(Vg + (kt * 128 + r) * 64 + cs * 8);
        }
        if (tid < 128) mf[tid] = (mask[b * SEQ + kt * 128 + tid] == 0) ? 1.f : 0.f;
        __syncthreads();

        float s[16][4];
#pragma unroll
        for (int f = 0; f < 16; f++)
#pragma unroll
            for (int i = 0; i < 4; i++) s[f][i] = 0.f;

#pragma unroll
        for (int kb = 0; kb < 4; kb++) {
#pragma unroll
            for (int nb2 = 0; nb2 < 8; nb2++) {
                uint32_t bf[4];
                int krow = nb2 * 16 + (lane & 7) + ((lane >> 4) & 1) * 8;
                int kcol = kb * 16 + ((lane >> 3) & 1) * 8;
                LDSM4(bf, smem_u32(Ks + krow * FLD + kcol));
                MMA16816(s[2 * nb2],     qf[kb], bf[0], bf[1]);
                MMA16816(s[2 * nb2 + 1], qf[kb], bf[2], bf[3]);
            }
        }

#pragma unroll
        for (int f = 0; f < 16; f++) {
            int c0 = f * 8 + (lane & 3) * 2;
            float f0 = mf[c0], f1 = mf[c0 + 1];
            s[f][0] = (f0 != 0.f) ? -1e9f : s[f][0] * 0.125f;
            s[f][1] = (f1 != 0.f) ? -1e9f : s[f][1] * 0.125f;
            s[f][2] = (f0 != 0.f) ? -1e9f : s[f][2] * 0.125f;
            s[f][3] = (f1 != 0.f) ? -1e9f : s[f][3] * 0.125f;
        }

        float mx0 = -1e30f, mx1 = -1e30f;
#pragma unroll
        for (int f = 0; f < 16; f++) {
            mx0 = fmaxf(mx0, fmaxf(s[f][0], s[f][1]));
            mx1 = fmaxf(mx1, fmaxf(s[f][2], s[f][3]));
        }
        mx0 = fmaxf(mx0, __shfl_xor_sync(0xffffffffu, mx0, 1));
        mx0 = fmaxf(mx0, __shfl_xor_sync(0xffffffffu, mx0, 2));
        mx1 = fmaxf(mx1, __shfl_xor_sync(0xffffffffu, mx1, 1));
        mx1 = fmaxf(mx1, __shfl_xor_sync(0xffffffffu, mx1, 2));

        float Mn0 = fmaxf(mrow[0], mx0), Mn1 = fmaxf(mrow[1], mx1);
        float sc0 = __expf(mrow[0] - Mn0), sc1 = __expf(mrow[1] - Mn1);
        mrow[0] = Mn0; mrow[1] = Mn1;

        float rs0 = 0.f, rs1 = 0.f;
#pragma unroll
        for (int f = 0; f < 16; f++) {
            s[f][0] = __expf(s[f][0] - Mn0); s[f][1] = __expf(s[f][1] - Mn0);
            s[f][2] = __expf(s[f][2] - Mn1); s[f][3] = __expf(s[f][3] - Mn1);
            rs0 += s[f][0] + s[f][1];
            rs1 += s[f][2] + s[f][3];
        }
        rs0 += __shfl_xor_sync(0xffffffffu, rs0, 1);
        rs0 += __shfl_xor_sync(0xffffffffu, rs0, 2);
        rs1 += __shfl_xor_sync(0xffffffffu, rs1, 1);
        rs1 += __shfl_xor_sync(0xffffffffu, rs1, 2);
        lrow[0] = lrow[0] * sc0 + rs0;
        lrow[1] = lrow[1] * sc1 + rs1;

#pragma unroll
        for (int nb = 0; nb < 8; nb++) {
            oacc[nb][0] *= sc0; oacc[nb][1] *= sc0;
            oacc[nb][2] *= sc1; oacc[nb][3] *= sc1;
        }

#pragma unroll
        for (int kb = 0; kb < 8; kb++) {
            uint32_t a[4];
            a[0] = packh2(s[2 * kb][0],     s[2 * kb][1]);
            a[1] = packh2(s[2 * kb][2],     s[2 * kb][3]);
            a[2] = packh2(s[2 * kb + 1][0], s[2 * kb + 1][1]);
            a[3] = packh2(s[2 * kb + 1][2], s[2 * kb + 1][3]);
#pragma unroll
            for (int nb2 = 0; nb2 < 4; nb2++) {
                uint32_t vf[4];
                int srow = kb * 16 + (lane & 15);
                int dcol = nb2 * 16 + (lane >> 4) * 8;
                LDSM4T(vf, smem_u32(Vs + srow * FLD + dcol));
                MMA16816(oacc[2 * nb2],     a, vf[0], vf[1]);
                MMA16816(oacc[2 * nb2 + 1], a, vf[2], vf[3]);
            }
        }
    }

    float inv0 = 1.f / lrow[0], inv1 = 1.f / lrow[1];
    int r0 = qt * 128 + m0 + (lane >> 2);
#pragma unroll
    for (int nb = 0; nb < 8; nb++) {
        int c = hd * 64 + nb * 8 + (lane & 3) * 2;
        *(__half2*)(out + (size_t)(b * SEQ + r0) * DMODEL + c) =
            __floats2half2_rn(oacc[nb][0] * inv0, oacc[nb][1] * inv0);
        *(__half2*)(out + (size_t)(b * SEQ + r0 + 8) * DMODEL + c) =
            __floats2half2_rn(oacc[nb][2] * inv1, oacc[nb][3] * inv1);
    }
}

// ---------------------------------------------------------------------------
// ALL weight conversions in one launch.
// ---------------------------------------------------------------------------
__global__ void wconv_all(const float* __restrict__ sw, const float* __restrict__ tw,
                          const float* __restrict__ fw, const float* __restrict__ aw,
                          const float* __restrict__ w1, const float* __restrict__ w2,
                          half_t* __restrict__ wt, int nlayers)
{
    __shared__ float t[32][33];
    int uid = blockIdx.z;
    const float* src;
    size_t dsto;
    int Ns, Kd;
    int A = 10 + 4 * nlayers;
    int Bu = A + 4 * nlayers;

    if (uid < 6) {
        src = (uid < 3) ? (sw + (size_t)uid * DDC) : (tw + (size_t)(uid - 3) * DDC);
        dsto = OFF_ST + (size_t)uid * M1; Ns = 1024; Kd = 1024;
    } else if (uid == 6) {
        src = sw + 3 * (size_t)DDC; dsto = OFF_SW3; Ns = 1024; Kd = 1024;
    } else if (uid == 7) {
        src = tw + 3 * (size_t)DDC; dsto = OFF_TW3; Ns = 1024; Kd = 1024;
    } else if (uid < 10) {
        int c = uid - 8;
        src = fw + (size_t)c * 1024 * 1024; dsto = OFF_FW + (size_t)c * 1024;
        Ns = 1024; Kd = 2048;
    } else if (uid < A) {
        int j = uid - 10;
        src = aw + (size_t)j * DDC; dsto = OFF_AW + (size_t)j * M1; Ns = 1024; Kd = 1024;
    } else if (uid < Bu) {
        int tix = uid - A; int i = tix >> 2, c = tix & 3;
        src = w1 + (size_t)i * 4 * M1 + (size_t)c * 1024;
        dsto = OFF_W1 + (size_t)i * 4 * M1 + (size_t)c * M1;
        Ns = 4096; Kd = 1024;
    } else {
        int tix = uid - Bu; int i = tix >> 2, c = tix & 3;
        src = w2 + (size_t)i * 4 * M1 + (size_t)c * M1;
        dsto = OFF_W2 + (size_t)i * 4 * M1 + (size_t)c * 1024;
        Ns = 1024; Kd = 4096;
    }

    int n0 = blockIdx.x * 32, k0 = blockIdx.y * 32;
    int tx = threadIdx.x & 31, ty = threadIdx.x >> 5;
    for (int r = ty; r < 32; r += 8) t[r][tx] = src[(size_t)(k0 + r) * Ns + n0 + tx];
    __syncthreads();
    for (int r = ty; r < 32; r += 8)
        wt[dsto + (size_t)(n0 + r) * Kd + k0 + tx] = __float2half_rn(t[tx][r]);
}

__global__ void aconv_kernel(const float* __restrict__ x, half_t* o, int n)
{
    int i = (blockIdx.x * blockDim.x + threadIdx.x) * 4;
    if (i >= n) return;
    float4 v = *(const float4*)(x + i);
    *(__half2*)(o + i)     = __floats2half2_rn(v.x, v.y);
    *(__half2*)(o + i + 2) = __floats2half2_rn(v.z, v.w);
}

// ---------------------------------------------------------------------------
// Merged spatial+temporal attention (unchanged from R7).
// ---------------------------------------------------------------------------
#define SP68 68
#define SMEM_STA 34816

__global__ __launch_bounds__(256)
void st_attn(const half_t* __restrict__ q, const half_t* __restrict__ k,
             const half_t* __restrict__ v,
             const half_t* __restrict__ t1, const half_t* __restrict__ t2,
             const half_t* __restrict__ t3,
             const int* __restrict__ mask,
             half_t* __restrict__ osp, half_t* __restrict__ ote)
{
    extern __shared__ float S[];
    int tid = threadIdx.x;

    if (blockIdx.x < 2048) {
        int unit = tid >> 6, tu = tid & 63;
        int u = blockIdx.x * 4 + unit;
        int h = u & 15;
        int c = (u >> 4) & 63;
        int b = u >> 10;
        int tb = b * SEQ + c * 8;
        float* Qs = S + unit * 1696;
        float* Ks = Qs + 544;
        float* Vs = Ks + 544;
        float* Ps = Vs + 544;

        {
            int r = tu >> 3, d0 = (tu & 7) * 8;
            size_t g = (size_t)(tb + r) * DMODEL + h * DKH + d0;
            uint4 qv = *(const uint4*)(q + g);
            uint4 kv = *(const uint4*)(k + g);
            uint4 vv = *(const uint4*)(v + g);
            const __half2* qh = (const __half2*)&qv;
            const __half2* kh = (const __half2*)&kv;
            const __half2* vh = (const __half2*)&vv;
#pragma unroll
            for (int j = 0; j < 4; j++) {
                float2 f = __half22float2(qh[j]);
                Qs[r * SP68 + d0 + 2 * j] = f.x; Qs[r * SP68 + d0 + 2 * j + 1] = f.y;
                f = __half22float2(kh[j]);
                Ks[r * SP68 + d0 + 2 * j] = f.x; Ks[r * SP68 + d0 + 2 * j + 1] = f.y;
                f = __half22float2(vh[j]);
                Vs[r * SP68 + d0 + 2 * j] = f.x; Vs[r * SP68 + d0 + 2 * j + 1] = f.y;
            }
        }
        __syncthreads();

        int i = tu >> 3, j = tu & 7;
        float4 a4; a4.x = 0.f; a4.y = 0.f; a4.z = 0.f; a4.w = 0.f;
#pragma unroll
        for (int d = 0; d < 64; d += 4) {
            float4 qa = *(const float4*)&Qs[i * SP68 + d];
            float4 kb = *(const float4*)&Ks[j * SP68 + d];
            a4.x += qa.x * kb.x; a4.y += qa.y * kb.y;
            a4.z += qa.z * kb.z; a4.w += qa.w * kb.w;
        }
        float s = (a4.x + a4.y + a4.z + a4.w) * 0.125f;
        if (mask[b * SEQ + c * 8 + j] == 0) s = -1e9f;

        float m = s;
        m = fmaxf(m, __shfl_xor_sync(0xffffffffu, m, 1));
        m = fmaxf(m, __shfl_xor_sync(0xffffffffu, m, 2));
        m = fmaxf(m, __shfl_xor_sync(0xffffffffu, m, 4));
        float p = expf(s - m);
        float sum = p;
        sum += __shfl_xor_sync(0xffffffffu, sum, 1);
        sum += __shfl_xor_sync(0xffffffffu, sum, 2);
        sum += __shfl_xor_sync(0xffffffffu, sum, 4);
        Ps[i * 8 + j] = p / sum;
        __syncthreads();

        {
            int r = tu >> 3, d0 = (tu & 7) * 8;
            float4 o0, o1;
            o0.x = o0.y = o0.z = o0.w = 0.f;
            o1.x = o1.y = o1.z = o1.w = 0.f;
#pragma unroll
            for (int jj = 0; jj < 8; jj++) {
                float pv = Ps[r * 8 + jj];
                float4 v0 = *(const float4*)&Vs[jj * SP68 + d0];
                float4 v1 = *(const float4*)&Vs[jj * SP68 + d0 + 4];
                o0.x += pv * v0.x; o0.y += pv * v0.y; o0.z += pv * v0.z; o0.w += pv * v0.w;
                o1.x += pv * v1.x; o1.y += pv * v1.y; o1.z += pv * v1.z; o1.w += pv * v1.w;
            }
            uint4 ov;
            ((uint32_t*)&ov)[0] = packh2(o0.x, o0.y);
            ((uint32_t*)&ov)[1] = packh2(o0.z, o0.w);
            ((uint32_t*)&ov)[2] = packh2(o1.x, o1.y);
            ((uint32_t*)&ov)[3] = packh2(o1.z, o1.w);
            *(uint4*)(osp + (size_t)(tb + r) * DMODEL + h * DKH + d0) = ov;
        }
    } else {
        int u = blockIdx.x - 2048;
        int h = u & 15;
        int jpos = (u >> 4) & 7;
        int b = u >> 7;
        int tx = tid & 15, ty = tid >> 4;
        half_t* QVh  = (half_t*)S;
        half_t* Ks2h = QVh + 64 * SP68;
        float*  Pst  = (float*)(Ks2h + 64 * SP68);

        for (int idx = tid; idx < 1024; idx += 256) {
            int r = idx >> 4;
            int d0 = (idx & 15) << 2;
            size_t g = (size_t)(b * SEQ + r * 8 + jpos) * DMODEL + h * DKH + d0;
            uint2 av = *(const uint2*)(t1 + g);
            const half_t* ah = (const half_t*)&av;
            QVh[(d0 + 0) * SP68 + r] = ah[0];
            QVh[(d0 + 1) * SP68 + r] = ah[1];
            QVh[(d0 + 2) * SP68 + r] = ah[2];
            QVh[(d0 + 3) * SP68 + r] = ah[3];
            uint2 kv = *(const uint2*)(t2 + g);
            const half_t* kh = (const half_t*)&kv;
            Ks2h[(d0 + 0) * SP68 + r] = kh[0];
            Ks2h[(d0 + 1) * SP68 + r] = kh[1];
            Ks2h[(d0 + 2) * SP68 + r] = kh[2];
            Ks2h[(d0 + 3) * SP68 + r] = kh[3];
        }
        __syncthreads();

        float acc[4][4];
#pragma unroll
        for (int i = 0; i < 4; i++)
#pragma unroll
            for (int j = 0; j < 4; j++) acc[i][j] = 0.f;

        for (int d = 0; d < 64; d++) {
            uint2 au = *(const uint2*)&QVh[d * SP68 + ty * 4];
            uint2 bu = *(const uint2*)&Ks2h[d * SP68 + tx * 4];
            const __half2* ah = (const __half2*)&au;
            const __half2* bh = (const __half2*)&bu;
            float2 a01 = __half22float2(ah[0]), a23 = __half22float2(ah[1]);
            float2 b01 = __half22float2(bh[0]), b23 = __half22float2(bh[1]);
            float av[4] = {a01.x, a01.y, a23.x, a23.y};
            float bv[4] = {b01.x, b01.y, b23.x, b23.y};
#pragma unroll
            for (int i = 0; i < 4; i++)
#pragma unroll
                for (int j = 0; j < 4; j++) acc[i][j] += av[i] * bv[j];
        }
#pragma unroll
        for (int jj = 0; jj < 4; jj++) {
            int cc = tx * 4 + jj;
            bool msk = (mask[b * SEQ + cc * 8 + jpos] == 0);
#pragma unroll
            for (int i = 0; i < 4; i++)
                Pst[cc * SP68 + ty * 4 + i] = msk ? -1e9f : acc[i][jj] * 0.125f;
        }
        __syncthreads();

        if (tid < 64) {
            float m = -1e30f;
            for (int cc = 0; cc < 64; cc++) m = fmaxf(m, Pst[cc * SP68 + tid]);
            float sum = 0.f;
            for (int cc = 0; cc < 64; cc++) {
                float p = expf(Pst[cc * SP68 + tid] - m);
                Pst[cc * SP68 + tid] = p; sum += p;
            }
            float inv = 1.f / sum;
            for (int cc = 0; cc < 64; cc++) Pst[cc * SP68 + tid] *= inv;
        }
        __syncthreads();

        for (int idx = tid; idx < 1024; idx += 256) {
            int r = idx >> 4;
            int d0 = (idx & 15) << 2;
            size_t g = (size_t)(b * SEQ + r * 8 + jpos) * DMODEL + h * DKH + d0;
            *(uint2*)&QVh[r * SP68 + d0] = *(const uint2*)(t3 + g);
        }
        __syncthreads();

        float oacc[4][4];
#pragma unroll
        for (int i = 0; i < 4; i++)
#pragma unroll
            for (int j = 0; j < 4; j++) oacc[i][j] = 0.f;

        for (int kk = 0; kk < 64; kk++) {
            float4 av4 = *(const float4*)&Pst[kk * SP68 + ty * 4];
            uint2 bu = *(const uint2*)&QVh[kk * SP68 + tx * 4];
            const __half2* bh = (const __half2*)&bu;
            float2 b01 = __half22float2(bh[0]), b23 = __half22float2(bh[1]);
            float av[4] = {av4.x, av4.y, av4.z, av4.w};
            float bv[4] = {b01.x, b01.y, b23.x, b23.y};
#pragma unroll
            for (int i = 0; i < 4; i++)
#pragma unroll
                for (int j = 0; j < 4; j++) oacc[i][j] += av[i] * bv[j];
        }
#pragma unroll
        for (int i = 0; i < 4; i++) {
            uint2 ov;
            ((uint32_t*)&ov)[0] = packh2(oacc[i][0], oacc[i][1]);
            ((uint32_t*)&ov)[1] = packh2(oacc[i][2], oacc[i][3]);
            *(uint2*)(ote + (size_t)(b * SEQ + (ty * 4 + i) * 8 + jpos) * DMODEL +
                      h * DKH + tx * 4) = ov;
        }
    }
}

// ---------------------------------------------------------------------------
// LayerNorm: warp-per-row, 8 rows per 256-thread block, no __syncthreads.
// ---------------------------------------------------------------------------
__global__ __launch_bounds__(256)
void layernorm_kernel(const float* __restrict__ x,
                      const float* __restrict__ gamma,
                      const float* __restrict__ beta,
                      half_t* __restrict__ oh)
{
    int row = blockIdx.x * 8 + (threadIdx.x >> 5);
    int lane = threadIdx.x & 31;
    const float* xr = x + (size_t)row * DMODEL;

    float4 v[8];
    float s1 = 0.f, s2 = 0.f;
#pragma unroll
    for (int i = 0; i < 8; i++) {
        v[i] = *(const float4*)(xr + lane * 4 + i * 128);
        s1 += v[i].x + v[i].y + v[i].z + v[i].w;
        s2 += v[i].x * v[i].x + v[i].y * v[i].y + v[i].z * v[i].z + v[i].w * v[i].w;
    }
#pragma unroll
    for (int o = 16; o; o >>= 1) {
        s1 += __shfl_xor_sync(0xffffffffu, s1, o);
        s2 += __shfl_xor_sync(0xffffffffu, s2, o);
    }
    float mean = s1 * (1.f / DMODEL);
    float var = s2 * (1.f / DMODEL) - mean * mean;
    float inv = rsqrtf(var + LN_EPS);

#pragma unroll
    for (int i = 0; i < 8; i++) {
        int c = lane * 4 + i * 128;
        float4 g = *(const float4*)(gamma + c);
        float4 bb = *(const float4*)(beta + c);
        uint2 ov;
        ((uint32_t*)&ov)[0] = packh2((v[i].x - mean) * inv * g.x + bb.x,
                                     (v[i].y - mean) * inv * g.y + bb.y);
        ((uint32_t*)&ov)[1] = packh2((v[i].z - mean) * inv * g.z + bb.z,
                                     (v[i].w - mean) * inv * g.w + bb.w);
        *(uint2*)(oh + (size_t)row * DMODEL + c) = ov;
    }
}

// ---------------------------------------------------------------------------
// Host orchestration
// ---------------------------------------------------------------------------
extern "C" void kernel_launch(void* const* d_in, const int* in_sizes, int n_in,
                              void* d_out, int out_size)
{
    (void)n_in; (void)out_size;
    const float* x    = (const float*)d_in[0];
    const int*   mask = (const int*)  d_in[1];
    const float* sw   = (const float*)d_in[2];
    const float* sb   = (const float*)d_in[3];
    const float* tw   = (const float*)d_in[4];
    const float* tbia = (const float*)d_in[5];
    const float* fw   = (const float*)d_in[6];
    const float* fb   = (const float*)d_in[7];
    const float* aw   = (const float*)d_in[8];
    const float* ab   = (const float*)d_in[9];
    const float* w1   = (const float*)d_in[10];
    const float* b1   = (const float*)d_in[11];
    const float* w2   = (const float*)d_in[12];
    const float* b2   = (const float*)d_in[13];
    const float* lns  = (const float*)d_in[14];
    const float* lnb  = (const float*)d_in[15];
    float* out = (float*)d_out;

    cudaFuncSetAttribute(gemm_hmma<0>, cudaFuncAttributeMaxDynamicSharedMemorySize, SMEM_GEMM);
    cudaFuncSetAttribute(gemm_hmma<1>, cudaFuncAttributeMaxDynamicSharedMemorySize, SMEM_GEMM);
    cudaFuncSetAttribute(gemm_hmma<2>, cudaFuncAttributeMaxDynamicSharedMemorySize, SMEM_GEMM);
    cudaFuncSetAttribute(gemm_hmma<3>, cudaFuncAttributeMaxDynamicSharedMemorySize, SMEM_GEMM);
    cudaFuncSetAttribute(flash_attn,   cudaFuncAttributeMaxDynamicSharedMemorySize, SMEM_FLASH);
    cudaFuncSetAttribute(st_attn,      cudaFuncAttributeMaxDynamicSharedMemorySize, SMEM_STA);

    half_t *wt, *xh, *hh, *ah, *fh, *qkvh, *q, *k, *v, *t1, *t2, *t3;
    float *xb;
    cudaGetSymbolAddress((void**)&wt,   g_wt);
    cudaGetSymbolAddress((void**)&xh,   g_xh);
    cudaGetSymbolAddress((void**)&hh,   g_hh);
    cudaGetSymbolAddress((void**)&ah,   g_ah);
    cudaGetSymbolAddress((void**)&fh,   g_fh);
    cudaGetSymbolAddress((void**)&qkvh, g_qkvh);
    cudaGetSymbolAddress((void**)&q,    g_q);
    cudaGetSymbolAddress((void**)&k,    g_k);
    cudaGetSymbolAddress((void**)&v,    g_v);
    cudaGetSymbolAddress((void**)&t1,   g_t1);
    cudaGetSymbolAddress((void**)&t2,   g_t2);
    cudaGetSymbolAddress((void**)&t3,   g_t3);
    cudaGetSymbolAddress((void**)&xb,   g_xb);

    const size_t DD = (size_t)DMODEL * DMODEL;
    int nlayers = in_sizes[8] / (int)(4 * DD);

    wconv_all<<<dim3(32, 32, 10 + 12 * nlayers), 256>>>(sw, tw, fw, aw, w1, w2, wt, nlayers);
    aconv_kernel<<<(MTOK * DMODEL / 4 + 255) / 256, 256>>>(x, xh, MTOK * DMODEL);

    gemm_hmma<2><<<dim3(48, 32), 256, SMEM_GEMM>>>(
        xh, wt + OFF_ST, nullptr, nullptr, sb, tbia, nullptr, nullptr, nullptr,
        MTOK, 6144, DMODEL, 0, 0, q, k, v, t1, t2, t3);

    st_attn<<<3072, 256, SMEM_STA>>>(q, k, v, t1, t2, t3, mask, ah, hh);

    gemm_hmma<3><<<dim3(8, 32, 2), 256, SMEM_GEMM>>>(
        ah, wt + OFF_SW3, hh, wt + OFF_TW3, sb + 3 * DMODEL, tbia + 3 * DMODEL,
        nullptr, nullptr, fh, MTOK, DMODEL, DMODEL, 0, 2048,
        nullptr, nullptr, nullptr, nullptr, nullptr, nullptr);

    gemm_hmma<0><<<dim3(8, 32), 256, SMEM_GEMM>>>(
        fh, wt + OFF_FW, nullptr, nullptr, fb, nullptr, nullptr, xb, nullptr,
        MTOK, DMODEL, 2 * DMODEL, 0, DMODEL, nullptr, nullptr, nullptr, nullptr, nullptr, nullptr);

    for (int i = 0; i < nlayers; i++) {
        const float* abi = ab + (size_t)i * 4 * DMODEL;
        const half_t* awi = wt + OFF_AW + (size_t)i * 4 * M1;

        layernorm_kernel<<<MTOK / 8, 256>>>(xb, lns + (i * 2 + 0) * DMODEL,
                                            lnb + (i * 2 + 0) * DMODEL, hh);
        gemm_hmma<1><<<dim3(24, 32), 256, SMEM_GEMM>>>(
            hh, awi, nullptr, nullptr, abi, nullptr, nullptr, nullptr, qkvh,
            MTOK, 3 * DMODEL, DMODEL, 0, 0, nullptr, nullptr, nullptr, nullptr, nullptr, nullptr);

        flash_attn<<<dim3(4, 128), 256, SMEM_FLASH>>>(qkvh, mask, ah);

        gemm_hmma<0><<<dim3(8, 32), 256, SMEM_GEMM>>>(
            ah, awi + 3 * M1, nullptr, nullptr, abi + 3 * DMODEL, nullptr, xb, xb, nullptr,
            MTOK, DMODEL, DMODEL, 0, DMODEL, nullptr, nullptr, nullptr, nullptr, nullptr, nullptr);

        layernorm_kernel<<<MTOK / 8, 256>>>(xb, lns + (i * 2 + 1) * DMODEL,
                                            lnb + (i * 2 + 1) * DMODEL, hh);
        gemm_hmma<0><<<dim3(32, 32), 256, SMEM_GEMM>>>(
            hh, wt + OFF_W1 + (size_t)i * 4 * M1, nullptr, nullptr, b1 + i * DFF, nullptr,
            nullptr, nullptr, fh, MTOK, DFF, DMODEL, 1, DFF,
            nullptr, nullptr, nullptr, nullptr, nullptr, nullptr);
        float* dst = (i == nlayers - 1) ? out : xb;
        gemm_hmma<0><<<dim3(8, 32), 256, SMEM_GEMM>>>(
            fh, wt + OFF_W2 + (size_t)i * 4 * M1, nullptr, nullptr, b2 + i * DMODEL, nullptr,
            xb, dst, nullptr, MTOK, DMODEL, DFF, 0, DMODEL,
            nullptr, nullptr, nullptr, nullptr, nullptr, nullptr);
    }
}